// round 8
// baseline (speedup 1.0000x reference)
#include <cuda_runtime.h>
#include <cuda_bf16.h>
#include <cstdint>
#include <cstddef>

#define BATCH   2
#define SEQ     4096
#define DMODEL  2048
#define DINNER  4096
#define NHEADS  32
#define DHEAD   128
#define DSTATE  64
#define CONVDIM 4224          // DINNER + 2*DSTATE
#define EPROJ   8352          // 2*DINNER + 2*DSTATE + NHEADS
#define NCHUNK  16
#define CHUNK   256
#define MROWS   8192          // BATCH*SEQ

// ---------------- device scratch (static: allocation-free) ----------------
__device__ float g_zx[(size_t)MROWS * EPROJ];     // in_proj output
__device__ float g_xc[(size_t)MROWS * CONVDIM];   // conv+silu output
__device__ float g_dtv[(size_t)MROWS * NHEADS];   // softplus dt
__device__ float g_cum[BATCH * NCHUNK * NHEADS * CHUNK]; // per-chunk cumsum(dA)
__device__ float g_st[(size_t)BATCH * NCHUNK * NHEADS * DHEAD * DSTATE]; // chunk states
__device__ float g_pv[(size_t)BATCH * NCHUNK * NHEADS * DHEAD * DSTATE]; // prev states
__device__ float g_y [(size_t)MROWS * DINNER];    // y (pre-norm)
// pre-split bf16 operands (hi/lo); sized for the larger GEMM use
__device__ __nv_bfloat16 g_Ah[(size_t)MROWS * DINNER];
__device__ __nv_bfloat16 g_Al[(size_t)MROWS * DINNER];
__device__ __nv_bfloat16 g_Bh[(size_t)EPROJ * DMODEL];
__device__ __nv_bfloat16 g_Bl[(size_t)EPROJ * DMODEL];

// ============================================================================
// helpers
// ============================================================================
__device__ __forceinline__ uint32_t smem_u32(const void* p) {
    uint32_t a;
    asm("{ .reg .u64 t; cvta.to.shared.u64 t, %1; cvt.u32.u64 %0, t; }" : "=r"(a) : "l"(p));
    return a;
}
__device__ __forceinline__ void ldm4(uint32_t* r, uint32_t a) {
    asm volatile("ldmatrix.sync.aligned.m8n8.x4.shared.b16 {%0,%1,%2,%3}, [%4];"
                 : "=r"(r[0]), "=r"(r[1]), "=r"(r[2]), "=r"(r[3]) : "r"(a));
}
__device__ __forceinline__ void mma16816(float* d, const uint32_t* a, uint32_t b0, uint32_t b1) {
    asm volatile("mma.sync.aligned.m16n8k16.row.col.f32.bf16.bf16.f32 "
                 "{%0,%1,%2,%3}, {%4,%5,%6,%7}, {%8,%9}, {%0,%1,%2,%3};"
                 : "+f"(d[0]), "+f"(d[1]), "+f"(d[2]), "+f"(d[3])
                 : "r"(a[0]), "r"(a[1]), "r"(a[2]), "r"(a[3]), "r"(b0), "r"(b1));
}
__device__ __forceinline__ uint32_t pk2(__nv_bfloat16 a, __nv_bfloat16 b) {
    return (uint32_t)__bfloat16_as_ushort(a) | ((uint32_t)__bfloat16_as_ushort(b) << 16);
}
__device__ __forceinline__ void dec4(float4 v, uint2& h, uint2& l) {
    __nv_bfloat16 h0 = __float2bfloat16_rn(v.x), h1 = __float2bfloat16_rn(v.y);
    __nv_bfloat16 h2 = __float2bfloat16_rn(v.z), h3 = __float2bfloat16_rn(v.w);
    __nv_bfloat16 l0 = __float2bfloat16_rn(v.x - __bfloat162float(h0));
    __nv_bfloat16 l1 = __float2bfloat16_rn(v.y - __bfloat162float(h1));
    __nv_bfloat16 l2 = __float2bfloat16_rn(v.z - __bfloat162float(h2));
    __nv_bfloat16 l3 = __float2bfloat16_rn(v.w - __bfloat162float(h3));
    h = make_uint2(pk2(h0, h1), pk2(h2, h3));
    l = make_uint2(pk2(l0, l1), pk2(l2, l3));
}
__device__ __forceinline__ void cpasync16(uint32_t dst, const void* src, int srcsz) {
    asm volatile("cp.async.cg.shared.global [%0], [%1], 16, %2;"
                 :: "r"(dst), "l"(src), "r"(srcsz) : "memory");
}
#define CP_COMMIT() asm volatile("cp.async.commit_group;" ::: "memory")
#define CP_WAIT1()  asm volatile("cp.async.wait_group 1;" ::: "memory")

// ---------------- fp32 -> (hi, lo) bf16 split (memory-bound pass) ----------
__global__ void split_k(const float4* __restrict__ in,
                        uint2* __restrict__ hi, uint2* __restrict__ lo, int n4) {
    int i = blockIdx.x * 256 + threadIdx.x;
    if (i < n4) {
        uint2 h, l;
        dec4(in[i], h, l);
        hi[i] = h;
        lo[i] = l;
    }
}

// ============================================================================
// HMMA bf16x3 NT GEMM on pre-split operands:
// C[M,N] = (Ah+Al)[M,K] * (Bh+Bl)[N,K]^T, D = Ah*Bh + Al*Bh + Ah*Bl.
// Tile 128x128, BK=32, 2-stage cp.async pipeline, 2 CTAs/SM (4 warps/SMSP).
// ============================================================================
#define BK      32
#define TROW    80                       // padded row bytes: 16-aligned, 5 mod 8 -> ldmatrix conflict-free
#define TILE_B  (128 * TROW)             // 10240 B per bf16 tile
#define STAGE_B (4 * TILE_B)             // Ah | Al | Bh | Bl = 40960 B
#define NSTAGE  2
#define GSMEM   (NSTAGE * STAGE_B)       // 81920 B

__device__ __forceinline__ void ld_stage(uint32_t sb, int stage,
        const __nv_bfloat16* __restrict__ Ah, const __nv_bfloat16* __restrict__ Al,
        const __nv_bfloat16* __restrict__ Bh, const __nv_bfloat16* __restrict__ Bl,
        int m0, int n0, int K, int N, int k0, int t) {
    uint32_t stb = sb + (uint32_t)stage * STAGE_B;
    #pragma unroll
    for (int j = 0; j < 8; j++) {
        int lin = t + j * 256;
        int tile = lin >> 9, li = lin & 511;
        int row = li >> 2, c = li & 3;
        uint32_t dst = stb + (uint32_t)tile * TILE_B + (uint32_t)row * TROW + c * 16;
        const __nv_bfloat16* src;
        int sz = 16;
        if (tile == 0)      src = Ah + (size_t)(m0 + row) * K + k0 + c * 8;
        else if (tile == 1) src = Al + (size_t)(m0 + row) * K + k0 + c * 8;
        else {
            const __nv_bfloat16* base = (tile == 2) ? Bh : Bl;
            int r = n0 + row;
            if (r >= N) { r = 0; sz = 0; }
            src = base + (size_t)r * K + k0 + c * 8;
        }
        cpasync16(dst, src, sz);
    }
}

__global__ __launch_bounds__(256, 2)
void gemm_bf(const __nv_bfloat16* __restrict__ Ah, const __nv_bfloat16* __restrict__ Al,
             const __nv_bfloat16* __restrict__ Bh, const __nv_bfloat16* __restrict__ Bl,
             float* __restrict__ C, int M, int N, int K) {
    extern __shared__ char smem[];
    const uint32_t sb = smem_u32(smem);
    const int t = threadIdx.x, wid = t >> 5, lane = t & 31;
    const int m0 = blockIdx.y * 128, n0b = blockIdx.x * 128;
    const int wm = (wid & 1) * 64, wn = (wid >> 1) * 32;

    float acc[4][4][4];
    #pragma unroll
    for (int i = 0; i < 4; i++)
        #pragma unroll
        for (int j = 0; j < 4; j++)
            #pragma unroll
            for (int k = 0; k < 4; k++) acc[i][j][k] = 0.f;

    const int NC = K / BK;
    ld_stage(sb, 0, Ah, Al, Bh, Bl, m0, n0b, K, N, 0, t);
    CP_COMMIT();
    if (NC > 1)
        ld_stage(sb, 1, Ah, Al, Bh, Bl, m0, n0b, K, N, BK, t);
    CP_COMMIT();

    const int lr = lane & 15, lh = lane >> 4;

    for (int c = 0; c < NC; c++) {
        CP_WAIT1();
        __syncthreads();
        uint32_t stb = sb + (uint32_t)(c & 1) * STAGE_B;
        #pragma unroll
        for (int kk = 0; kk < 2; kk++) {
            uint32_t kb = kk * 32 + lh * 16;
            uint32_t bh[2][4], bl[2][4];
            #pragma unroll
            for (int np = 0; np < 2; np++) {
                uint32_t ro = (uint32_t)(wn + np * 16 + lr) * TROW + kb;
                ldm4(bh[np], stb + 2 * TILE_B + ro);
                ldm4(bl[np], stb + 3 * TILE_B + ro);
            }
            // A fragments double-buffered per-mf to stay under 128 regs
            uint32_t ah2[2][4], al2[2][4];
            {
                uint32_t ro = (uint32_t)(wm + lr) * TROW + kb;
                ldm4(ah2[0], stb + ro);
                ldm4(al2[0], stb + TILE_B + ro);
            }
            #pragma unroll
            for (int mf = 0; mf < 4; mf++) {
                if (mf < 3) {
                    uint32_t ro = (uint32_t)(wm + (mf + 1) * 16 + lr) * TROW + kb;
                    ldm4(ah2[(mf + 1) & 1], stb + ro);
                    ldm4(al2[(mf + 1) & 1], stb + TILE_B + ro);
                }
                const uint32_t* ah = ah2[mf & 1];
                const uint32_t* al = al2[mf & 1];
                #pragma unroll
                for (int np = 0; np < 2; np++) {
                    mma16816(acc[mf][2 * np],     ah, bh[np][0], bh[np][2]);
                    mma16816(acc[mf][2 * np + 1], ah, bh[np][1], bh[np][3]);
                    mma16816(acc[mf][2 * np],     al, bh[np][0], bh[np][2]);
                    mma16816(acc[mf][2 * np + 1], al, bh[np][1], bh[np][3]);
                    mma16816(acc[mf][2 * np],     ah, bl[np][0], bl[np][2]);
                    mma16816(acc[mf][2 * np + 1], ah, bl[np][1], bl[np][3]);
                }
            }
        }
        __syncthreads();
        int nx = c + 2;
        if (nx < NC)
            ld_stage(sb, nx & 1, Ah, Al, Bh, Bl, m0, n0b, K, N, nx * BK, t);
        CP_COMMIT();
    }

    // epilogue: mma C layout — row = lane>>2 (+8), col = (lane&3)*2 (+1)
    const int gr = lane >> 2, gc = (lane & 3) * 2;
    #pragma unroll
    for (int mf = 0; mf < 4; mf++) {
        int m = m0 + wm + mf * 16 + gr;
        #pragma unroll
        for (int nf = 0; nf < 4; nf++) {
            int n = n0b + wn + nf * 8 + gc;
            if (n < N) {
                *(float2*)&C[(size_t)m * N + n] =
                    make_float2(acc[mf][nf][0], acc[mf][nf][1]);
                *(float2*)&C[(size_t)(m + 8) * N + n] =
                    make_float2(acc[mf][nf][2], acc[mf][nf][3]);
            }
        }
    }
}

// ---------------- conv1d (depthwise, causal, D_CONV=4) + SiLU ----------------
__global__ void conv_silu_k(const float* __restrict__ cw, const float* __restrict__ cb) {
    size_t idx = (size_t)blockIdx.x * 256 + threadIdx.x;
    int c = (int)(idx % CONVDIM);
    size_t bl = idx / CONVDIM;
    int l = (int)(bl % SEQ);
    int b = (int)(bl / SEQ);
    float acc = cb[c];
    #pragma unroll
    for (int k = 0; k < 4; k++) {
        int ls = l - 3 + k;
        if (ls >= 0)
            acc += g_zx[((size_t)(b * SEQ + ls)) * EPROJ + DINNER + c] * cw[c * 4 + k];
    }
    acc = acc / (1.f + expf(-acc));
    g_xc[idx] = acc;
}

// ---------------- dt softplus + per-chunk cumsum(dA) ----------------
__global__ void dtcum_k(const float* __restrict__ dtb, const float* __restrict__ Alog) {
    int blk = blockIdx.x;                // ((b*16+c)*32+h)
    int h = blk & 31, c = (blk >> 5) & 15, b = blk >> 9;
    int s = threadIdx.x;
    int l = c * CHUNK + s;
    float raw = g_zx[((size_t)(b * SEQ + l)) * EPROJ + (EPROJ - NHEADS) + h] + dtb[h];
    float dtv = (raw > 20.f) ? raw : log1pf(expf(raw));
    g_dtv[(size_t)(b * SEQ + l) * NHEADS + h] = dtv;
    float dA = dtv * (-expf(Alog[h]));
    __shared__ float sc[256];
    sc[s] = dA;
    __syncthreads();
    for (int off = 1; off < 256; off <<= 1) {
        float v = (s >= off) ? sc[s - off] : 0.f;
        __syncthreads();
        sc[s] += v;
        __syncthreads();
    }
    g_cum[blk * CHUNK + s] = sc[s];
}

// ---------------- per-chunk states: st[p,n] = sum_z exp(cumL-cum[z])*dt[z]*x[z,p]*B[z,n]
__global__ __launch_bounds__(256)
void states_k() {
    extern __shared__ float sm[];
    float* xw  = sm;                 // 64*128
    float* Bsh = xw + 64 * 128;      // 64*64
    float* ws  = Bsh + 64 * 64;      // 256
    int blk = blockIdx.x;
    int h = blk & 31, c = (blk >> 5) & 15, b = blk >> 9;
    int t = threadIdx.x;
    float clast = g_cum[blk * CHUNK + 255];
    {
        float cz = g_cum[blk * CHUNK + t];
        float dtv = g_dtv[(size_t)(b * SEQ + c * CHUNK + t) * NHEADS + h];
        ws[t] = expf(clast - cz) * dtv;
    }
    __syncthreads();
    int tx = t & 15, ty = t >> 4;
    int p0 = tx * 8, n0 = ty * 4;
    float acc[8][4];
    #pragma unroll
    for (int i = 0; i < 8; i++)
        #pragma unroll
        for (int j = 0; j < 4; j++) acc[i][j] = 0.f;
    size_t base = (size_t)(b * SEQ + c * CHUNK) * CONVDIM;
    for (int zt = 0; zt < 4; zt++) {
        #pragma unroll
        for (int i = 0; i < 32; i++) {
            int lin = t + i * 256; int zz = lin >> 7; int p = lin & 127; int z = zt * 64 + zz;
            xw[zz * 128 + p] = g_xc[base + (size_t)z * CONVDIM + h * DHEAD + p] * ws[z];
        }
        #pragma unroll
        for (int i = 0; i < 16; i++) {
            int lin = t + i * 256; int zz = lin >> 6; int n = lin & 63; int z = zt * 64 + zz;
            Bsh[zz * 64 + n] = g_xc[base + (size_t)z * CONVDIM + DINNER + n];
        }
        __syncthreads();
        #pragma unroll
        for (int zz = 0; zz < 64; zz++) {
            float xv[8];
            *(float4*)&xv[0] = *(const float4*)&xw[zz * 128 + p0];
            *(float4*)&xv[4] = *(const float4*)&xw[zz * 128 + p0 + 4];
            float4 bv = *(const float4*)&Bsh[zz * 64 + n0];
            float bb[4] = {bv.x, bv.y, bv.z, bv.w};
            #pragma unroll
            for (int i = 0; i < 8; i++)
                #pragma unroll
                for (int j = 0; j < 4; j++)
                    acc[i][j] += xv[i] * bb[j];
        }
        __syncthreads();
    }
    size_t ob = (size_t)blk * DHEAD * DSTATE;
    #pragma unroll
    for (int i = 0; i < 8; i++)
        #pragma unroll
        for (int j = 0; j < 4; j++)
            g_st[ob + (size_t)(p0 + i) * DSTATE + n0 + j] = acc[i][j];
}

// ---------------- inter-chunk scan (16 steps, parallel over (b,h) and (p,n))
__global__ void scan_k() {
    int blk = blockIdx.x;                // b*32 + h
    int h = blk & 31, b = blk >> 5;
    int t = threadIdx.x;
    float carry[32];
    #pragma unroll
    for (int k = 0; k < 32; k++) carry[k] = 0.f;
    for (int c = 0; c < NCHUNK; c++) {
        int idx = (b * NCHUNK + c) * NHEADS + h;
        float decay = expf(g_cum[idx * CHUNK + 255]);
        size_t base = (size_t)idx * DHEAD * DSTATE;
        #pragma unroll
        for (int k = 0; k < 32; k++) {
            size_t e = base + t + k * 256;
            g_pv[e] = carry[k];
            carry[k] = carry[k] * decay + g_st[e];
        }
    }
}

// ---------------- Y kernel: Y = masked(C B^T L) @ xdt + exp(cum)*C@prev^T + D*x
#define BTS 260
#define CTS 68
#define PTS 132
__global__ __launch_bounds__(256, 1)
void y_k(const float* __restrict__ Dvec) {
    extern __shared__ float sm[];
    float* Bt   = sm;                  // [64][BTS]  B^T (n-major)
    float* Gtt  = Bt + 64 * BTS;       // [256][64]  G^T (z-major, masked*L)
    float* Ct   = Gtt + 256 * 64;      // [64][CTS]  C^T tile (n-major)
    float* sX   = Ct + 64 * CTS;       // [64][128]  xdt z-tile
    float* pT   = sX + 64 * 128;       // [64][PTS]  prev^T (n-major)
    float* cums = pT + 64 * PTS;       // [256]
    float* sdt  = cums + 256;          // [256]
    int blk = blockIdx.x;
    int h = blk & 31, c = (blk >> 5) & 15, b = blk >> 9;
    int t = threadIdx.x;
    size_t base = (size_t)(b * SEQ + c * CHUNK) * CONVDIM;

    cums[t] = g_cum[blk * CHUNK + t];
    sdt[t]  = g_dtv[(size_t)(b * SEQ + c * CHUNK + t) * NHEADS + h];
    #pragma unroll
    for (int i = 0; i < 64; i++) {
        int lin = t + i * 256; int n = lin & 63; int z = lin >> 6;
        Bt[n * BTS + z] = g_xc[base + (size_t)z * CONVDIM + DINNER + n];
    }
    size_t pvb = (size_t)blk * DHEAD * DSTATE;
    #pragma unroll
    for (int i = 0; i < 32; i++) {
        int lin = t + i * 256; int n = lin & 63; int p = lin >> 6;
        pT[n * PTS + p] = g_pv[pvb + (size_t)p * DSTATE + n];
    }
    __syncthreads();
    float Dh = Dvec[h];
    const int sg = t & 15, zg = t >> 4;    // phase-1 mapping
    const int pg = t & 15, sg2 = t >> 4;   // phase-2/3 mapping

    for (int st = 0; st < 4; st++) {
        int s0 = st * 64;
        #pragma unroll
        for (int i = 0; i < 16; i++) {
            int lin = t + i * 256; int n = lin & 63; int si = lin >> 6;
            Ct[n * CTS + si] = g_xc[base + (size_t)(s0 + si) * CONVDIM + DINNER + DSTATE + n];
        }
        __syncthreads();
        // -------- phase 1: G^T tile = (C_tile · B^T), masked * L --------
        {
            int sl0 = sg * 4, z0 = zg * 16;
            float acc1[4][16];
            #pragma unroll
            for (int i = 0; i < 4; i++)
                #pragma unroll
                for (int j = 0; j < 16; j++) acc1[i][j] = 0.f;
            if (z0 <= s0 + 63) {
                for (int n = 0; n < 64; n++) {
                    float cv[4];
                    *(float4*)cv = *(const float4*)&Ct[n * CTS + sl0];
                    float bz[16];
                    #pragma unroll
                    for (int j = 0; j < 16; j += 4)
                        *(float4*)&bz[j] = *(const float4*)&Bt[n * BTS + z0 + j];
                    #pragma unroll
                    for (int i = 0; i < 4; i++)
                        #pragma unroll
                        for (int j = 0; j < 16; j++)
                            acc1[i][j] += cv[i] * bz[j];
                }
            }
            #pragma unroll
            for (int i = 0; i < 4; i++) {
                int sgl = s0 + sl0 + i;
                float cs = cums[sgl];
                #pragma unroll
                for (int j = 0; j < 16; j++) {
                    int z = z0 + j;
                    float v = (z <= sgl) ? acc1[i][j] * expf(cs - cums[z]) : 0.f;
                    Gtt[z * 64 + sl0 + i] = v;
                }
            }
        }
        __syncthreads();
        // -------- phase 2: Y_tile += G^T-masked @ xdt (skip fully-masked z-tiles)
        int p0 = pg * 8, sl0 = sg2 * 4;
        float acc2[4][8];
        #pragma unroll
        for (int i = 0; i < 4; i++)
            #pragma unroll
            for (int j = 0; j < 8; j++) acc2[i][j] = 0.f;
        for (int zt = 0; zt <= st; zt++) {
            #pragma unroll
            for (int i = 0; i < 32; i++) {
                int lin = t + i * 256; int zz = lin >> 7; int p = lin & 127; int z = zt * 64 + zz;
                sX[zz * 128 + p] = g_xc[base + (size_t)z * CONVDIM + h * DHEAD + p] * sdt[z];
            }
            __syncthreads();
            #pragma unroll
            for (int zz = 0; zz < 64; zz++) {
                float gv[4];
                *(float4*)gv = *(const float4*)&Gtt[(zt * 64 + zz) * 64 + sl0];
                float xv[8];
                *(float4*)&xv[0] = *(const float4*)&sX[zz * 128 + p0];
                *(float4*)&xv[4] = *(const float4*)&sX[zz * 128 + p0 + 4];
                #pragma unroll
                for (int i = 0; i < 4; i++)
                    #pragma unroll
                    for (int j = 0; j < 8; j++)
                        acc2[i][j] += gv[i] * xv[j];
            }
            __syncthreads();
        }
        // -------- phase 3: Y_off = exp(cum[s]) * C · prev^T --------
        {
            float es[4];
            #pragma unroll
            for (int i = 0; i < 4; i++) es[i] = expf(cums[s0 + sl0 + i]);
            for (int n = 0; n < 64; n++) {
                float cv[4];
                *(float4*)cv = *(const float4*)&Ct[n * CTS + sl0];
                float pv[8];
                *(float4*)&pv[0] = *(const float4*)&pT[n * PTS + p0];
                *(float4*)&pv[4] = *(const float4*)&pT[n * PTS + p0 + 4];
                #pragma unroll
                for (int i = 0; i < 4; i++) {
                    float cvs = cv[i] * es[i];
                    #pragma unroll
                    for (int j = 0; j < 8; j++)
                        acc2[i][j] += cvs * pv[j];
                }
            }
        }
        // -------- store: + D*x --------
        #pragma unroll
        for (int i = 0; i < 4; i++) {
            int s = s0 + sl0 + i;
            size_t row = (size_t)(b * SEQ + c * CHUNK + s);
            #pragma unroll
            for (int j = 0; j < 8; j++) {
                int p = p0 + j;
                g_y[row * DINNER + h * DHEAD + p] =
                    acc2[i][j] + Dh * g_xc[row * CONVDIM + h * DHEAD + p];
            }
        }
        __syncthreads();
    }
}

// ---------------- gated RMSNorm fused with bf16 hi/lo split for GEMM2 ------
__global__ void gatenorm_k(const float* __restrict__ nw) {
    int row = blockIdx.x;
    __shared__ float yg[DINNER];
    __shared__ float red[256];
    int t = threadIdx.x;
    float ss = 0.f;
    size_t zb = (size_t)row * EPROJ;
    size_t yb = (size_t)row * DINNER;
    #pragma unroll
    for (int i = 0; i < 16; i++) {
        int e = t + i * 256;
        float z = g_zx[zb + e];
        float sz = z / (1.f + expf(-z));
        float v = g_y[yb + e] * sz;
        yg[e] = v;
        ss += v * v;
    }
    red[t] = ss;
    __syncthreads();
    for (int off = 128; off > 0; off >>= 1) {
        if (t < off) red[t] += red[t + off];
        __syncthreads();
    }
    float scale = rsqrtf(red[0] / (float)DINNER + 1e-5f);
    #pragma unroll
    for (int i = 0; i < 16; i++) {
        int e = t + i * 256;
        float v = yg[e] * scale * nw[e];
        __nv_bfloat16 h = __float2bfloat16_rn(v);
        g_Ah[yb + e] = h;
        g_Al[yb + e] = __float2bfloat16_rn(v - __bfloat162float(h));
    }
}

// ---------------- launch ----------------
extern "C" void kernel_launch(void* const* d_in, const int* in_sizes, int n_in,
                              void* d_out, int out_size) {
    const float* u     = (const float*)d_in[0];
    const float* W_in  = (const float*)d_in[1];
    const float* convw = (const float*)d_in[2];
    const float* convb = (const float*)d_in[3];
    const float* dtb   = (const float*)d_in[4];
    const float* Alog  = (const float*)d_in[5];
    const float* Dvec  = (const float*)d_in[6];
    const float* nw    = (const float*)d_in[7];
    const float* W_out = (const float*)d_in[8];
    float* out = (float*)d_out;

    float* zx_p;
    __nv_bfloat16 *ah_p, *al_p, *bh_p, *bl_p;
    cudaGetSymbolAddress((void**)&zx_p, g_zx);
    cudaGetSymbolAddress((void**)&ah_p, g_Ah);
    cudaGetSymbolAddress((void**)&al_p, g_Al);
    cudaGetSymbolAddress((void**)&bh_p, g_Bh);
    cudaGetSymbolAddress((void**)&bl_p, g_Bl);

    const int STATES_SMEM = (64 * 128 + 64 * 64 + 256) * 4;
    const int Y_SMEM = (64 * BTS + 256 * 64 + 64 * CTS + 64 * 128 + 64 * PTS + 512) * 4;
    cudaFuncSetAttribute(states_k, cudaFuncAttributeMaxDynamicSharedMemorySize, STATES_SMEM);
    cudaFuncSetAttribute(y_k,      cudaFuncAttributeMaxDynamicSharedMemorySize, Y_SMEM);
    cudaFuncSetAttribute(gemm_bf,  cudaFuncAttributeMaxDynamicSharedMemorySize, GSMEM);

    // ---- GEMM1: zx[8192,8352] = u[8192,2048] @ W_in[8352,2048]^T ----
    {
        int n4a = MROWS * DMODEL / 4;       // u
        int n4b = EPROJ * DMODEL / 4;       // W_in
        split_k<<<(n4a + 255) / 256, 256>>>((const float4*)u, (uint2*)ah_p, (uint2*)al_p, n4a);
        split_k<<<(n4b + 255) / 256, 256>>>((const float4*)W_in, (uint2*)bh_p, (uint2*)bl_p, n4b);
        gemm_bf<<<dim3(66, 64), 256, GSMEM>>>(ah_p, al_p, bh_p, bl_p, zx_p,
                                              MROWS, EPROJ, DMODEL);
    }
    // ---- SSD middle section ----
    conv_silu_k<<<(int)(((size_t)MROWS * CONVDIM) / 256), 256>>>(convw, convb);
    dtcum_k<<<1024, 256>>>(dtb, Alog);
    states_k<<<1024, 256, STATES_SMEM>>>();
    scan_k<<<64, 256>>>();
    y_k<<<1024, 256, Y_SMEM>>>(Dvec);
    gatenorm_k<<<MROWS, 256>>>(nw);     // writes bf16 hi/lo of yn into g_Ah/g_Al
    // ---- GEMM2: out[8192,2048] = yn[8192,4096] @ W_out[2048,4096]^T ----
    {
        int n4b = DMODEL * DINNER / 4;      // W_out
        split_k<<<(n4b + 255) / 256, 256>>>((const float4*)W_out, (uint2*)bh_p, (uint2*)bl_p, n4b);
        gemm_bf<<<dim3(16, 64), 256, GSMEM>>>(ah_p, al_p, bh_p, bl_p, out,
                                              MROWS, DMODEL, DINNER);
    }
}

// round 9
// speedup vs baseline: 1.3944x; 1.3944x over previous
#include <cuda_runtime.h>
#include <cuda_bf16.h>
#include <cstdint>
#include <cstddef>

#define BATCH   2
#define SEQ     4096
#define DMODEL  2048
#define DINNER  4096
#define NHEADS  32
#define DHEAD   128
#define DSTATE  64
#define CONVDIM 4224          // DINNER + 2*DSTATE
#define EPROJ   8352          // 2*DINNER + 2*DSTATE + NHEADS
#define NCHUNK  16
#define CHUNK   256
#define MROWS   8192          // BATCH*SEQ

// ---------------- device scratch (static: allocation-free) ----------------
__device__ float g_zx[(size_t)MROWS * EPROJ];     // in_proj output
__device__ float g_xc[(size_t)MROWS * CONVDIM];   // conv+silu output
__device__ float g_dtv[(size_t)MROWS * NHEADS];   // softplus dt
__device__ float g_cum[BATCH * NCHUNK * NHEADS * CHUNK]; // per-chunk cumsum(dA)
__device__ float g_st[(size_t)BATCH * NCHUNK * NHEADS * DHEAD * DSTATE]; // chunk states
__device__ float g_pv[(size_t)BATCH * NCHUNK * NHEADS * DHEAD * DSTATE]; // prev states
__device__ float g_y [(size_t)MROWS * DINNER];    // y (pre-norm)
// pre-split bf16 operands (hi/lo); sized for the larger GEMM use
__device__ __nv_bfloat16 g_Ah[(size_t)MROWS * DINNER];
__device__ __nv_bfloat16 g_Al[(size_t)MROWS * DINNER];
__device__ __nv_bfloat16 g_Bh[(size_t)EPROJ * DMODEL];
__device__ __nv_bfloat16 g_Bl[(size_t)EPROJ * DMODEL];

// ============================================================================
// helpers
// ============================================================================
__device__ __forceinline__ uint32_t smem_u32(const void* p) {
    uint32_t a;
    asm("{ .reg .u64 t; cvta.to.shared.u64 t, %1; cvt.u32.u64 %0, t; }" : "=r"(a) : "l"(p));
    return a;
}
__device__ __forceinline__ void ldm4(uint32_t* r, uint32_t a) {
    asm volatile("ldmatrix.sync.aligned.m8n8.x4.shared.b16 {%0,%1,%2,%3}, [%4];"
                 : "=r"(r[0]), "=r"(r[1]), "=r"(r[2]), "=r"(r[3]) : "r"(a));
}
__device__ __forceinline__ void mma16816(float* d, const uint32_t* a, uint32_t b0, uint32_t b1) {
    asm volatile("mma.sync.aligned.m16n8k16.row.col.f32.bf16.bf16.f32 "
                 "{%0,%1,%2,%3}, {%4,%5,%6,%7}, {%8,%9}, {%0,%1,%2,%3};"
                 : "+f"(d[0]), "+f"(d[1]), "+f"(d[2]), "+f"(d[3])
                 : "r"(a[0]), "r"(a[1]), "r"(a[2]), "r"(a[3]), "r"(b0), "r"(b1));
}
__device__ __forceinline__ uint32_t pk2(__nv_bfloat16 a, __nv_bfloat16 b) {
    return (uint32_t)__bfloat16_as_ushort(a) | ((uint32_t)__bfloat16_as_ushort(b) << 16);
}
__device__ __forceinline__ void dec4(float4 v, uint2& h, uint2& l) {
    __nv_bfloat16 h0 = __float2bfloat16_rn(v.x), h1 = __float2bfloat16_rn(v.y);
    __nv_bfloat16 h2 = __float2bfloat16_rn(v.z), h3 = __float2bfloat16_rn(v.w);
    __nv_bfloat16 l0 = __float2bfloat16_rn(v.x - __bfloat162float(h0));
    __nv_bfloat16 l1 = __float2bfloat16_rn(v.y - __bfloat162float(h1));
    __nv_bfloat16 l2 = __float2bfloat16_rn(v.z - __bfloat162float(h2));
    __nv_bfloat16 l3 = __float2bfloat16_rn(v.w - __bfloat162float(h3));
    h = make_uint2(pk2(h0, h1), pk2(h2, h3));
    l = make_uint2(pk2(l0, l1), pk2(l2, l3));
}
__device__ __forceinline__ void cpasync16(uint32_t dst, const void* src, int srcsz) {
    asm volatile("cp.async.cg.shared.global [%0], [%1], 16, %2;"
                 :: "r"(dst), "l"(src), "r"(srcsz) : "memory");
}
#define CP_COMMIT() asm volatile("cp.async.commit_group;" ::: "memory")
#define CP_WAIT2()  asm volatile("cp.async.wait_group 2;" ::: "memory")

// ---------------- fp32 -> (hi, lo) bf16 split (memory-bound pass) ----------
__global__ void split_k(const float4* __restrict__ in,
                        uint2* __restrict__ hi, uint2* __restrict__ lo, int n4) {
    int i = blockIdx.x * 256 + threadIdx.x;
    if (i < n4) {
        uint2 h, l;
        dec4(in[i], h, l);
        hi[i] = h;
        lo[i] = l;
    }
}

// ============================================================================
// HMMA bf16x3 NT GEMM on pre-split operands:
// C[M,N] = (Ah+Al)[M,K] * (Bh+Bl)[N,K]^T, D = Ah*Bh + Al*Bh + Ah*Bl.
// Tile 128x128, BK=32, 4-stage cp.async pipeline (R7 config).
// MMA issue is product-major so consecutive mmas hit distinct accumulators
// (same-acc reuse distance 16 issues -> HMMA RAW latency fully hidden).
// ============================================================================
#define BK      32
#define TROW    80                       // padded row bytes: 16-aligned, 5 mod 8 -> ldmatrix conflict-free
#define TILE_B  (128 * TROW)             // 10240 B per bf16 tile
#define STAGE_B (4 * TILE_B)             // Ah | Al | Bh | Bl = 40960 B
#define NSTAGE  4
#define GSMEM   (NSTAGE * STAGE_B)       // 163840 B

__device__ __forceinline__ void ld_stage(uint32_t sb, int stage,
        const __nv_bfloat16* __restrict__ Ah, const __nv_bfloat16* __restrict__ Al,
        const __nv_bfloat16* __restrict__ Bh, const __nv_bfloat16* __restrict__ Bl,
        int m0, int n0, int K, int N, int k0, int t) {
    uint32_t stb = sb + (uint32_t)stage * STAGE_B;
    #pragma unroll
    for (int j = 0; j < 8; j++) {
        int lin = t + j * 256;
        int tile = lin >> 9, li = lin & 511;
        int row = li >> 2, c = li & 3;
        uint32_t dst = stb + (uint32_t)tile * TILE_B + (uint32_t)row * TROW + c * 16;
        const __nv_bfloat16* src;
        int sz = 16;
        if (tile == 0)      src = Ah + (size_t)(m0 + row) * K + k0 + c * 8;
        else if (tile == 1) src = Al + (size_t)(m0 + row) * K + k0 + c * 8;
        else {
            const __nv_bfloat16* base = (tile == 2) ? Bh : Bl;
            int r = n0 + row;
            if (r >= N) { r = 0; sz = 0; }
            src = base + (size_t)r * K + k0 + c * 8;
        }
        cpasync16(dst, src, sz);
    }
}

__global__ __launch_bounds__(256, 1)
void gemm_bf(const __nv_bfloat16* __restrict__ Ah, const __nv_bfloat16* __restrict__ Al,
             const __nv_bfloat16* __restrict__ Bh, const __nv_bfloat16* __restrict__ Bl,
             float* __restrict__ C, int M, int N, int K) {
    extern __shared__ char smem[];
    const uint32_t sb = smem_u32(smem);
    const int t = threadIdx.x, wid = t >> 5, lane = t & 31;
    const int m0 = blockIdx.y * 128, n0b = blockIdx.x * 128;
    const int wm = (wid & 1) * 64, wn = (wid >> 1) * 32;

    float acc[4][4][4];
    #pragma unroll
    for (int i = 0; i < 4; i++)
        #pragma unroll
        for (int j = 0; j < 4; j++)
            #pragma unroll
            for (int k = 0; k < 4; k++) acc[i][j][k] = 0.f;

    const int NC = K / BK;
    // prologue: fill 3 stages
    #pragma unroll
    for (int s = 0; s < NSTAGE - 1; s++) {
        if (s < NC)
            ld_stage(sb, s, Ah, Al, Bh, Bl, m0, n0b, K, N, s * BK, t);
        CP_COMMIT();
    }

    const int lr = lane & 15, lh = lane >> 4;

    for (int c = 0; c < NC; c++) {
        CP_WAIT2();
        __syncthreads();
        uint32_t stb = sb + (uint32_t)(c & (NSTAGE - 1)) * STAGE_B;
        #pragma unroll
        for (int kk = 0; kk < 2; kk++) {
            uint32_t kb = kk * 32 + lh * 16;
            uint32_t ah[4][4], al[4][4], bh[2][4], bl[2][4];
            #pragma unroll
            for (int mf = 0; mf < 4; mf++) {
                uint32_t ro = (uint32_t)(wm + mf * 16 + lr) * TROW + kb;
                ldm4(ah[mf], stb + ro);
                ldm4(al[mf], stb + TILE_B + ro);
            }
            #pragma unroll
            for (int np = 0; np < 2; np++) {
                uint32_t ro = (uint32_t)(wn + np * 16 + lr) * TROW + kb;
                ldm4(bh[np], stb + 2 * TILE_B + ro);
                ldm4(bl[np], stb + 3 * TILE_B + ro);
            }
            // product-major: 16 mmas per pass, all distinct accumulators
            #pragma unroll
            for (int mf = 0; mf < 4; mf++)
                #pragma unroll
                for (int np = 0; np < 2; np++) {
                    mma16816(acc[mf][2 * np],     ah[mf], bh[np][0], bh[np][2]);
                    mma16816(acc[mf][2 * np + 1], ah[mf], bh[np][1], bh[np][3]);
                }
            #pragma unroll
            for (int mf = 0; mf < 4; mf++)
                #pragma unroll
                for (int np = 0; np < 2; np++) {
                    mma16816(acc[mf][2 * np],     al[mf], bh[np][0], bh[np][2]);
                    mma16816(acc[mf][2 * np + 1], al[mf], bh[np][1], bh[np][3]);
                }
            #pragma unroll
            for (int mf = 0; mf < 4; mf++)
                #pragma unroll
                for (int np = 0; np < 2; np++) {
                    mma16816(acc[mf][2 * np],     ah[mf], bl[np][0], bl[np][2]);
                    mma16816(acc[mf][2 * np + 1], ah[mf], bl[np][1], bl[np][3]);
                }
        }
        __syncthreads();
        int nx = c + NSTAGE - 1;
        if (nx < NC)
            ld_stage(sb, nx & (NSTAGE - 1), Ah, Al, Bh, Bl, m0, n0b, K, N, nx * BK, t);
        CP_COMMIT();
    }

    // epilogue: mma C layout — row = lane>>2 (+8), col = (lane&3)*2 (+1)
    const int gr = lane >> 2, gc = (lane & 3) * 2;
    #pragma unroll
    for (int mf = 0; mf < 4; mf++) {
        int m = m0 + wm + mf * 16 + gr;
        #pragma unroll
        for (int nf = 0; nf < 4; nf++) {
            int n = n0b + wn + nf * 8 + gc;
            if (n < N) {
                *(float2*)&C[(size_t)m * N + n] =
                    make_float2(acc[mf][nf][0], acc[mf][nf][1]);
                *(float2*)&C[(size_t)(m + 8) * N + n] =
                    make_float2(acc[mf][nf][2], acc[mf][nf][3]);
            }
        }
    }
}

// ---------------- conv1d (depthwise, causal, D_CONV=4) + SiLU ----------------
__global__ void conv_silu_k(const float* __restrict__ cw, const float* __restrict__ cb) {
    size_t idx = (size_t)blockIdx.x * 256 + threadIdx.x;
    int c = (int)(idx % CONVDIM);
    size_t bl = idx / CONVDIM;
    int l = (int)(bl % SEQ);
    int b = (int)(bl / SEQ);
    float acc = cb[c];
    #pragma unroll
    for (int k = 0; k < 4; k++) {
        int ls = l - 3 + k;
        if (ls >= 0)
            acc += g_zx[((size_t)(b * SEQ + ls)) * EPROJ + DINNER + c] * cw[c * 4 + k];
    }
    acc = acc / (1.f + __expf(-acc));
    g_xc[idx] = acc;
}

// ---------------- dt softplus + per-chunk cumsum(dA) ----------------
__global__ void dtcum_k(const float* __restrict__ dtb, const float* __restrict__ Alog) {
    int blk = blockIdx.x;                // ((b*16+c)*32+h)
    int h = blk & 31, c = (blk >> 5) & 15, b = blk >> 9;
    int s = threadIdx.x;
    int l = c * CHUNK + s;
    float raw = g_zx[((size_t)(b * SEQ + l)) * EPROJ + (EPROJ - NHEADS) + h] + dtb[h];
    float dtv = (raw > 20.f) ? raw : log1pf(__expf(raw));
    g_dtv[(size_t)(b * SEQ + l) * NHEADS + h] = dtv;
    float dA = dtv * (-__expf(Alog[h]));
    __shared__ float sc[256];
    sc[s] = dA;
    __syncthreads();
    for (int off = 1; off < 256; off <<= 1) {
        float v = (s >= off) ? sc[s - off] : 0.f;
        __syncthreads();
        sc[s] += v;
        __syncthreads();
    }
    g_cum[blk * CHUNK + s] = sc[s];
}

// ---------------- per-chunk states: st[p,n] = sum_z exp(cumL-cum[z])*dt[z]*x[z,p]*B[z,n]
__global__ __launch_bounds__(256)
void states_k() {
    extern __shared__ float sm[];
    float* xw  = sm;                 // 64*128
    float* Bsh = xw + 64 * 128;      // 64*64
    float* ws  = Bsh + 64 * 64;      // 256
    int blk = blockIdx.x;
    int h = blk & 31, c = (blk >> 5) & 15, b = blk >> 9;
    int t = threadIdx.x;
    float clast = g_cum[blk * CHUNK + 255];
    {
        float cz = g_cum[blk * CHUNK + t];
        float dtv = g_dtv[(size_t)(b * SEQ + c * CHUNK + t) * NHEADS + h];
        ws[t] = __expf(clast - cz) * dtv;
    }
    __syncthreads();
    int tx = t & 15, ty = t >> 4;
    int p0 = tx * 8, n0 = ty * 4;
    float acc[8][4];
    #pragma unroll
    for (int i = 0; i < 8; i++)
        #pragma unroll
        for (int j = 0; j < 4; j++) acc[i][j] = 0.f;
    size_t base = (size_t)(b * SEQ + c * CHUNK) * CONVDIM;
    for (int zt = 0; zt < 4; zt++) {
        #pragma unroll
        for (int i = 0; i < 32; i++) {
            int lin = t + i * 256; int zz = lin >> 7; int p = lin & 127; int z = zt * 64 + zz;
            xw[zz * 128 + p] = g_xc[base + (size_t)z * CONVDIM + h * DHEAD + p] * ws[z];
        }
        #pragma unroll
        for (int i = 0; i < 16; i++) {
            int lin = t + i * 256; int zz = lin >> 6; int n = lin & 63; int z = zt * 64 + zz;
            Bsh[zz * 64 + n] = g_xc[base + (size_t)z * CONVDIM + DINNER + n];
        }
        __syncthreads();
        #pragma unroll
        for (int zz = 0; zz < 64; zz++) {
            float xv[8];
            *(float4*)&xv[0] = *(const float4*)&xw[zz * 128 + p0];
            *(float4*)&xv[4] = *(const float4*)&xw[zz * 128 + p0 + 4];
            float4 bv = *(const float4*)&Bsh[zz * 64 + n0];
            float bb[4] = {bv.x, bv.y, bv.z, bv.w};
            #pragma unroll
            for (int i = 0; i < 8; i++)
                #pragma unroll
                for (int j = 0; j < 4; j++)
                    acc[i][j] += xv[i] * bb[j];
        }
        __syncthreads();
    }
    size_t ob = (size_t)blk * DHEAD * DSTATE;
    #pragma unroll
    for (int i = 0; i < 8; i++)
        #pragma unroll
        for (int j = 0; j < 4; j++)
            g_st[ob + (size_t)(p0 + i) * DSTATE + n0 + j] = acc[i][j];
}

// ---------------- inter-chunk scan (16 steps, parallel over (b,h) and (p,n))
__global__ void scan_k() {
    int blk = blockIdx.x;                // b*32 + h
    int h = blk & 31, b = blk >> 5;
    int t = threadIdx.x;
    float carry[32];
    #pragma unroll
    for (int k = 0; k < 32; k++) carry[k] = 0.f;
    for (int c = 0; c < NCHUNK; c++) {
        int idx = (b * NCHUNK + c) * NHEADS + h;
        float decay = __expf(g_cum[idx * CHUNK + 255]);
        size_t base = (size_t)idx * DHEAD * DSTATE;
        #pragma unroll
        for (int k = 0; k < 32; k++) {
            size_t e = base + t + k * 256;
            g_pv[e] = carry[k];
            carry[k] = carry[k] * decay + g_st[e];
        }
    }
}

// ---------------- Y kernel: Y = masked(C B^T L) @ xdt + exp(cum)*C@prev^T + D*x
#define BTS 260
#define CTS 68
#define PTS 132
__global__ __launch_bounds__(256, 1)
void y_k(const float* __restrict__ Dvec) {
    extern __shared__ float sm[];
    float* Bt   = sm;                  // [64][BTS]  B^T (n-major)
    float* Gtt  = Bt + 64 * BTS;       // [256][64]  G^T (z-major, masked*L)
    float* Ct   = Gtt + 256 * 64;      // [64][CTS]  C^T tile (n-major)
    float* sX   = Ct + 64 * CTS;       // [64][128]  xdt z-tile
    float* pT   = sX + 64 * 128;       // [64][PTS]  prev^T (n-major)
    float* cums = pT + 64 * PTS;       // [256]
    float* sdt  = cums + 256;          // [256]
    int blk = blockIdx.x;
    int h = blk & 31, c = (blk >> 5) & 15, b = blk >> 9;
    int t = threadIdx.x;
    size_t base = (size_t)(b * SEQ + c * CHUNK) * CONVDIM;

    cums[t] = g_cum[blk * CHUNK + t];
    sdt[t]  = g_dtv[(size_t)(b * SEQ + c * CHUNK + t) * NHEADS + h];
    #pragma unroll
    for (int i = 0; i < 64; i++) {
        int lin = t + i * 256; int n = lin & 63; int z = lin >> 6;
        Bt[n * BTS + z] = g_xc[base + (size_t)z * CONVDIM + DINNER + n];
    }
    size_t pvb = (size_t)blk * DHEAD * DSTATE;
    #pragma unroll
    for (int i = 0; i < 32; i++) {
        int lin = t + i * 256; int n = lin & 63; int p = lin >> 6;
        pT[n * PTS + p] = g_pv[pvb + (size_t)p * DSTATE + n];
    }
    __syncthreads();
    float Dh = Dvec[h];
    const int sg = t & 15, zg = t >> 4;    // phase-1 mapping
    const int pg = t & 15, sg2 = t >> 4;   // phase-2/3 mapping

    for (int st = 0; st < 4; st++) {
        int s0 = st * 64;
        #pragma unroll
        for (int i = 0; i < 16; i++) {
            int lin = t + i * 256; int n = lin & 63; int si = lin >> 6;
            Ct[n * CTS + si] = g_xc[base + (size_t)(s0 + si) * CONVDIM + DINNER + DSTATE + n];
        }
        __syncthreads();
        // -------- phase 1: G^T tile = (C_tile · B^T), masked * L --------
        {
            int sl0 = sg * 4, z0 = zg * 16;
            float acc1[4][16];
            #pragma unroll
            for (int i = 0; i < 4; i++)
                #pragma unroll
                for (int j = 0; j < 16; j++) acc1[i][j] = 0.f;
            if (z0 <= s0 + 63) {
                for (int n = 0; n < 64; n++) {
                    float cv[4];
                    *(float4*)cv = *(const float4*)&Ct[n * CTS + sl0];
                    float bz[16];
                    #pragma unroll
                    for (int j = 0; j < 16; j += 4)
                        *(float4*)&bz[j] = *(const float4*)&Bt[n * BTS + z0 + j];
                    #pragma unroll
                    for (int i = 0; i < 4; i++)
                        #pragma unroll
                        for (int j = 0; j < 16; j++)
                            acc1[i][j] += cv[i] * bz[j];
                }
            }
            #pragma unroll
            for (int i = 0; i < 4; i++) {
                int sgl = s0 + sl0 + i;
                float cs = cums[sgl];
                #pragma unroll
                for (int j = 0; j < 16; j++) {
                    int z = z0 + j;
                    float v = (z <= sgl) ? acc1[i][j] * __expf(cs - cums[z]) : 0.f;
                    Gtt[z * 64 + sl0 + i] = v;
                }
            }
        }
        __syncthreads();
        // -------- phase 2: Y_tile += G^T-masked @ xdt (skip fully-masked z-tiles)
        int p0 = pg * 8, sl0 = sg2 * 4;
        float acc2[4][8];
        #pragma unroll
        for (int i = 0; i < 4; i++)
            #pragma unroll
            for (int j = 0; j < 8; j++) acc2[i][j] = 0.f;
        for (int zt = 0; zt <= st; zt++) {
            #pragma unroll
            for (int i = 0; i < 32; i++) {
                int lin = t + i * 256; int zz = lin >> 7; int p = lin & 127; int z = zt * 64 + zz;
                sX[zz * 128 + p] = g_xc[base + (size_t)z * CONVDIM + h * DHEAD + p] * sdt[z];
            }
            __syncthreads();
            #pragma unroll
            for (int zz = 0; zz < 64; zz++) {
                float gv[4];
                *(float4*)gv = *(const float4*)&Gtt[(zt * 64 + zz) * 64 + sl0];
                float xv[8];
                *(float4*)&xv[0] = *(const float4*)&sX[zz * 128 + p0];
                *(float4*)&xv[4] = *(const float4*)&sX[zz * 128 + p0 + 4];
                #pragma unroll
                for (int i = 0; i < 4; i++)
                    #pragma unroll
                    for (int j = 0; j < 8; j++)
                        acc2[i][j] += gv[i] * xv[j];
            }
            __syncthreads();
        }
        // -------- phase 3: Y_off = exp(cum[s]) * C · prev^T --------
        {
            float es[4];
            #pragma unroll
            for (int i = 0; i < 4; i++) es[i] = __expf(cums[s0 + sl0 + i]);
            for (int n = 0; n < 64; n++) {
                float cv[4];
                *(float4*)cv = *(const float4*)&Ct[n * CTS + sl0];
                float pv[8];
                *(float4*)&pv[0] = *(const float4*)&pT[n * PTS + p0];
                *(float4*)&pv[4] = *(const float4*)&pT[n * PTS + p0 + 4];
                #pragma unroll
                for (int i = 0; i < 4; i++) {
                    float cvs = cv[i] * es[i];
                    #pragma unroll
                    for (int j = 0; j < 8; j++)
                        acc2[i][j] += cvs * pv[j];
                }
            }
        }
        // -------- store: + D*x --------
        #pragma unroll
        for (int i = 0; i < 4; i++) {
            int s = s0 + sl0 + i;
            size_t row = (size_t)(b * SEQ + c * CHUNK + s);
            #pragma unroll
            for (int j = 0; j < 8; j++) {
                int p = p0 + j;
                g_y[row * DINNER + h * DHEAD + p] =
                    acc2[i][j] + Dh * g_xc[row * CONVDIM + h * DHEAD + p];
            }
        }
        __syncthreads();
    }
}

// ---------------- gated RMSNorm fused with bf16 hi/lo split for GEMM2 ------
__global__ void gatenorm_k(const float* __restrict__ nw) {
    int row = blockIdx.x;
    __shared__ float yg[DINNER];
    __shared__ float red[256];
    int t = threadIdx.x;
    float ss = 0.f;
    size_t zb = (size_t)row * EPROJ;
    size_t yb = (size_t)row * DINNER;
    #pragma unroll
    for (int i = 0; i < 16; i++) {
        int e = t + i * 256;
        float z = g_zx[zb + e];
        float sz = z / (1.f + __expf(-z));
        float v = g_y[yb + e] * sz;
        yg[e] = v;
        ss += v * v;
    }
    red[t] = ss;
    __syncthreads();
    for (int off = 128; off > 0; off >>= 1) {
        if (t < off) red[t] += red[t + off];
        __syncthreads();
    }
    float scale = rsqrtf(red[0] / (float)DINNER + 1e-5f);
    #pragma unroll
    for (int i = 0; i < 16; i++) {
        int e = t + i * 256;
        float v = yg[e] * scale * nw[e];
        __nv_bfloat16 h = __float2bfloat16_rn(v);
        g_Ah[yb + e] = h;
        g_Al[yb + e] = __float2bfloat16_rn(v - __bfloat162float(h));
    }
}

// ---------------- launch ----------------
extern "C" void kernel_launch(void* const* d_in, const int* in_sizes, int n_in,
                              void* d_out, int out_size) {
    const float* u     = (const float*)d_in[0];
    const float* W_in  = (const float*)d_in[1];
    const float* convw = (const float*)d_in[2];
    const float* convb = (const float*)d_in[3];
    const float* dtb   = (const float*)d_in[4];
    const float* Alog  = (const float*)d_in[5];
    const float* Dvec  = (const float*)d_in[6];
    const float* nw    = (const float*)d_in[7];
    const float* W_out = (const float*)d_in[8];
    float* out = (float*)d_out;

    float* zx_p;
    __nv_bfloat16 *ah_p, *al_p, *bh_p, *bl_p;
    cudaGetSymbolAddress((void**)&zx_p, g_zx);
    cudaGetSymbolAddress((void**)&ah_p, g_Ah);
    cudaGetSymbolAddress((void**)&al_p, g_Al);
    cudaGetSymbolAddress((void**)&bh_p, g_Bh);
    cudaGetSymbolAddress((void**)&bl_p, g_Bl);

    const int STATES_SMEM = (64 * 128 + 64 * 64 + 256) * 4;
    const int Y_SMEM = (64 * BTS + 256 * 64 + 64 * CTS + 64 * 128 + 64 * PTS + 512) * 4;
    cudaFuncSetAttribute(states_k, cudaFuncAttributeMaxDynamicSharedMemorySize, STATES_SMEM);
    cudaFuncSetAttribute(y_k,      cudaFuncAttributeMaxDynamicSharedMemorySize, Y_SMEM);
    cudaFuncSetAttribute(gemm_bf,  cudaFuncAttributeMaxDynamicSharedMemorySize, GSMEM);

    // ---- GEMM1: zx[8192,8352] = u[8192,2048] @ W_in[8352,2048]^T ----
    {
        int n4a = MROWS * DMODEL / 4;       // u
        int n4b = EPROJ * DMODEL / 4;       // W_in
        split_k<<<(n4a + 255) / 256, 256>>>((const float4*)u, (uint2*)ah_p, (uint2*)al_p, n4a);
        split_k<<<(n4b + 255) / 256, 256>>>((const float4*)W_in, (uint2*)bh_p, (uint2*)bl_p, n4b);
        gemm_bf<<<dim3(66, 64), 256, GSMEM>>>(ah_p, al_p, bh_p, bl_p, zx_p,
                                              MROWS, EPROJ, DMODEL);
    }
    // ---- SSD middle section ----
    conv_silu_k<<<(int)(((size_t)MROWS * CONVDIM) / 256), 256>>>(convw, convb);
    dtcum_k<<<1024, 256>>>(dtb, Alog);
    states_k<<<1024, 256, STATES_SMEM>>>();
    scan_k<<<64, 256>>>();
    y_k<<<1024, 256, Y_SMEM>>>(Dvec);
    gatenorm_k<<<MROWS, 256>>>(nw);     // writes bf16 hi/lo of yn into g_Ah/g_Al
    // ---- GEMM2: out[8192,2048] = yn[8192,4096] @ W_out[2048,4096]^T ----
    {
        int n4b = DMODEL * DINNER / 4;      // W_out
        split_k<<<(n4b + 255) / 256, 256>>>((const float4*)W_out, (uint2*)bh_p, (uint2*)bl_p, n4b);
        gemm_bf<<<dim3(16, 64), 256, GSMEM>>>(ah_p, al_p, bh_p, bl_p, out,
                                              MROWS, DMODEL, DINNER);
    }
}

// round 10
// speedup vs baseline: 1.4102x; 1.0113x over previous
#include <cuda_runtime.h>
#include <cuda_bf16.h>
#include <cstdint>
#include <cstddef>

#define BATCH   2
#define SEQ     4096
#define DMODEL  2048
#define DINNER  4096
#define NHEADS  32
#define DHEAD   128
#define DSTATE  64
#define CONVDIM 4224          // DINNER + 2*DSTATE
#define EPROJ   8352          // 2*DINNER + 2*DSTATE + NHEADS
#define NCHUNK  16
#define CHUNK   256
#define MROWS   8192          // BATCH*SEQ

// ---------------- device scratch (static: allocation-free) ----------------
__device__ float g_zx[(size_t)MROWS * EPROJ];     // in_proj output
__device__ float g_xc[(size_t)MROWS * CONVDIM];   // conv+silu output
__device__ float g_dtv[(size_t)MROWS * NHEADS];   // softplus dt
__device__ float g_cum[BATCH * NCHUNK * NHEADS * CHUNK]; // per-chunk cumsum(dA)
__device__ float g_st[(size_t)BATCH * NCHUNK * NHEADS * DHEAD * DSTATE]; // chunk states
__device__ float g_pv[(size_t)BATCH * NCHUNK * NHEADS * DHEAD * DSTATE]; // prev states
__device__ float g_y [(size_t)MROWS * DINNER];    // y (pre-norm)
// pre-split bf16 operands (hi/lo); sized for the larger GEMM use
__device__ __nv_bfloat16 g_Ah[(size_t)MROWS * DINNER];
__device__ __nv_bfloat16 g_Al[(size_t)MROWS * DINNER];
__device__ __nv_bfloat16 g_Bh[(size_t)EPROJ * DMODEL];
__device__ __nv_bfloat16 g_Bl[(size_t)EPROJ * DMODEL];

// ============================================================================
// helpers
// ============================================================================
__device__ __forceinline__ uint32_t smem_u32(const void* p) {
    uint32_t a;
    asm("{ .reg .u64 t; cvta.to.shared.u64 t, %1; cvt.u32.u64 %0, t; }" : "=r"(a) : "l"(p));
    return a;
}
__device__ __forceinline__ void ldm4(uint32_t* r, uint32_t a) {
    asm volatile("ldmatrix.sync.aligned.m8n8.x4.shared.b16 {%0,%1,%2,%3}, [%4];"
                 : "=r"(r[0]), "=r"(r[1]), "=r"(r[2]), "=r"(r[3]) : "r"(a));
}
__device__ __forceinline__ void mma16816(float* d, const uint32_t* a, uint32_t b0, uint32_t b1) {
    asm volatile("mma.sync.aligned.m16n8k16.row.col.f32.bf16.bf16.f32 "
                 "{%0,%1,%2,%3}, {%4,%5,%6,%7}, {%8,%9}, {%0,%1,%2,%3};"
                 : "+f"(d[0]), "+f"(d[1]), "+f"(d[2]), "+f"(d[3])
                 : "r"(a[0]), "r"(a[1]), "r"(a[2]), "r"(a[3]), "r"(b0), "r"(b1));
}
__device__ __forceinline__ uint32_t pk2(__nv_bfloat16 a, __nv_bfloat16 b) {
    return (uint32_t)__bfloat16_as_ushort(a) | ((uint32_t)__bfloat16_as_ushort(b) << 16);
}
__device__ __forceinline__ void dec4(float4 v, uint2& h, uint2& l) {
    __nv_bfloat16 h0 = __float2bfloat16_rn(v.x), h1 = __float2bfloat16_rn(v.y);
    __nv_bfloat16 h2 = __float2bfloat16_rn(v.z), h3 = __float2bfloat16_rn(v.w);
    __nv_bfloat16 l0 = __float2bfloat16_rn(v.x - __bfloat162float(h0));
    __nv_bfloat16 l1 = __float2bfloat16_rn(v.y - __bfloat162float(h1));
    __nv_bfloat16 l2 = __float2bfloat16_rn(v.z - __bfloat162float(h2));
    __nv_bfloat16 l3 = __float2bfloat16_rn(v.w - __bfloat162float(h3));
    h = make_uint2(pk2(h0, h1), pk2(h2, h3));
    l = make_uint2(pk2(l0, l1), pk2(l2, l3));
}
__device__ __forceinline__ void cpasync16(uint32_t dst, const void* src, int srcsz) {
    asm volatile("cp.async.cg.shared.global [%0], [%1], 16, %2;"
                 :: "r"(dst), "l"(src), "r"(srcsz) : "memory");
}
#define CP_COMMIT() asm volatile("cp.async.commit_group;" ::: "memory")
#define CP_WAIT2()  asm volatile("cp.async.wait_group 2;" ::: "memory")

// ---------------- fp32 -> (hi, lo) bf16 split (memory-bound pass) ----------
__global__ void split_k(const float4* __restrict__ in,
                        uint2* __restrict__ hi, uint2* __restrict__ lo, int n4) {
    int i = blockIdx.x * 256 + threadIdx.x;
    if (i < n4) {
        uint2 h, l;
        dec4(in[i], h, l);
        hi[i] = h;
        lo[i] = l;
    }
}

// ============================================================================
// HMMA bf16x3 NT GEMM on pre-split operands:
// C[M,N] = (Ah+Al)[M,K] * (Bh+Bl)[N,K]^T, D = Ah*Bh + Al*Bh + Ah*Bl.
// Tile 128x128, BK=32, 4-stage cp.async pipeline.
// ONE barrier per chunk; next stage's cp.async issued BEFORE the MMA block so
// loads overlap compute (stage slot written == stage read at chunk c-1, and
// all warps passed this chunk's barrier after finishing c-1 -> no race).
// ============================================================================
#define BK      32
#define TROW    80                       // padded row bytes: 16-aligned, 5 mod 8 -> ldmatrix conflict-free
#define TILE_B  (128 * TROW)             // 10240 B per bf16 tile
#define STAGE_B (4 * TILE_B)             // Ah | Al | Bh | Bl = 40960 B
#define NSTAGE  4
#define GSMEM   (NSTAGE * STAGE_B)       // 163840 B

__device__ __forceinline__ void ld_stage(uint32_t sb, int stage,
        const __nv_bfloat16* __restrict__ Ah, const __nv_bfloat16* __restrict__ Al,
        const __nv_bfloat16* __restrict__ Bh, const __nv_bfloat16* __restrict__ Bl,
        int m0, int n0, int K, int N, int k0, int t) {
    uint32_t stb = sb + (uint32_t)stage * STAGE_B;
    #pragma unroll
    for (int j = 0; j < 8; j++) {
        int lin = t + j * 256;
        int tile = lin >> 9, li = lin & 511;
        int row = li >> 2, c = li & 3;
        uint32_t dst = stb + (uint32_t)tile * TILE_B + (uint32_t)row * TROW + c * 16;
        const __nv_bfloat16* src;
        int sz = 16;
        if (tile == 0)      src = Ah + (size_t)(m0 + row) * K + k0 + c * 8;
        else if (tile == 1) src = Al + (size_t)(m0 + row) * K + k0 + c * 8;
        else {
            const __nv_bfloat16* base = (tile == 2) ? Bh : Bl;
            int r = n0 + row;
            if (r >= N) { r = 0; sz = 0; }
            src = base + (size_t)r * K + k0 + c * 8;
        }
        cpasync16(dst, src, sz);
    }
}

__global__ __launch_bounds__(256, 1)
void gemm_bf(const __nv_bfloat16* __restrict__ Ah, const __nv_bfloat16* __restrict__ Al,
             const __nv_bfloat16* __restrict__ Bh, const __nv_bfloat16* __restrict__ Bl,
             float* __restrict__ C, int M, int N, int K) {
    extern __shared__ char smem[];
    const uint32_t sb = smem_u32(smem);
    const int t = threadIdx.x, wid = t >> 5, lane = t & 31;
    const int m0 = blockIdx.y * 128, n0b = blockIdx.x * 128;
    const int wm = (wid & 1) * 64, wn = (wid >> 1) * 32;

    float acc[4][4][4];
    #pragma unroll
    for (int i = 0; i < 4; i++)
        #pragma unroll
        for (int j = 0; j < 4; j++)
            #pragma unroll
            for (int k = 0; k < 4; k++) acc[i][j][k] = 0.f;

    const int NC = K / BK;
    // prologue: fill 3 stages
    #pragma unroll
    for (int s = 0; s < NSTAGE - 1; s++) {
        if (s < NC)
            ld_stage(sb, s, Ah, Al, Bh, Bl, m0, n0b, K, N, s * BK, t);
        CP_COMMIT();
    }

    const int lr = lane & 15, lh = lane >> 4;

    for (int c = 0; c < NC; c++) {
        CP_WAIT2();
        __syncthreads();
        // issue next stage NOW so it overlaps this chunk's MMAs (slot == the
        // stage consumed at chunk c-1; barrier above makes the reuse safe)
        int nx = c + NSTAGE - 1;
        if (nx < NC)
            ld_stage(sb, nx & (NSTAGE - 1), Ah, Al, Bh, Bl, m0, n0b, K, N, nx * BK, t);
        CP_COMMIT();

        uint32_t stb = sb + (uint32_t)(c & (NSTAGE - 1)) * STAGE_B;
        #pragma unroll
        for (int kk = 0; kk < 2; kk++) {
            uint32_t kb = kk * 32 + lh * 16;
            uint32_t ah[4][4], al[4][4], bh[2][4], bl[2][4];
            #pragma unroll
            for (int mf = 0; mf < 4; mf++) {
                uint32_t ro = (uint32_t)(wm + mf * 16 + lr) * TROW + kb;
                ldm4(ah[mf], stb + ro);
                ldm4(al[mf], stb + TILE_B + ro);
            }
            #pragma unroll
            for (int np = 0; np < 2; np++) {
                uint32_t ro = (uint32_t)(wn + np * 16 + lr) * TROW + kb;
                ldm4(bh[np], stb + 2 * TILE_B + ro);
                ldm4(bl[np], stb + 3 * TILE_B + ro);
            }
            // product-major: consecutive mmas hit distinct accumulators
            #pragma unroll
            for (int mf = 0; mf < 4; mf++)
                #pragma unroll
                for (int np = 0; np < 2; np++) {
                    mma16816(acc[mf][2 * np],     ah[mf], bh[np][0], bh[np][2]);
                    mma16816(acc[mf][2 * np + 1], ah[mf], bh[np][1], bh[np][3]);
                }
            #pragma unroll
            for (int mf = 0; mf < 4; mf++)
                #pragma unroll
                for (int np = 0; np < 2; np++) {
                    mma16816(acc[mf][2 * np],     al[mf], bh[np][0], bh[np][2]);
                    mma16816(acc[mf][2 * np + 1], al[mf], bh[np][1], bh[np][3]);
                }
            #pragma unroll
            for (int mf = 0; mf < 4; mf++)
                #pragma unroll
                for (int np = 0; np < 2; np++) {
                    mma16816(acc[mf][2 * np],     ah[mf], bl[np][0], bl[np][2]);
                    mma16816(acc[mf][2 * np + 1], ah[mf], bl[np][1], bl[np][3]);
                }
        }
    }

    // epilogue: mma C layout — row = lane>>2 (+8), col = (lane&3)*2 (+1)
    const int gr = lane >> 2, gc = (lane & 3) * 2;
    #pragma unroll
    for (int mf = 0; mf < 4; mf++) {
        int m = m0 + wm + mf * 16 + gr;
        #pragma unroll
        for (int nf = 0; nf < 4; nf++) {
            int n = n0b + wn + nf * 8 + gc;
            if (n < N) {
                *(float2*)&C[(size_t)m * N + n] =
                    make_float2(acc[mf][nf][0], acc[mf][nf][1]);
                *(float2*)&C[(size_t)(m + 8) * N + n] =
                    make_float2(acc[mf][nf][2], acc[mf][nf][3]);
            }
        }
    }
}

// ---------------- conv1d (depthwise, causal, D_CONV=4) + SiLU, float4 -------
__global__ void conv_silu_k(const float* __restrict__ cw, const float* __restrict__ cb) {
    const int C4 = CONVDIM / 4;                    // 1056
    int idx = blockIdx.x * 256 + threadIdx.x;      // one float4 (4 channels)
    int c4 = idx % C4;
    int bl = idx / C4;                             // 0..MROWS-1
    int l = bl & (SEQ - 1), b = bl / SEQ;
    int c = c4 * 4;
    float4 acc = *(const float4*)&cb[c];
    float w[4][4];
    #pragma unroll
    for (int j = 0; j < 4; j++)
        *(float4*)w[j] = *(const float4*)&cw[(c + j) * 4];
    #pragma unroll
    for (int k = 0; k < 4; k++) {
        int ls = l - 3 + k;
        if (ls >= 0) {
            float4 v = *(const float4*)&g_zx[(size_t)(b * SEQ + ls) * EPROJ + DINNER + c];
            acc.x += v.x * w[0][k];
            acc.y += v.y * w[1][k];
            acc.z += v.z * w[2][k];
            acc.w += v.w * w[3][k];
        }
    }
    acc.x = acc.x / (1.f + __expf(-acc.x));
    acc.y = acc.y / (1.f + __expf(-acc.y));
    acc.z = acc.z / (1.f + __expf(-acc.z));
    acc.w = acc.w / (1.f + __expf(-acc.w));
    *(float4*)&g_xc[(size_t)bl * CONVDIM + c] = acc;
}

// ---------------- dt softplus + per-chunk cumsum(dA) ----------------
__global__ void dtcum_k(const float* __restrict__ dtb, const float* __restrict__ Alog) {
    int blk = blockIdx.x;                // ((b*16+c)*32+h)
    int h = blk & 31, c = (blk >> 5) & 15, b = blk >> 9;
    int s = threadIdx.x;
    int l = c * CHUNK + s;
    float raw = g_zx[((size_t)(b * SEQ + l)) * EPROJ + (EPROJ - NHEADS) + h] + dtb[h];
    float dtv = (raw > 20.f) ? raw : log1pf(__expf(raw));
    g_dtv[(size_t)(b * SEQ + l) * NHEADS + h] = dtv;
    float dA = dtv * (-__expf(Alog[h]));
    __shared__ float sc[256];
    sc[s] = dA;
    __syncthreads();
    for (int off = 1; off < 256; off <<= 1) {
        float v = (s >= off) ? sc[s - off] : 0.f;
        __syncthreads();
        sc[s] += v;
        __syncthreads();
    }
    g_cum[blk * CHUNK + s] = sc[s];
}

// ---------------- per-chunk states: st[p,n] = sum_z exp(cumL-cum[z])*dt[z]*x[z,p]*B[z,n]
__global__ __launch_bounds__(256)
void states_k() {
    extern __shared__ float sm[];
    float* xw  = sm;                 // 64*128
    float* Bsh = xw + 64 * 128;      // 64*64
    float* ws  = Bsh + 64 * 64;      // 256
    int blk = blockIdx.x;
    int h = blk & 31, c = (blk >> 5) & 15, b = blk >> 9;
    int t = threadIdx.x;
    float clast = g_cum[blk * CHUNK + 255];
    {
        float cz = g_cum[blk * CHUNK + t];
        float dtv = g_dtv[(size_t)(b * SEQ + c * CHUNK + t) * NHEADS + h];
        ws[t] = __expf(clast - cz) * dtv;
    }
    __syncthreads();
    int tx = t & 15, ty = t >> 4;
    int p0 = tx * 8, n0 = ty * 4;
    float acc[8][4];
    #pragma unroll
    for (int i = 0; i < 8; i++)
        #pragma unroll
        for (int j = 0; j < 4; j++) acc[i][j] = 0.f;
    size_t base = (size_t)(b * SEQ + c * CHUNK) * CONVDIM;
    for (int zt = 0; zt < 4; zt++) {
        #pragma unroll
        for (int i = 0; i < 32; i++) {
            int lin = t + i * 256; int zz = lin >> 7; int p = lin & 127; int z = zt * 64 + zz;
            xw[zz * 128 + p] = g_xc[base + (size_t)z * CONVDIM + h * DHEAD + p] * ws[z];
        }
        #pragma unroll
        for (int i = 0; i < 16; i++) {
            int lin = t + i * 256; int zz = lin >> 6; int n = lin & 63; int z = zt * 64 + zz;
            Bsh[zz * 64 + n] = g_xc[base + (size_t)z * CONVDIM + DINNER + n];
        }
        __syncthreads();
        #pragma unroll
        for (int zz = 0; zz < 64; zz++) {
            float xv[8];
            *(float4*)&xv[0] = *(const float4*)&xw[zz * 128 + p0];
            *(float4*)&xv[4] = *(const float4*)&xw[zz * 128 + p0 + 4];
            float4 bv = *(const float4*)&Bsh[zz * 64 + n0];
            float bb[4] = {bv.x, bv.y, bv.z, bv.w};
            #pragma unroll
            for (int i = 0; i < 8; i++)
                #pragma unroll
                for (int j = 0; j < 4; j++)
                    acc[i][j] += xv[i] * bb[j];
        }
        __syncthreads();
    }
    size_t ob = (size_t)blk * DHEAD * DSTATE;
    #pragma unroll
    for (int i = 0; i < 8; i++)
        #pragma unroll
        for (int j = 0; j < 4; j++)
            g_st[ob + (size_t)(p0 + i) * DSTATE + n0 + j] = acc[i][j];
}

// ---------------- inter-chunk scan (16 steps, parallel over (b,h) and (p,n))
__global__ void scan_k() {
    int blk = blockIdx.x;                // b*32 + h
    int h = blk & 31, b = blk >> 5;
    int t = threadIdx.x;
    float carry[32];
    #pragma unroll
    for (int k = 0; k < 32; k++) carry[k] = 0.f;
    for (int c = 0; c < NCHUNK; c++) {
        int idx = (b * NCHUNK + c) * NHEADS + h;
        float decay = __expf(g_cum[idx * CHUNK + 255]);
        size_t base = (size_t)idx * DHEAD * DSTATE;
        #pragma unroll
        for (int k = 0; k < 32; k++) {
            size_t e = base + t + k * 256;
            g_pv[e] = carry[k];
            carry[k] = carry[k] * decay + g_st[e];
        }
    }
}

// ---------------- Y kernel: Y = masked(C B^T L) @ xdt + exp(cum)*C@prev^T + D*x
#define BTS 260
#define CTS 68
#define PTS 132
__global__ __launch_bounds__(256, 1)
void y_k(const float* __restrict__ Dvec) {
    extern __shared__ float sm[];
    float* Bt   = sm;                  // [64][BTS]  B^T (n-major)
    float* Gtt  = Bt + 64 * BTS;       // [256][64]  G^T (z-major, masked*L)
    float* Ct   = Gtt + 256 * 64;      // [64][CTS]  C^T tile (n-major)
    float* sX   = Ct + 64 * CTS;       // [64][128]  xdt z-tile
    float* pT   = sX + 64 * 128;       // [64][PTS]  prev^T (n-major)
    float* cums = pT + 64 * PTS;       // [256]
    float* sdt  = cums + 256;          // [256]
    int blk = blockIdx.x;
    int h = blk & 31, c = (blk >> 5) & 15, b = blk >> 9;
    int t = threadIdx.x;
    size_t base = (size_t)(b * SEQ + c * CHUNK) * CONVDIM;

    cums[t] = g_cum[blk * CHUNK + t];
    sdt[t]  = g_dtv[(size_t)(b * SEQ + c * CHUNK + t) * NHEADS + h];
    #pragma unroll
    for (int i = 0; i < 64; i++) {
        int lin = t + i * 256; int n = lin & 63; int z = lin >> 6;
        Bt[n * BTS + z] = g_xc[base + (size_t)z * CONVDIM + DINNER + n];
    }
    size_t pvb = (size_t)blk * DHEAD * DSTATE;
    #pragma unroll
    for (int i = 0; i < 32; i++) {
        int lin = t + i * 256; int n = lin & 63; int p = lin >> 6;
        pT[n * PTS + p] = g_pv[pvb + (size_t)p * DSTATE + n];
    }
    __syncthreads();
    float Dh = Dvec[h];
    const int sg = t & 15, zg = t >> 4;    // phase-1 mapping
    const int pg = t & 15, sg2 = t >> 4;   // phase-2/3 mapping

    for (int st = 0; st < 4; st++) {
        int s0 = st * 64;
        #pragma unroll
        for (int i = 0; i < 16; i++) {
            int lin = t + i * 256; int n = lin & 63; int si = lin >> 6;
            Ct[n * CTS + si] = g_xc[base + (size_t)(s0 + si) * CONVDIM + DINNER + DSTATE + n];
        }
        __syncthreads();
        // -------- phase 1: G^T tile = (C_tile · B^T), masked * L --------
        {
            int sl0 = sg * 4, z0 = zg * 16;
            float acc1[4][16];
            #pragma unroll
            for (int i = 0; i < 4; i++)
                #pragma unroll
                for (int j = 0; j < 16; j++) acc1[i][j] = 0.f;
            if (z0 <= s0 + 63) {
                for (int n = 0; n < 64; n++) {
                    float cv[4];
                    *(float4*)cv = *(const float4*)&Ct[n * CTS + sl0];
                    float bz[16];
                    #pragma unroll
                    for (int j = 0; j < 16; j += 4)
                        *(float4*)&bz[j] = *(const float4*)&Bt[n * BTS + z0 + j];
                    #pragma unroll
                    for (int i = 0; i < 4; i++)
                        #pragma unroll
                        for (int j = 0; j < 16; j++)
                            acc1[i][j] += cv[i] * bz[j];
                }
            }
            #pragma unroll
            for (int i = 0; i < 4; i++) {
                int sgl = s0 + sl0 + i;
                float cs = cums[sgl];
                #pragma unroll
                for (int j = 0; j < 16; j++) {
                    int z = z0 + j;
                    float v = (z <= sgl) ? acc1[i][j] * __expf(cs - cums[z]) : 0.f;
                    Gtt[z * 64 + sl0 + i] = v;
                }
            }
        }
        __syncthreads();
        // -------- phase 2: Y_tile += G^T-masked @ xdt (skip fully-masked z-tiles)
        int p0 = pg * 8, sl0 = sg2 * 4;
        float acc2[4][8];
        #pragma unroll
        for (int i = 0; i < 4; i++)
            #pragma unroll
            for (int j = 0; j < 8; j++) acc2[i][j] = 0.f;
        for (int zt = 0; zt <= st; zt++) {
            #pragma unroll
            for (int i = 0; i < 32; i++) {
                int lin = t + i * 256; int zz = lin >> 7; int p = lin & 127; int z = zt * 64 + zz;
                sX[zz * 128 + p] = g_xc[base + (size_t)z * CONVDIM + h * DHEAD + p] * sdt[z];
            }
            __syncthreads();
            #pragma unroll
            for (int zz = 0; zz < 64; zz++) {
                float gv[4];
                *(float4*)gv = *(const float4*)&Gtt[(zt * 64 + zz) * 64 + sl0];
                float xv[8];
                *(float4*)&xv[0] = *(const float4*)&sX[zz * 128 + p0];
                *(float4*)&xv[4] = *(const float4*)&sX[zz * 128 + p0 + 4];
                #pragma unroll
                for (int i = 0; i < 4; i++)
                    #pragma unroll
                    for (int j = 0; j < 8; j++)
                        acc2[i][j] += gv[i] * xv[j];
            }
            __syncthreads();
        }
        // -------- phase 3: Y_off = exp(cum[s]) * C · prev^T --------
        {
            float es[4];
            #pragma unroll
            for (int i = 0; i < 4; i++) es[i] = __expf(cums[s0 + sl0 + i]);
            for (int n = 0; n < 64; n++) {
                float cv[4];
                *(float4*)cv = *(const float4*)&Ct[n * CTS + sl0];
                float pv[8];
                *(float4*)&pv[0] = *(const float4*)&pT[n * PTS + p0];
                *(float4*)&pv[4] = *(const float4*)&pT[n * PTS + p0 + 4];
                #pragma unroll
                for (int i = 0; i < 4; i++) {
                    float cvs = cv[i] * es[i];
                    #pragma unroll
                    for (int j = 0; j < 8; j++)
                        acc2[i][j] += cvs * pv[j];
                }
            }
        }
        // -------- store: + D*x --------
        #pragma unroll
        for (int i = 0; i < 4; i++) {
            int s = s0 + sl0 + i;
            size_t row = (size_t)(b * SEQ + c * CHUNK + s);
            #pragma unroll
            for (int j = 0; j < 8; j++) {
                int p = p0 + j;
                g_y[row * DINNER + h * DHEAD + p] =
                    acc2[i][j] + Dh * g_xc[row * CONVDIM + h * DHEAD + p];
            }
        }
        __syncthreads();
    }
}

// ---------------- gated RMSNorm fused with bf16 hi/lo split for GEMM2 ------
__global__ void gatenorm_k(const float* __restrict__ nw) {
    int row = blockIdx.x;
    __shared__ float yg[DINNER];
    __shared__ float red[256];
    int t = threadIdx.x;
    float ss = 0.f;
    size_t zb = (size_t)row * EPROJ;
    size_t yb = (size_t)row * DINNER;
    #pragma unroll
    for (int i = 0; i < 16; i++) {
        int e = t + i * 256;
        float z = g_zx[zb + e];
        float sz = z / (1.f + __expf(-z));
        float v = g_y[yb + e] * sz;
        yg[e] = v;
        ss += v * v;
    }
    red[t] = ss;
    __syncthreads();
    for (int off = 128; off > 0; off >>= 1) {
        if (t < off) red[t] += red[t + off];
        __syncthreads();
    }
    float scale = rsqrtf(red[0] / (float)DINNER + 1e-5f);
    #pragma unroll
    for (int i = 0; i < 16; i++) {
        int e = t + i * 256;
        float v = yg[e] * scale * nw[e];
        __nv_bfloat16 h = __float2bfloat16_rn(v);
        g_Ah[yb + e] = h;
        g_Al[yb + e] = __float2bfloat16_rn(v - __bfloat162float(h));
    }
}

// ---------------- launch ----------------
extern "C" void kernel_launch(void* const* d_in, const int* in_sizes, int n_in,
                              void* d_out, int out_size) {
    const float* u     = (const float*)d_in[0];
    const float* W_in  = (const float*)d_in[1];
    const float* convw = (const float*)d_in[2];
    const float* convb = (const float*)d_in[3];
    const float* dtb   = (const float*)d_in[4];
    const float* Alog  = (const float*)d_in[5];
    const float* Dvec  = (const float*)d_in[6];
    const float* nw    = (const float*)d_in[7];
    const float* W_out = (const float*)d_in[8];
    float* out = (float*)d_out;

    float* zx_p;
    __nv_bfloat16 *ah_p, *al_p, *bh_p, *bl_p;
    cudaGetSymbolAddress((void**)&zx_p, g_zx);
    cudaGetSymbolAddress((void**)&ah_p, g_Ah);
    cudaGetSymbolAddress((void**)&al_p, g_Al);
    cudaGetSymbolAddress((void**)&bh_p, g_Bh);
    cudaGetSymbolAddress((void**)&bl_p, g_Bl);

    const int STATES_SMEM = (64 * 128 + 64 * 64 + 256) * 4;
    const int Y_SMEM = (64 * BTS + 256 * 64 + 64 * CTS + 64 * 128 + 64 * PTS + 512) * 4;
    cudaFuncSetAttribute(states_k, cudaFuncAttributeMaxDynamicSharedMemorySize, STATES_SMEM);
    cudaFuncSetAttribute(y_k,      cudaFuncAttributeMaxDynamicSharedMemorySize, Y_SMEM);
    cudaFuncSetAttribute(gemm_bf,  cudaFuncAttributeMaxDynamicSharedMemorySize, GSMEM);

    // ---- GEMM1: zx[8192,8352] = u[8192,2048] @ W_in[8352,2048]^T ----
    {
        int n4a = MROWS * DMODEL / 4;       // u
        int n4b = EPROJ * DMODEL / 4;       // W_in
        split_k<<<(n4a + 255) / 256, 256>>>((const float4*)u, (uint2*)ah_p, (uint2*)al_p, n4a);
        split_k<<<(n4b + 255) / 256, 256>>>((const float4*)W_in, (uint2*)bh_p, (uint2*)bl_p, n4b);
        gemm_bf<<<dim3(66, 64), 256, GSMEM>>>(ah_p, al_p, bh_p, bl_p, zx_p,
                                              MROWS, EPROJ, DMODEL);
    }
    // ---- SSD middle section ----
    conv_silu_k<<<(int)(((size_t)MROWS * (CONVDIM / 4)) / 256), 256>>>(convw, convb);
    dtcum_k<<<1024, 256>>>(dtb, Alog);
    states_k<<<1024, 256, STATES_SMEM>>>();
    scan_k<<<64, 256>>>();
    y_k<<<1024, 256, Y_SMEM>>>(Dvec);
    gatenorm_k<<<MROWS, 256>>>(nw);     // writes bf16 hi/lo of yn into g_Ah/g_Al
    // ---- GEMM2: out[8192,2048] = yn[8192,4096] @ W_out[2048,4096]^T ----
    {
        int n4b = DMODEL * DINNER / 4;      // W_out
        split_k<<<(n4b + 255) / 256, 256>>>((const float4*)W_out, (uint2*)bh_p, (uint2*)bl_p, n4b);
        gemm_bf<<<dim3(16, 64), 256, GSMEM>>>(ah_p, al_p, bh_p, bl_p, out,
                                              MROWS, DMODEL, DINNER);
    }
}

// round 11
// speedup vs baseline: 1.7638x; 1.2508x over previous
#include <cuda_runtime.h>
#include <cuda_fp16.h>
#include <cuda_bf16.h>
#include <cstdint>
#include <cstddef>

#define BATCH   2
#define SEQ     4096
#define DMODEL  2048
#define DINNER  4096
#define NHEADS  32
#define DHEAD   128
#define DSTATE  64
#define CONVDIM 4224          // DINNER + 2*DSTATE
#define EPROJ   8352          // 2*DINNER + 2*DSTATE + NHEADS
#define NCHUNK  16
#define CHUNK   256
#define MROWS   8192          // BATCH*SEQ

// ---------------- device scratch (static: allocation-free) ----------------
__device__ float g_zx[(size_t)MROWS * EPROJ];     // in_proj output
__device__ float g_xc[(size_t)MROWS * CONVDIM];   // conv+silu output
__device__ float g_dtv[(size_t)MROWS * NHEADS];   // softplus dt
__device__ float g_cum[BATCH * NCHUNK * NHEADS * CHUNK]; // per-chunk cumsum(dA)
__device__ float g_st[(size_t)BATCH * NCHUNK * NHEADS * DHEAD * DSTATE]; // chunk states
__device__ float g_pv[(size_t)BATCH * NCHUNK * NHEADS * DHEAD * DSTATE]; // prev states
__device__ float g_y [(size_t)MROWS * DINNER];    // y (pre-norm)
// fp16 operands: A hi/lo split, B single-rounded
__device__ __half g_Ah[(size_t)MROWS * DINNER];
__device__ __half g_Al[(size_t)MROWS * DINNER];
__device__ __half g_Bh[(size_t)EPROJ * DMODEL];

// ============================================================================
// helpers
// ============================================================================
__device__ __forceinline__ uint32_t smem_u32(const void* p) {
    uint32_t a;
    asm("{ .reg .u64 t; cvta.to.shared.u64 t, %1; cvt.u32.u64 %0, t; }" : "=r"(a) : "l"(p));
    return a;
}
__device__ __forceinline__ void ldm4(uint32_t* r, uint32_t a) {
    asm volatile("ldmatrix.sync.aligned.m8n8.x4.shared.b16 {%0,%1,%2,%3}, [%4];"
                 : "=r"(r[0]), "=r"(r[1]), "=r"(r[2]), "=r"(r[3]) : "r"(a));
}
__device__ __forceinline__ void mma16816(float* d, const uint32_t* a, uint32_t b0, uint32_t b1) {
    asm volatile("mma.sync.aligned.m16n8k16.row.col.f32.f16.f16.f32 "
                 "{%0,%1,%2,%3}, {%4,%5,%6,%7}, {%8,%9}, {%0,%1,%2,%3};"
                 : "+f"(d[0]), "+f"(d[1]), "+f"(d[2]), "+f"(d[3])
                 : "r"(a[0]), "r"(a[1]), "r"(a[2]), "r"(a[3]), "r"(b0), "r"(b1));
}
__device__ __forceinline__ uint32_t pk2h(__half a, __half b) {
    return (uint32_t)__half_as_ushort(a) | ((uint32_t)__half_as_ushort(b) << 16);
}
// fp32 -> fp16 hi + fp16 lo (A-side split)
__device__ __forceinline__ void dec4h(float4 v, uint2& h, uint2& l) {
    __half h0 = __float2half_rn(v.x), h1 = __float2half_rn(v.y);
    __half h2 = __float2half_rn(v.z), h3 = __float2half_rn(v.w);
    __half l0 = __float2half_rn(v.x - __half2float(h0));
    __half l1 = __float2half_rn(v.y - __half2float(h1));
    __half l2 = __float2half_rn(v.z - __half2float(h2));
    __half l3 = __float2half_rn(v.w - __half2float(h3));
    h = make_uint2(pk2h(h0, h1), pk2h(h2, h3));
    l = make_uint2(pk2h(l0, l1), pk2h(l2, l3));
}
__device__ __forceinline__ void cpasync16(uint32_t dst, const void* src, int srcsz) {
    asm volatile("cp.async.cg.shared.global [%0], [%1], 16, %2;"
                 :: "r"(dst), "l"(src), "r"(srcsz) : "memory");
}
#define CP_COMMIT() asm volatile("cp.async.commit_group;" ::: "memory")
#define CP_WAIT2()  asm volatile("cp.async.wait_group 2;" ::: "memory")

// ---------------- fp32 -> fp16 hi/lo split (A operands) ----------
__global__ void split_k(const float4* __restrict__ in,
                        uint2* __restrict__ hi, uint2* __restrict__ lo, int n4) {
    int i = blockIdx.x * 256 + threadIdx.x;
    if (i < n4) {
        uint2 h, l;
        dec4h(in[i], h, l);
        hi[i] = h;
        lo[i] = l;
    }
}
// ---------------- fp32 -> fp16 round (B operands, single) ----------
__global__ void cvt_k(const float4* __restrict__ in, uint2* __restrict__ out, int n4) {
    int i = blockIdx.x * 256 + threadIdx.x;
    if (i < n4) {
        float4 v = in[i];
        out[i] = make_uint2(pk2h(__float2half_rn(v.x), __float2half_rn(v.y)),
                            pk2h(__float2half_rn(v.z), __float2half_rn(v.w)));
    }
}

// ============================================================================
// HMMA fp16x2 NT GEMM: C[M,N] = (Ah+Al)[M,K] * Bh[N,K]^T  (fp32 accum).
// A split fp16 hi/lo (22-bit effective mantissa); B rounded to fp16 once
// (dominant error ~2^-11 RMS). 2 MMA products per k-step instead of 3.
// Tile 128x128, BK=32, 4-stage cp.async pipeline, one barrier per chunk.
// ============================================================================
#define BK      32
#define TROW    80                       // padded row bytes: 16-aligned, 5 mod 8 -> ldmatrix conflict-free
#define TILE_B  (128 * TROW)             // 10240 B per fp16 tile
#define STAGE_B (3 * TILE_B)             // Ah | Al | Bh = 30720 B
#define NSTAGE  4
#define GSMEM   (NSTAGE * STAGE_B)       // 122880 B

__device__ __forceinline__ void ld_stage(uint32_t sb, int stage,
        const __half* __restrict__ Ah, const __half* __restrict__ Al,
        const __half* __restrict__ Bh,
        int m0, int n0, int K, int N, int k0, int t) {
    uint32_t stb = sb + (uint32_t)stage * STAGE_B;
    #pragma unroll
    for (int j = 0; j < 6; j++) {
        int lin = t + j * 256;                 // 0..1535
        int tile = lin >> 9, li = lin & 511;
        int row = li >> 2, c = li & 3;
        uint32_t dst = stb + (uint32_t)tile * TILE_B + (uint32_t)row * TROW + c * 16;
        const __half* src;
        int sz = 16;
        if (tile == 0)      src = Ah + (size_t)(m0 + row) * K + k0 + c * 8;
        else if (tile == 1) src = Al + (size_t)(m0 + row) * K + k0 + c * 8;
        else {
            int r = n0 + row;
            if (r >= N) { r = 0; sz = 0; }
            src = Bh + (size_t)r * K + k0 + c * 8;
        }
        cpasync16(dst, src, sz);
    }
}

__global__ __launch_bounds__(256, 1)
void gemm_hf(const __half* __restrict__ Ah, const __half* __restrict__ Al,
             const __half* __restrict__ Bh,
             float* __restrict__ C, int M, int N, int K) {
    extern __shared__ char smem[];
    const uint32_t sb = smem_u32(smem);
    const int t = threadIdx.x, wid = t >> 5, lane = t & 31;
    const int m0 = blockIdx.y * 128, n0b = blockIdx.x * 128;
    const int wm = (wid & 1) * 64, wn = (wid >> 1) * 32;

    float acc[4][4][4];
    #pragma unroll
    for (int i = 0; i < 4; i++)
        #pragma unroll
        for (int j = 0; j < 4; j++)
            #pragma unroll
            for (int k = 0; k < 4; k++) acc[i][j][k] = 0.f;

    const int NC = K / BK;
    #pragma unroll
    for (int s = 0; s < NSTAGE - 1; s++) {
        if (s < NC)
            ld_stage(sb, s, Ah, Al, Bh, m0, n0b, K, N, s * BK, t);
        CP_COMMIT();
    }

    const int lr = lane & 15, lh = lane >> 4;

    for (int c = 0; c < NC; c++) {
        CP_WAIT2();
        __syncthreads();
        // issue next stage now so cp.async overlaps this chunk's MMAs
        int nx = c + NSTAGE - 1;
        if (nx < NC)
            ld_stage(sb, nx & (NSTAGE - 1), Ah, Al, Bh, m0, n0b, K, N, nx * BK, t);
        CP_COMMIT();

        uint32_t stb = sb + (uint32_t)(c & (NSTAGE - 1)) * STAGE_B;
        #pragma unroll
        for (int kk = 0; kk < 2; kk++) {
            uint32_t kb = kk * 32 + lh * 16;
            uint32_t ah[4][4], al[4][4], bh[2][4];
            #pragma unroll
            for (int mf = 0; mf < 4; mf++) {
                uint32_t ro = (uint32_t)(wm + mf * 16 + lr) * TROW + kb;
                ldm4(ah[mf], stb + ro);
                ldm4(al[mf], stb + TILE_B + ro);
            }
            #pragma unroll
            for (int np = 0; np < 2; np++) {
                uint32_t ro = (uint32_t)(wn + np * 16 + lr) * TROW + kb;
                ldm4(bh[np], stb + 2 * TILE_B + ro);
            }
            // product-major: consecutive mmas hit distinct accumulators
            #pragma unroll
            for (int mf = 0; mf < 4; mf++)
                #pragma unroll
                for (int np = 0; np < 2; np++) {
                    mma16816(acc[mf][2 * np],     ah[mf], bh[np][0], bh[np][2]);
                    mma16816(acc[mf][2 * np + 1], ah[mf], bh[np][1], bh[np][3]);
                }
            #pragma unroll
            for (int mf = 0; mf < 4; mf++)
                #pragma unroll
                for (int np = 0; np < 2; np++) {
                    mma16816(acc[mf][2 * np],     al[mf], bh[np][0], bh[np][2]);
                    mma16816(acc[mf][2 * np + 1], al[mf], bh[np][1], bh[np][3]);
                }
        }
    }

    // epilogue: mma C layout — row = lane>>2 (+8), col = (lane&3)*2 (+1)
    const int gr = lane >> 2, gc = (lane & 3) * 2;
    #pragma unroll
    for (int mf = 0; mf < 4; mf++) {
        int m = m0 + wm + mf * 16 + gr;
        #pragma unroll
        for (int nf = 0; nf < 4; nf++) {
            int n = n0b + wn + nf * 8 + gc;
            if (n < N) {
                *(float2*)&C[(size_t)m * N + n] =
                    make_float2(acc[mf][nf][0], acc[mf][nf][1]);
                *(float2*)&C[(size_t)(m + 8) * N + n] =
                    make_float2(acc[mf][nf][2], acc[mf][nf][3]);
            }
        }
    }
}

// ---------------- conv1d (depthwise, causal, D_CONV=4) + SiLU, float4 -------
__global__ void conv_silu_k(const float* __restrict__ cw, const float* __restrict__ cb) {
    const int C4 = CONVDIM / 4;                    // 1056
    int idx = blockIdx.x * 256 + threadIdx.x;      // one float4 (4 channels)
    int c4 = idx % C4;
    int bl = idx / C4;                             // 0..MROWS-1
    int l = bl & (SEQ - 1), b = bl / SEQ;
    int c = c4 * 4;
    float4 acc = *(const float4*)&cb[c];
    float w[4][4];
    #pragma unroll
    for (int j = 0; j < 4; j++)
        *(float4*)w[j] = *(const float4*)&cw[(c + j) * 4];
    #pragma unroll
    for (int k = 0; k < 4; k++) {
        int ls = l - 3 + k;
        if (ls >= 0) {
            float4 v = *(const float4*)&g_zx[(size_t)(b * SEQ + ls) * EPROJ + DINNER + c];
            acc.x += v.x * w[0][k];
            acc.y += v.y * w[1][k];
            acc.z += v.z * w[2][k];
            acc.w += v.w * w[3][k];
        }
    }
    acc.x = acc.x / (1.f + __expf(-acc.x));
    acc.y = acc.y / (1.f + __expf(-acc.y));
    acc.z = acc.z / (1.f + __expf(-acc.z));
    acc.w = acc.w / (1.f + __expf(-acc.w));
    *(float4*)&g_xc[(size_t)bl * CONVDIM + c] = acc;
}

// ---------------- dt softplus + per-chunk cumsum(dA) ----------------
__global__ void dtcum_k(const float* __restrict__ dtb, const float* __restrict__ Alog) {
    int blk = blockIdx.x;                // ((b*16+c)*32+h)
    int h = blk & 31, c = (blk >> 5) & 15, b = blk >> 9;
    int s = threadIdx.x;
    int l = c * CHUNK + s;
    float raw = g_zx[((size_t)(b * SEQ + l)) * EPROJ + (EPROJ - NHEADS) + h] + dtb[h];
    float dtv = (raw > 20.f) ? raw : log1pf(__expf(raw));
    g_dtv[(size_t)(b * SEQ + l) * NHEADS + h] = dtv;
    float dA = dtv * (-__expf(Alog[h]));
    __shared__ float sc[256];
    sc[s] = dA;
    __syncthreads();
    for (int off = 1; off < 256; off <<= 1) {
        float v = (s >= off) ? sc[s - off] : 0.f;
        __syncthreads();
        sc[s] += v;
        __syncthreads();
    }
    g_cum[blk * CHUNK + s] = sc[s];
}

// ---------------- per-chunk states: st[p,n] = sum_z exp(cumL-cum[z])*dt[z]*x[z,p]*B[z,n]
__global__ __launch_bounds__(256)
void states_k() {
    extern __shared__ float sm[];
    float* xw  = sm;                 // 64*128
    float* Bsh = xw + 64 * 128;      // 64*64
    float* ws  = Bsh + 64 * 64;      // 256
    int blk = blockIdx.x;
    int h = blk & 31, c = (blk >> 5) & 15, b = blk >> 9;
    int t = threadIdx.x;
    float clast = g_cum[blk * CHUNK + 255];
    {
        float cz = g_cum[blk * CHUNK + t];
        float dtv = g_dtv[(size_t)(b * SEQ + c * CHUNK + t) * NHEADS + h];
        ws[t] = __expf(clast - cz) * dtv;
    }
    __syncthreads();
    int tx = t & 15, ty = t >> 4;
    int p0 = tx * 8, n0 = ty * 4;
    float acc[8][4];
    #pragma unroll
    for (int i = 0; i < 8; i++)
        #pragma unroll
        for (int j = 0; j < 4; j++) acc[i][j] = 0.f;
    size_t base = (size_t)(b * SEQ + c * CHUNK) * CONVDIM;
    for (int zt = 0; zt < 4; zt++) {
        #pragma unroll
        for (int i = 0; i < 32; i++) {
            int lin = t + i * 256; int zz = lin >> 7; int p = lin & 127; int z = zt * 64 + zz;
            xw[zz * 128 + p] = g_xc[base + (size_t)z * CONVDIM + h * DHEAD + p] * ws[z];
        }
        #pragma unroll
        for (int i = 0; i < 16; i++) {
            int lin = t + i * 256; int zz = lin >> 6; int n = lin & 63; int z = zt * 64 + zz;
            Bsh[zz * 64 + n] = g_xc[base + (size_t)z * CONVDIM + DINNER + n];
        }
        __syncthreads();
        #pragma unroll
        for (int zz = 0; zz < 64; zz++) {
            float xv[8];
            *(float4*)&xv[0] = *(const float4*)&xw[zz * 128 + p0];
            *(float4*)&xv[4] = *(const float4*)&xw[zz * 128 + p0 + 4];
            float4 bv = *(const float4*)&Bsh[zz * 64 + n0];
            float bb[4] = {bv.x, bv.y, bv.z, bv.w};
            #pragma unroll
            for (int i = 0; i < 8; i++)
                #pragma unroll
                for (int j = 0; j < 4; j++)
                    acc[i][j] += xv[i] * bb[j];
        }
        __syncthreads();
    }
    size_t ob = (size_t)blk * DHEAD * DSTATE;
    #pragma unroll
    for (int i = 0; i < 8; i++)
        #pragma unroll
        for (int j = 0; j < 4; j++)
            g_st[ob + (size_t)(p0 + i) * DSTATE + n0 + j] = acc[i][j];
}

// ---------------- inter-chunk scan (16 steps, parallel over (b,h) and (p,n))
__global__ void scan_k() {
    int blk = blockIdx.x;                // b*32 + h
    int h = blk & 31, b = blk >> 5;
    int t = threadIdx.x;
    float carry[32];
    #pragma unroll
    for (int k = 0; k < 32; k++) carry[k] = 0.f;
    for (int c = 0; c < NCHUNK; c++) {
        int idx = (b * NCHUNK + c) * NHEADS + h;
        float decay = __expf(g_cum[idx * CHUNK + 255]);
        size_t base = (size_t)idx * DHEAD * DSTATE;
        #pragma unroll
        for (int k = 0; k < 32; k++) {
            size_t e = base + t + k * 256;
            g_pv[e] = carry[k];
            carry[k] = carry[k] * decay + g_st[e];
        }
    }
}

// ---------------- Y kernel: Y = masked(C B^T L) @ xdt + exp(cum)*C@prev^T + D*x
#define BTS 260
#define CTS 68
#define PTS 132
__global__ __launch_bounds__(256, 1)
void y_k(const float* __restrict__ Dvec) {
    extern __shared__ float sm[];
    float* Bt   = sm;                  // [64][BTS]  B^T (n-major)
    float* Gtt  = Bt + 64 * BTS;       // [256][64]  G^T (z-major, masked*L)
    float* Ct   = Gtt + 256 * 64;      // [64][CTS]  C^T tile (n-major)
    float* sX   = Ct + 64 * CTS;       // [64][128]  xdt z-tile
    float* pT   = sX + 64 * 128;       // [64][PTS]  prev^T (n-major)
    float* cums = pT + 64 * PTS;       // [256]
    float* sdt  = cums + 256;          // [256]
    int blk = blockIdx.x;
    int h = blk & 31, c = (blk >> 5) & 15, b = blk >> 9;
    int t = threadIdx.x;
    size_t base = (size_t)(b * SEQ + c * CHUNK) * CONVDIM;

    cums[t] = g_cum[blk * CHUNK + t];
    sdt[t]  = g_dtv[(size_t)(b * SEQ + c * CHUNK + t) * NHEADS + h];
    #pragma unroll
    for (int i = 0; i < 64; i++) {
        int lin = t + i * 256; int n = lin & 63; int z = lin >> 6;
        Bt[n * BTS + z] = g_xc[base + (size_t)z * CONVDIM + DINNER + n];
    }
    size_t pvb = (size_t)blk * DHEAD * DSTATE;
    #pragma unroll
    for (int i = 0; i < 32; i++) {
        int lin = t + i * 256; int n = lin & 63; int p = lin >> 6;
        pT[n * PTS + p] = g_pv[pvb + (size_t)p * DSTATE + n];
    }
    __syncthreads();
    float Dh = Dvec[h];
    const int sg = t & 15, zg = t >> 4;    // phase-1 mapping
    const int pg = t & 15, sg2 = t >> 4;   // phase-2/3 mapping

    for (int st = 0; st < 4; st++) {
        int s0 = st * 64;
        #pragma unroll
        for (int i = 0; i < 16; i++) {
            int lin = t + i * 256; int n = lin & 63; int si = lin >> 6;
            Ct[n * CTS + si] = g_xc[base + (size_t)(s0 + si) * CONVDIM + DINNER + DSTATE + n];
        }
        __syncthreads();
        // -------- phase 1: G^T tile = (C_tile · B^T), masked * L --------
        {
            int sl0 = sg * 4, z0 = zg * 16;
            float acc1[4][16];
            #pragma unroll
            for (int i = 0; i < 4; i++)
                #pragma unroll
                for (int j = 0; j < 16; j++) acc1[i][j] = 0.f;
            if (z0 <= s0 + 63) {
                for (int n = 0; n < 64; n++) {
                    float cv[4];
                    *(float4*)cv = *(const float4*)&Ct[n * CTS + sl0];
                    float bz[16];
                    #pragma unroll
                    for (int j = 0; j < 16; j += 4)
                        *(float4*)&bz[j] = *(const float4*)&Bt[n * BTS + z0 + j];
                    #pragma unroll
                    for (int i = 0; i < 4; i++)
                        #pragma unroll
                        for (int j = 0; j < 16; j++)
                            acc1[i][j] += cv[i] * bz[j];
                }
            }
            #pragma unroll
            for (int i = 0; i < 4; i++) {
                int sgl = s0 + sl0 + i;
                float cs = cums[sgl];
                #pragma unroll
                for (int j = 0; j < 16; j++) {
                    int z = z0 + j;
                    float v = (z <= sgl) ? acc1[i][j] * __expf(cs - cums[z]) : 0.f;
                    Gtt[z * 64 + sl0 + i] = v;
                }
            }
        }
        __syncthreads();
        // -------- phase 2: Y_tile += G^T-masked @ xdt (skip fully-masked z-tiles)
        int p0 = pg * 8, sl0 = sg2 * 4;
        float acc2[4][8];
        #pragma unroll
        for (int i = 0; i < 4; i++)
            #pragma unroll
            for (int j = 0; j < 8; j++) acc2[i][j] = 0.f;
        for (int zt = 0; zt <= st; zt++) {
            #pragma unroll
            for (int i = 0; i < 32; i++) {
                int lin = t + i * 256; int zz = lin >> 7; int p = lin & 127; int z = zt * 64 + zz;
                sX[zz * 128 + p] = g_xc[base + (size_t)z * CONVDIM + h * DHEAD + p] * sdt[z];
            }
            __syncthreads();
            #pragma unroll
            for (int zz = 0; zz < 64; zz++) {
                float gv[4];
                *(float4*)gv = *(const float4*)&Gtt[(zt * 64 + zz) * 64 + sl0];
                float xv[8];
                *(float4*)&xv[0] = *(const float4*)&sX[zz * 128 + p0];
                *(float4*)&xv[4] = *(const float4*)&sX[zz * 128 + p0 + 4];
                #pragma unroll
                for (int i = 0; i < 4; i++)
                    #pragma unroll
                    for (int j = 0; j < 8; j++)
                        acc2[i][j] += gv[i] * xv[j];
            }
            __syncthreads();
        }
        // -------- phase 3: Y_off = exp(cum[s]) * C · prev^T --------
        {
            float es[4];
            #pragma unroll
            for (int i = 0; i < 4; i++) es[i] = __expf(cums[s0 + sl0 + i]);
            for (int n = 0; n < 64; n++) {
                float cv[4];
                *(float4*)cv = *(const float4*)&Ct[n * CTS + sl0];
                float pv[8];
                *(float4*)&pv[0] = *(const float4*)&pT[n * PTS + p0];
                *(float4*)&pv[4] = *(const float4*)&pT[n * PTS + p0 + 4];
                #pragma unroll
                for (int i = 0; i < 4; i++) {
                    float cvs = cv[i] * es[i];
                    #pragma unroll
                    for (int j = 0; j < 8; j++)
                        acc2[i][j] += cvs * pv[j];
                }
            }
        }
        // -------- store: + D*x --------
        #pragma unroll
        for (int i = 0; i < 4; i++) {
            int s = s0 + sl0 + i;
            size_t row = (size_t)(b * SEQ + c * CHUNK + s);
            #pragma unroll
            for (int j = 0; j < 8; j++) {
                int p = p0 + j;
                g_y[row * DINNER + h * DHEAD + p] =
                    acc2[i][j] + Dh * g_xc[row * CONVDIM + h * DHEAD + p];
            }
        }
        __syncthreads();
    }
}

// ---------------- gated RMSNorm fused with fp16 hi/lo split for GEMM2 ------
__global__ void gatenorm_k(const float* __restrict__ nw) {
    int row = blockIdx.x;
    __shared__ float yg[DINNER];
    __shared__ float red[256];
    int t = threadIdx.x;
    float ss = 0.f;
    size_t zb = (size_t)row * EPROJ;
    size_t yb = (size_t)row * DINNER;
    #pragma unroll
    for (int i = 0; i < 16; i++) {
        int e = t + i * 256;
        float z = g_zx[zb + e];
        float sz = z / (1.f + __expf(-z));
        float v = g_y[yb + e] * sz;
        yg[e] = v;
        ss += v * v;
    }
    red[t] = ss;
    __syncthreads();
    for (int off = 128; off > 0; off >>= 1) {
        if (t < off) red[t] += red[t + off];
        __syncthreads();
    }
    float scale = rsqrtf(red[0] / (float)DINNER + 1e-5f);
    #pragma unroll
    for (int i = 0; i < 16; i++) {
        int e = t + i * 256;
        float v = yg[e] * scale * nw[e];
        __half h = __float2half_rn(v);
        g_Ah[yb + e] = h;
        g_Al[yb + e] = __float2half_rn(v - __half2float(h));
    }
}

// ---------------- launch ----------------
extern "C" void kernel_launch(void* const* d_in, const int* in_sizes, int n_in,
                              void* d_out, int out_size) {
    const float* u     = (const float*)d_in[0];
    const float* W_in  = (const float*)d_in[1];
    const float* convw = (const float*)d_in[2];
    const float* convb = (const float*)d_in[3];
    const float* dtb   = (const float*)d_in[4];
    const float* Alog  = (const float*)d_in[5];
    const float* Dvec  = (const float*)d_in[6];
    const float* nw    = (const float*)d_in[7];
    const float* W_out = (const float*)d_in[8];
    float* out = (float*)d_out;

    float* zx_p;
    __half *ah_p, *al_p, *bh_p;
    cudaGetSymbolAddress((void**)&zx_p, g_zx);
    cudaGetSymbolAddress((void**)&ah_p, g_Ah);
    cudaGetSymbolAddress((void**)&al_p, g_Al);
    cudaGetSymbolAddress((void**)&bh_p, g_Bh);

    const int STATES_SMEM = (64 * 128 + 64 * 64 + 256) * 4;
    const int Y_SMEM = (64 * BTS + 256 * 64 + 64 * CTS + 64 * 128 + 64 * PTS + 512) * 4;
    cudaFuncSetAttribute(states_k, cudaFuncAttributeMaxDynamicSharedMemorySize, STATES_SMEM);
    cudaFuncSetAttribute(y_k,      cudaFuncAttributeMaxDynamicSharedMemorySize, Y_SMEM);
    cudaFuncSetAttribute(gemm_hf,  cudaFuncAttributeMaxDynamicSharedMemorySize, GSMEM);

    // ---- GEMM1: zx[8192,8352] = u[8192,2048] @ W_in[8352,2048]^T ----
    {
        int n4a = MROWS * DMODEL / 4;       // u (split hi/lo)
        int n4b = EPROJ * DMODEL / 4;       // W_in (single fp16)
        split_k<<<(n4a + 255) / 256, 256>>>((const float4*)u, (uint2*)ah_p, (uint2*)al_p, n4a);
        cvt_k<<<(n4b + 255) / 256, 256>>>((const float4*)W_in, (uint2*)bh_p, n4b);
        gemm_hf<<<dim3(66, 64), 256, GSMEM>>>(ah_p, al_p, bh_p, zx_p,
                                              MROWS, EPROJ, DMODEL);
    }
    // ---- SSD middle section ----
    conv_silu_k<<<(int)(((size_t)MROWS * (CONVDIM / 4)) / 256), 256>>>(convw, convb);
    dtcum_k<<<1024, 256>>>(dtb, Alog);
    states_k<<<1024, 256, STATES_SMEM>>>();
    scan_k<<<64, 256>>>();
    y_k<<<1024, 256, Y_SMEM>>>(Dvec);
    gatenorm_k<<<MROWS, 256>>>(nw);     // writes fp16 hi/lo of yn into g_Ah/g_Al
    // ---- GEMM2: out[8192,2048] = yn[8192,4096] @ W_out[2048,4096]^T ----
    {
        int n4b = DMODEL * DINNER / 4;      // W_out (single fp16)
        cvt_k<<<(n4b + 255) / 256, 256>>>((const float4*)W_out, (uint2*)bh_p, n4b);
        gemm_hf<<<dim3(16, 64), 256, GSMEM>>>(ah_p, al_p, bh_p, out,
                                              MROWS, DMODEL, DINNER);
    }
}

// round 13
// speedup vs baseline: 2.7007x; 1.5312x over previous
#include <cuda_runtime.h>
#include <cuda_fp16.h>
#include <cstdint>
#include <cstddef>

#define BATCH   2
#define SEQ     4096
#define DMODEL  2048
#define DINNER  4096
#define NHEADS  32
#define DHEAD   128
#define DSTATE  64
#define CONVDIM 4224          // DINNER + 2*DSTATE
#define EPROJ   8352          // 2*DINNER + 2*DSTATE + NHEADS
#define NCHUNK  16
#define CHUNK   256
#define MROWS   8192          // BATCH*SEQ

// ---------------- device scratch (static: allocation-free) ----------------
__device__ float g_zx[(size_t)MROWS * EPROJ];     // in_proj output
__device__ float g_xc[(size_t)MROWS * CONVDIM];   // conv+silu output
__device__ float g_dtv[(size_t)MROWS * NHEADS];   // softplus dt
__device__ float g_cum[BATCH * NCHUNK * NHEADS * CHUNK]; // per-chunk cumsum(dA)
__device__ float g_st[(size_t)BATCH * NCHUNK * NHEADS * DHEAD * DSTATE]; // chunk states
__device__ float g_pv[(size_t)BATCH * NCHUNK * NHEADS * DHEAD * DSTATE]; // prev states
__device__ float g_y [(size_t)MROWS * DINNER];    // y (pre-norm)
// fp16 operands (single-rounded A and B)
__device__ __half g_Ah[(size_t)MROWS * DINNER];
__device__ __half g_Bh[(size_t)EPROJ * DMODEL];

// ============================================================================
// helpers
// ============================================================================
__device__ __forceinline__ uint32_t smem_u32(const void* p) {
    uint32_t a;
    asm("{ .reg .u64 t; cvta.to.shared.u64 t, %1; cvt.u32.u64 %0, t; }" : "=r"(a) : "l"(p));
    return a;
}
__device__ __forceinline__ void ldm4(uint32_t* r, uint32_t a) {
    asm volatile("ldmatrix.sync.aligned.m8n8.x4.shared.b16 {%0,%1,%2,%3}, [%4];"
                 : "=r"(r[0]), "=r"(r[1]), "=r"(r[2]), "=r"(r[3]) : "r"(a));
}
__device__ __forceinline__ void mma16816(float* d, const uint32_t* a, uint32_t b0, uint32_t b1) {
    asm volatile("mma.sync.aligned.m16n8k16.row.col.f32.f16.f16.f32 "
                 "{%0,%1,%2,%3}, {%4,%5,%6,%7}, {%8,%9}, {%0,%1,%2,%3};"
                 : "+f"(d[0]), "+f"(d[1]), "+f"(d[2]), "+f"(d[3])
                 : "r"(a[0]), "r"(a[1]), "r"(a[2]), "r"(a[3]), "r"(b0), "r"(b1));
}
__device__ __forceinline__ uint32_t pk2h(__half a, __half b) {
    return (uint32_t)__half_as_ushort(a) | ((uint32_t)__half_as_ushort(b) << 16);
}
__device__ __forceinline__ void cpasync16(uint32_t dst, const void* src, int srcsz) {
    asm volatile("cp.async.cg.shared.global [%0], [%1], 16, %2;"
                 :: "r"(dst), "l"(src), "r"(srcsz) : "memory");
}
#define CP_COMMIT() asm volatile("cp.async.commit_group;" ::: "memory")
#define CP_WAIT2()  asm volatile("cp.async.wait_group 2;" ::: "memory")

// ---------------- fp32 -> fp16 round (memory-bound pass) ----------
__global__ void cvt_k(const float4* __restrict__ in, uint2* __restrict__ out, int n4) {
    int i = blockIdx.x * 256 + threadIdx.x;
    if (i < n4) {
        float4 v = in[i];
        out[i] = make_uint2(pk2h(__float2half_rn(v.x), __float2half_rn(v.y)),
                            pk2h(__float2half_rn(v.z), __float2half_rn(v.w)));
    }
}

// ============================================================================
// HMMA fp16 NT GEMM: C[M,N] = Ah[M,K] * Bh[N,K]^T (fp32 accum), single product.
// Tile 128x128, BK=32, 4-stage cp.async pipeline, 2 CTAs/SM (4 warps/SMSP).
// One barrier per chunk; next stage's cp.async issued before the MMA block.
// ============================================================================
#define BK      32
#define TROW    80                       // padded row bytes: 16-aligned, 5 mod 8 -> ldmatrix conflict-free
#define TILE_B  (128 * TROW)             // 10240 B per fp16 tile
#define STAGE_B (2 * TILE_B)             // A | B = 20480 B
#define NSTAGE  4
#define GSMEM   (NSTAGE * STAGE_B)       // 81920 B -> 2 CTAs/SM

__device__ __forceinline__ void ld_stage(uint32_t sb, int stage,
        const __half* __restrict__ Ah, const __half* __restrict__ Bh,
        int m0, int n0, int K, int N, int k0, int t) {
    uint32_t stb = sb + (uint32_t)stage * STAGE_B;
    #pragma unroll
    for (int j = 0; j < 4; j++) {
        int lin = t + j * 256;                 // 0..1023
        int tile = lin >> 9, li = lin & 511;
        int row = li >> 2, c = li & 3;
        uint32_t dst = stb + (uint32_t)tile * TILE_B + (uint32_t)row * TROW + c * 16;
        const __half* src;
        int sz = 16;
        if (tile == 0) {
            src = Ah + (size_t)(m0 + row) * K + k0 + c * 8;
        } else {
            int r = n0 + row;
            if (r >= N) { r = 0; sz = 0; }
            src = Bh + (size_t)r * K + k0 + c * 8;
        }
        cpasync16(dst, src, sz);
    }
}

__global__ __launch_bounds__(256, 2)
void gemm_hf(const __half* __restrict__ Ah, const __half* __restrict__ Bh,
             float* __restrict__ C, int M, int N, int K) {
    extern __shared__ char smem[];
    const uint32_t sb = smem_u32(smem);
    const int t = threadIdx.x, wid = t >> 5, lane = t & 31;
    const int m0 = blockIdx.y * 128, n0b = blockIdx.x * 128;
    const int wm = (wid & 1) * 64, wn = (wid >> 1) * 32;

    float acc[4][4][4];
    #pragma unroll
    for (int i = 0; i < 4; i++)
        #pragma unroll
        for (int j = 0; j < 4; j++)
            #pragma unroll
            for (int k = 0; k < 4; k++) acc[i][j][k] = 0.f;

    const int NC = K / BK;
    #pragma unroll
    for (int s = 0; s < NSTAGE - 1; s++) {
        if (s < NC)
            ld_stage(sb, s, Ah, Bh, m0, n0b, K, N, s * BK, t);
        CP_COMMIT();
    }

    const int lr = lane & 15, lh = lane >> 4;

    for (int c = 0; c < NC; c++) {
        CP_WAIT2();
        __syncthreads();
        // issue next stage now so cp.async overlaps this chunk's MMAs
        int nx = c + NSTAGE - 1;
        if (nx < NC)
            ld_stage(sb, nx & (NSTAGE - 1), Ah, Bh, m0, n0b, K, N, nx * BK, t);
        CP_COMMIT();

        uint32_t stb = sb + (uint32_t)(c & (NSTAGE - 1)) * STAGE_B;
        #pragma unroll
        for (int kk = 0; kk < 2; kk++) {
            uint32_t kb = kk * 32 + lh * 16;
            uint32_t ah[4][4], bh[2][4];
            #pragma unroll
            for (int mf = 0; mf < 4; mf++) {
                uint32_t ro = (uint32_t)(wm + mf * 16 + lr) * TROW + kb;
                ldm4(ah[mf], stb + ro);
            }
            #pragma unroll
            for (int np = 0; np < 2; np++) {
                uint32_t ro = (uint32_t)(wn + np * 16 + lr) * TROW + kb;
                ldm4(bh[np], stb + TILE_B + ro);
            }
            #pragma unroll
            for (int mf = 0; mf < 4; mf++)
                #pragma unroll
                for (int np = 0; np < 2; np++) {
                    mma16816(acc[mf][2 * np],     ah[mf], bh[np][0], bh[np][2]);
                    mma16816(acc[mf][2 * np + 1], ah[mf], bh[np][1], bh[np][3]);
                }
        }
    }

    // epilogue: mma C layout — row = lane>>2 (+8), col = (lane&3)*2 (+1)
    const int gr = lane >> 2, gc = (lane & 3) * 2;
    #pragma unroll
    for (int mf = 0; mf < 4; mf++) {
        int m = m0 + wm + mf * 16 + gr;
        #pragma unroll
        for (int nf = 0; nf < 4; nf++) {
            int n = n0b + wn + nf * 8 + gc;
            if (n < N) {
                *(float2*)&C[(size_t)m * N + n] =
                    make_float2(acc[mf][nf][0], acc[mf][nf][1]);
                *(float2*)&C[(size_t)(m + 8) * N + n] =
                    make_float2(acc[mf][nf][2], acc[mf][nf][3]);
            }
        }
    }
}

// ---------------- conv1d (depthwise, causal, D_CONV=4) + SiLU, float4 -------
__global__ void conv_silu_k(const float* __restrict__ cw, const float* __restrict__ cb) {
    const int C4 = CONVDIM / 4;                    // 1056
    int idx = blockIdx.x * 256 + threadIdx.x;      // one float4 (4 channels)
    int c4 = idx % C4;
    int bl = idx / C4;                             // 0..MROWS-1
    int l = bl & (SEQ - 1), b = bl / SEQ;
    int c = c4 * 4;
    float4 acc = *(const float4*)&cb[c];
    float w[4][4];
    #pragma unroll
    for (int j = 0; j < 4; j++)
        *(float4*)w[j] = *(const float4*)&cw[(c + j) * 4];
    #pragma unroll
    for (int k = 0; k < 4; k++) {
        int ls = l - 3 + k;
        if (ls >= 0) {
            float4 v = *(const float4*)&g_zx[(size_t)(b * SEQ + ls) * EPROJ + DINNER + c];
            acc.x += v.x * w[0][k];
            acc.y += v.y * w[1][k];
            acc.z += v.z * w[2][k];
            acc.w += v.w * w[3][k];
        }
    }
    acc.x = acc.x / (1.f + __expf(-acc.x));
    acc.y = acc.y / (1.f + __expf(-acc.y));
    acc.z = acc.z / (1.f + __expf(-acc.z));
    acc.w = acc.w / (1.f + __expf(-acc.w));
    *(float4*)&g_xc[(size_t)bl * CONVDIM + c] = acc;
}

// ---------------- dt softplus + per-chunk cumsum(dA) ----------------
__global__ void dtcum_k(const float* __restrict__ dtb, const float* __restrict__ Alog) {
    int blk = blockIdx.x;                // ((b*16+c)*32+h)
    int h = blk & 31, c = (blk >> 5) & 15, b = blk >> 9;
    int s = threadIdx.x;
    int l = c * CHUNK + s;
    float raw = g_zx[((size_t)(b * SEQ + l)) * EPROJ + (EPROJ - NHEADS) + h] + dtb[h];
    float dtv = (raw > 20.f) ? raw : log1pf(__expf(raw));
    g_dtv[(size_t)(b * SEQ + l) * NHEADS + h] = dtv;
    float dA = dtv * (-__expf(Alog[h]));
    __shared__ float sc[256];
    sc[s] = dA;
    __syncthreads();
    for (int off = 1; off < 256; off <<= 1) {
        float v = (s >= off) ? sc[s - off] : 0.f;
        __syncthreads();
        sc[s] += v;
        __syncthreads();
    }
    g_cum[blk * CHUNK + s] = sc[s];
}

// ---------------- per-chunk states: st[p,n] = sum_z exp(cumL-cum[z])*dt[z]*x[z,p]*B[z,n]
__global__ __launch_bounds__(256)
void states_k() {
    extern __shared__ float sm[];
    float* xw  = sm;                 // 64*128
    float* Bsh = xw + 64 * 128;      // 64*64
    float* ws  = Bsh + 64 * 64;      // 256
    int blk = blockIdx.x;
    int h = blk & 31, c = (blk >> 5) & 15, b = blk >> 9;
    int t = threadIdx.x;
    float clast = g_cum[blk * CHUNK + 255];
    {
        float cz = g_cum[blk * CHUNK + t];
        float dtv = g_dtv[(size_t)(b * SEQ + c * CHUNK + t) * NHEADS + h];
        ws[t] = __expf(clast - cz) * dtv;
    }
    __syncthreads();
    int tx = t & 15, ty = t >> 4;
    int p0 = tx * 8, n0 = ty * 4;
    float acc[8][4];
    #pragma unroll
    for (int i = 0; i < 8; i++)
        #pragma unroll
        for (int j = 0; j < 4; j++) acc[i][j] = 0.f;
    size_t base = (size_t)(b * SEQ + c * CHUNK) * CONVDIM;
    for (int zt = 0; zt < 4; zt++) {
        #pragma unroll
        for (int i = 0; i < 32; i++) {
            int lin = t + i * 256; int zz = lin >> 7; int p = lin & 127; int z = zt * 64 + zz;
            xw[zz * 128 + p] = g_xc[base + (size_t)z * CONVDIM + h * DHEAD + p] * ws[z];
        }
        #pragma unroll
        for (int i = 0; i < 16; i++) {
            int lin = t + i * 256; int zz = lin >> 6; int n = lin & 63; int z = zt * 64 + zz;
            Bsh[zz * 64 + n] = g_xc[base + (size_t)z * CONVDIM + DINNER + n];
        }
        __syncthreads();
        #pragma unroll
        for (int zz = 0; zz < 64; zz++) {
            float xv[8];
            *(float4*)&xv[0] = *(const float4*)&xw[zz * 128 + p0];
            *(float4*)&xv[4] = *(const float4*)&xw[zz * 128 + p0 + 4];
            float4 bv = *(const float4*)&Bsh[zz * 64 + n0];
            float bb[4] = {bv.x, bv.y, bv.z, bv.w};
            #pragma unroll
            for (int i = 0; i < 8; i++)
                #pragma unroll
                for (int j = 0; j < 4; j++)
                    acc[i][j] += xv[i] * bb[j];
        }
        __syncthreads();
    }
    size_t ob = (size_t)blk * DHEAD * DSTATE;
    #pragma unroll
    for (int i = 0; i < 8; i++)
        #pragma unroll
        for (int j = 0; j < 4; j++)
            g_st[ob + (size_t)(p0 + i) * DSTATE + n0 + j] = acc[i][j];
}

// ---------------- inter-chunk scan (16 steps, parallel over (b,h) and (p,n))
__global__ void scan_k() {
    int blk = blockIdx.x;                // b*32 + h
    int h = blk & 31, b = blk >> 5;
    int t = threadIdx.x;
    float carry[32];
    #pragma unroll
    for (int k = 0; k < 32; k++) carry[k] = 0.f;
    for (int c = 0; c < NCHUNK; c++) {
        int idx = (b * NCHUNK + c) * NHEADS + h;
        float decay = __expf(g_cum[idx * CHUNK + 255]);
        size_t base = (size_t)idx * DHEAD * DSTATE;
        #pragma unroll
        for (int k = 0; k < 32; k++) {
            size_t e = base + t + k * 256;
            g_pv[e] = carry[k];
            carry[k] = carry[k] * decay + g_st[e];
        }
    }
}

// ---------------- Y kernel: Y = masked(C B^T L) @ xdt + exp(cum)*C@prev^T + D*x
#define BTS 260
#define CTS 68
#define PTS 132
__global__ __launch_bounds__(256, 1)
void y_k(const float* __restrict__ Dvec) {
    extern __shared__ float sm[];
    float* Bt   = sm;                  // [64][BTS]  B^T (n-major)
    float* Gtt  = Bt + 64 * BTS;       // [256][64]  G^T (z-major, masked*L)
    float* Ct   = Gtt + 256 * 64;      // [64][CTS]  C^T tile (n-major)
    float* sX   = Ct + 64 * CTS;       // [64][128]  xdt z-tile
    float* pT   = sX + 64 * 128;       // [64][PTS]  prev^T (n-major)
    float* cums = pT + 64 * PTS;       // [256]
    float* sdt  = cums + 256;          // [256]
    int blk = blockIdx.x;
    int h = blk & 31, c = (blk >> 5) & 15, b = blk >> 9;
    int t = threadIdx.x;
    size_t base = (size_t)(b * SEQ + c * CHUNK) * CONVDIM;

    cums[t] = g_cum[blk * CHUNK + t];
    sdt[t]  = g_dtv[(size_t)(b * SEQ + c * CHUNK + t) * NHEADS + h];
    #pragma unroll
    for (int i = 0; i < 64; i++) {
        int lin = t + i * 256; int n = lin & 63; int z = lin >> 6;
        Bt[n * BTS + z] = g_xc[base + (size_t)z * CONVDIM + DINNER + n];
    }
    size_t pvb = (size_t)blk * DHEAD * DSTATE;
    #pragma unroll
    for (int i = 0; i < 32; i++) {
        int lin = t + i * 256; int n = lin & 63; int p = lin >> 6;
        pT[n * PTS + p] = g_pv[pvb + (size_t)p * DSTATE + n];
    }
    __syncthreads();
    float Dh = Dvec[h];
    const int sg = t & 15, zg = t >> 4;    // phase-1 mapping
    const int pg = t & 15, sg2 = t >> 4;   // phase-2/3 mapping

    for (int st = 0; st < 4; st++) {
        int s0 = st * 64;
        #pragma unroll
        for (int i = 0; i < 16; i++) {
            int lin = t + i * 256; int n = lin & 63; int si = lin >> 6;
            Ct[n * CTS + si] = g_xc[base + (size_t)(s0 + si) * CONVDIM + DINNER + DSTATE + n];
        }
        __syncthreads();
        // -------- phase 1: G^T tile = (C_tile · B^T), masked * L --------
        {
            int sl0 = sg * 4, z0 = zg * 16;
            float acc1[4][16];
            #pragma unroll
            for (int i = 0; i < 4; i++)
                #pragma unroll
                for (int j = 0; j < 16; j++) acc1[i][j] = 0.f;
            if (z0 <= s0 + 63) {
                for (int n = 0; n < 64; n++) {
                    float cv[4];
                    *(float4*)cv = *(const float4*)&Ct[n * CTS + sl0];
                    float bz[16];
                    #pragma unroll
                    for (int j = 0; j < 16; j += 4)
                        *(float4*)&bz[j] = *(const float4*)&Bt[n * BTS + z0 + j];
                    #pragma unroll
                    for (int i = 0; i < 4; i++)
                        #pragma unroll
                        for (int j = 0; j < 16; j++)
                            acc1[i][j] += cv[i] * bz[j];
                }
            }
            #pragma unroll
            for (int i = 0; i < 4; i++) {
                int sgl = s0 + sl0 + i;
                float cs = cums[sgl];
                #pragma unroll
                for (int j = 0; j < 16; j++) {
                    int z = z0 + j;
                    float v = (z <= sgl) ? acc1[i][j] * __expf(cs - cums[z]) : 0.f;
                    Gtt[z * 64 + sl0 + i] = v;
                }
            }
        }
        __syncthreads();
        // -------- phase 2: Y_tile += G^T-masked @ xdt (skip fully-masked z-tiles)
        int p0 = pg * 8, sl0 = sg2 * 4;
        float acc2[4][8];
        #pragma unroll
        for (int i = 0; i < 4; i++)
            #pragma unroll
            for (int j = 0; j < 8; j++) acc2[i][j] = 0.f;
        for (int zt = 0; zt <= st; zt++) {
            #pragma unroll
            for (int i = 0; i < 32; i++) {
                int lin = t + i * 256; int zz = lin >> 7; int p = lin & 127; int z = zt * 64 + zz;
                sX[zz * 128 + p] = g_xc[base + (size_t)z * CONVDIM + h * DHEAD + p] * sdt[z];
            }
            __syncthreads();
            #pragma unroll
            for (int zz = 0; zz < 64; zz++) {
                float gv[4];
                *(float4*)gv = *(const float4*)&Gtt[(zt * 64 + zz) * 64 + sl0];
                float xv[8];
                *(float4*)&xv[0] = *(const float4*)&sX[zz * 128 + p0];
                *(float4*)&xv[4] = *(const float4*)&sX[zz * 128 + p0 + 4];
                #pragma unroll
                for (int i = 0; i < 4; i++)
                    #pragma unroll
                    for (int j = 0; j < 8; j++)
                        acc2[i][j] += gv[i] * xv[j];
            }
            __syncthreads();
        }
        // -------- phase 3: Y_off = exp(cum[s]) * C · prev^T --------
        {
            float es[4];
            #pragma unroll
            for (int i = 0; i < 4; i++) es[i] = __expf(cums[s0 + sl0 + i]);
            for (int n = 0; n < 64; n++) {
                float cv[4];
                *(float4*)cv = *(const float4*)&Ct[n * CTS + sl0];
                float pv[8];
                *(float4*)&pv[0] = *(const float4*)&pT[n * PTS + p0];
                *(float4*)&pv[4] = *(const float4*)&pT[n * PTS + p0 + 4];
                #pragma unroll
                for (int i = 0; i < 4; i++) {
                    float cvs = cv[i] * es[i];
                    #pragma unroll
                    for (int j = 0; j < 8; j++)
                        acc2[i][j] += cvs * pv[j];
                }
            }
        }
        // -------- store: + D*x --------
        #pragma unroll
        for (int i = 0; i < 4; i++) {
            int s = s0 + sl0 + i;
            size_t row = (size_t)(b * SEQ + c * CHUNK + s);
            #pragma unroll
            for (int j = 0; j < 8; j++) {
                int p = p0 + j;
                g_y[row * DINNER + h * DHEAD + p] =
                    acc2[i][j] + Dh * g_xc[row * CONVDIM + h * DHEAD + p];
            }
        }
        __syncthreads();
    }
}

// ---------------- gated RMSNorm fused with fp16 round for GEMM2 ------
__global__ void gatenorm_k(const float* __restrict__ nw) {
    int row = blockIdx.x;
    __shared__ float yg[DINNER];
    __shared__ float red[256];
    int t = threadIdx.x;
    float ss = 0.f;
    size_t zb = (size_t)row * EPROJ;
    size_t yb = (size_t)row * DINNER;
    #pragma unroll
    for (int i = 0; i < 16; i++) {
        int e = t + i * 256;
        float z = g_zx[zb + e];
        float sz = z / (1.f + __expf(-z));
        float v = g_y[yb + e] * sz;
        yg[e] = v;
        ss += v * v;
    }
    red[t] = ss;
    __syncthreads();
    for (int off = 128; off > 0; off >>= 1) {
        if (t < off) red[t] += red[t + off];
        __syncthreads();
    }
    float scale = rsqrtf(red[0] / (float)DINNER + 1e-5f);
    #pragma unroll
    for (int i = 0; i < 16; i++) {
        int e = t + i * 256;
        float v = yg[e] * scale * nw[e];
        g_Ah[yb + e] = __float2half_rn(v);
    }
}

// ---------------- launch ----------------
extern "C" void kernel_launch(void* const* d_in, const int* in_sizes, int n_in,
                              void* d_out, int out_size) {
    const float* u     = (const float*)d_in[0];
    const float* W_in  = (const float*)d_in[1];
    const float* convw = (const float*)d_in[2];
    const float* convb = (const float*)d_in[3];
    const float* dtb   = (const float*)d_in[4];
    const float* Alog  = (const float*)d_in[5];
    const float* Dvec  = (const float*)d_in[6];
    const float* nw    = (const float*)d_in[7];
    const float* W_out = (const float*)d_in[8];
    float* out = (float*)d_out;

    float* zx_p;
    __half *ah_p, *bh_p;
    cudaGetSymbolAddress((void**)&zx_p, g_zx);
    cudaGetSymbolAddress((void**)&ah_p, g_Ah);
    cudaGetSymbolAddress((void**)&bh_p, g_Bh);

    const int STATES_SMEM = (64 * 128 + 64 * 64 + 256) * 4;
    const int Y_SMEM = (64 * BTS + 256 * 64 + 64 * CTS + 64 * 128 + 64 * PTS + 512) * 4;
    cudaFuncSetAttribute(states_k, cudaFuncAttributeMaxDynamicSharedMemorySize, STATES_SMEM);
    cudaFuncSetAttribute(y_k,      cudaFuncAttributeMaxDynamicSharedMemorySize, Y_SMEM);
    cudaFuncSetAttribute(gemm_hf,  cudaFuncAttributeMaxDynamicSharedMemorySize, GSMEM);

    // ---- GEMM1: zx[8192,8352] = u[8192,2048] @ W_in[8352,2048]^T ----
    {
        int n4a = MROWS * DMODEL / 4;       // u
        int n4b = EPROJ * DMODEL / 4;       // W_in
        cvt_k<<<(n4a + 255) / 256, 256>>>((const float4*)u, (uint2*)ah_p, n4a);
        cvt_k<<<(n4b + 255) / 256, 256>>>((const float4*)W_in, (uint2*)bh_p, n4b);
        gemm_hf<<<dim3(66, 64), 256, GSMEM>>>(ah_p, bh_p, zx_p, MROWS, EPROJ, DMODEL);
    }
    // ---- SSD middle section ----
    conv_silu_k<<<(int)(((size_t)MROWS * (CONVDIM / 4)) / 256), 256>>>(convw, convb);
    dtcum_k<<<1024, 256>>>(dtb, Alog);
    states_k<<<1024, 256, STATES_SMEM>>>();
    scan_k<<<64, 256>>>();
    y_k<<<1024, 256, Y_SMEM>>>(Dvec);
    gatenorm_k<<<MROWS, 256>>>(nw);     // writes fp16 yn into g_Ah
    // ---- GEMM2: out[8192,2048] = yn[8192,4096] @ W_out[2048,4096]^T ----
    {
        int n4b = DMODEL * DINNER / 4;      // W_out
        cvt_k<<<(n4b + 255) / 256, 256>>>((const float4*)W_out, (uint2*)bh_p, n4b);
        gemm_hf<<<dim3(16, 64), 256, GSMEM>>>(ah_p, bh_p, out, MROWS, DMODEL, DINNER);
    }
}

// round 14
// speedup vs baseline: 2.8847x; 1.0681x over previous
#include <cuda_runtime.h>
#include <cuda_fp16.h>
#include <cstdint>
#include <cstddef>

#define BATCH   2
#define SEQ     4096
#define DMODEL  2048
#define DINNER  4096
#define NHEADS  32
#define DHEAD   128
#define DSTATE  64
#define CONVDIM 4224          // DINNER + 2*DSTATE
#define EPROJ   8352          // 2*DINNER + 2*DSTATE + NHEADS
#define NCHUNK  16
#define CHUNK   256
#define MROWS   8192          // BATCH*SEQ

// ---------------- device scratch (static: allocation-free) ----------------
__device__ float g_zx[(size_t)MROWS * EPROJ];     // in_proj output
__device__ float g_xc[(size_t)MROWS * CONVDIM];   // conv+silu output
__device__ float g_dtv[(size_t)MROWS * NHEADS];   // softplus dt
__device__ float g_cum[BATCH * NCHUNK * NHEADS * CHUNK]; // per-chunk cumsum(dA)
__device__ float g_st[(size_t)BATCH * NCHUNK * NHEADS * DHEAD * DSTATE]; // chunk states
__device__ float g_pv[(size_t)BATCH * NCHUNK * NHEADS * DHEAD * DSTATE]; // prev states
__device__ float g_y [(size_t)MROWS * DINNER];    // y (pre-norm)
// fp16 operands (single-rounded A and B)
__device__ __half g_Ah[(size_t)MROWS * DINNER];
__device__ __half g_Bh[(size_t)EPROJ * DMODEL];

// ============================================================================
// helpers
// ============================================================================
__device__ __forceinline__ uint32_t smem_u32(const void* p) {
    uint32_t a;
    asm("{ .reg .u64 t; cvta.to.shared.u64 t, %1; cvt.u32.u64 %0, t; }" : "=r"(a) : "l"(p));
    return a;
}
__device__ __forceinline__ void ldm4(uint32_t* r, uint32_t a) {
    asm volatile("ldmatrix.sync.aligned.m8n8.x4.shared.b16 {%0,%1,%2,%3}, [%4];"
                 : "=r"(r[0]), "=r"(r[1]), "=r"(r[2]), "=r"(r[3]) : "r"(a));
}
__device__ __forceinline__ void mma16816(float* d, const uint32_t* a, uint32_t b0, uint32_t b1) {
    asm volatile("mma.sync.aligned.m16n8k16.row.col.f32.f16.f16.f32 "
                 "{%0,%1,%2,%3}, {%4,%5,%6,%7}, {%8,%9}, {%0,%1,%2,%3};"
                 : "+f"(d[0]), "+f"(d[1]), "+f"(d[2]), "+f"(d[3])
                 : "r"(a[0]), "r"(a[1]), "r"(a[2]), "r"(a[3]), "r"(b0), "r"(b1));
}
__device__ __forceinline__ uint32_t pk2h(__half a, __half b) {
    return (uint32_t)__half_as_ushort(a) | ((uint32_t)__half_as_ushort(b) << 16);
}
__device__ __forceinline__ void cpasync16(uint32_t dst, const void* src, int srcsz) {
    asm volatile("cp.async.cg.shared.global [%0], [%1], 16, %2;"
                 :: "r"(dst), "l"(src), "r"(srcsz) : "memory");
}
#define CP_COMMIT() asm volatile("cp.async.commit_group;" ::: "memory")
#define CP_WAIT2()  asm volatile("cp.async.wait_group 2;" ::: "memory")

// ---------------- fp32 -> fp16 round (memory-bound pass) ----------
__global__ void cvt_k(const float4* __restrict__ in, uint2* __restrict__ out, int n4) {
    int i = blockIdx.x * 256 + threadIdx.x;
    if (i < n4) {
        float4 v = in[i];
        out[i] = make_uint2(pk2h(__float2half_rn(v.x), __float2half_rn(v.y)),
                            pk2h(__float2half_rn(v.z), __float2half_rn(v.w)));
    }
}

// ============================================================================
// HMMA fp16 NT GEMM: C[M,N] = Ah[M,K] * Bh[N,K]^T (fp32 accum), single product.
// Tile 128x128, BK=32, 4-stage cp.async pipeline, 2 CTAs/SM (4 warps/SMSP).
// ============================================================================
#define BK      32
#define TROW    80                       // padded row bytes: 16-aligned, 5 mod 8 -> ldmatrix conflict-free
#define TILE_B  (128 * TROW)             // 10240 B per fp16 tile
#define STAGE_B (2 * TILE_B)             // A | B = 20480 B
#define NSTAGE  4
#define GSMEM   (NSTAGE * STAGE_B)       // 81920 B -> 2 CTAs/SM

__device__ __forceinline__ void ld_stage(uint32_t sb, int stage,
        const __half* __restrict__ Ah, const __half* __restrict__ Bh,
        int m0, int n0, int K, int N, int k0, int t) {
    uint32_t stb = sb + (uint32_t)stage * STAGE_B;
    #pragma unroll
    for (int j = 0; j < 4; j++) {
        int lin = t + j * 256;                 // 0..1023
        int tile = lin >> 9, li = lin & 511;
        int row = li >> 2, c = li & 3;
        uint32_t dst = stb + (uint32_t)tile * TILE_B + (uint32_t)row * TROW + c * 16;
        const __half* src;
        int sz = 16;
        if (tile == 0) {
            src = Ah + (size_t)(m0 + row) * K + k0 + c * 8;
        } else {
            int r = n0 + row;
            if (r >= N) { r = 0; sz = 0; }
            src = Bh + (size_t)r * K + k0 + c * 8;
        }
        cpasync16(dst, src, sz);
    }
}

__global__ __launch_bounds__(256, 2)
void gemm_hf(const __half* __restrict__ Ah, const __half* __restrict__ Bh,
             float* __restrict__ C, int M, int N, int K) {
    extern __shared__ char smem[];
    const uint32_t sb = smem_u32(smem);
    const int t = threadIdx.x, wid = t >> 5, lane = t & 31;
    const int m0 = blockIdx.y * 128, n0b = blockIdx.x * 128;
    const int wm = (wid & 1) * 64, wn = (wid >> 1) * 32;

    float acc[4][4][4];
    #pragma unroll
    for (int i = 0; i < 4; i++)
        #pragma unroll
        for (int j = 0; j < 4; j++)
            #pragma unroll
            for (int k = 0; k < 4; k++) acc[i][j][k] = 0.f;

    const int NC = K / BK;
    #pragma unroll
    for (int s = 0; s < NSTAGE - 1; s++) {
        if (s < NC)
            ld_stage(sb, s, Ah, Bh, m0, n0b, K, N, s * BK, t);
        CP_COMMIT();
    }

    const int lr = lane & 15, lh = lane >> 4;

    for (int c = 0; c < NC; c++) {
        CP_WAIT2();
        __syncthreads();
        int nx = c + NSTAGE - 1;
        if (nx < NC)
            ld_stage(sb, nx & (NSTAGE - 1), Ah, Bh, m0, n0b, K, N, nx * BK, t);
        CP_COMMIT();

        uint32_t stb = sb + (uint32_t)(c & (NSTAGE - 1)) * STAGE_B;
        #pragma unroll
        for (int kk = 0; kk < 2; kk++) {
            uint32_t kb = kk * 32 + lh * 16;
            uint32_t ah[4][4], bh[2][4];
            #pragma unroll
            for (int mf = 0; mf < 4; mf++) {
                uint32_t ro = (uint32_t)(wm + mf * 16 + lr) * TROW + kb;
                ldm4(ah[mf], stb + ro);
            }
            #pragma unroll
            for (int np = 0; np < 2; np++) {
                uint32_t ro = (uint32_t)(wn + np * 16 + lr) * TROW + kb;
                ldm4(bh[np], stb + TILE_B + ro);
            }
            #pragma unroll
            for (int mf = 0; mf < 4; mf++)
                #pragma unroll
                for (int np = 0; np < 2; np++) {
                    mma16816(acc[mf][2 * np],     ah[mf], bh[np][0], bh[np][2]);
                    mma16816(acc[mf][2 * np + 1], ah[mf], bh[np][1], bh[np][3]);
                }
        }
    }

    const int gr = lane >> 2, gc = (lane & 3) * 2;
    #pragma unroll
    for (int mf = 0; mf < 4; mf++) {
        int m = m0 + wm + mf * 16 + gr;
        #pragma unroll
        for (int nf = 0; nf < 4; nf++) {
            int n = n0b + wn + nf * 8 + gc;
            if (n < N) {
                *(float2*)&C[(size_t)m * N + n] =
                    make_float2(acc[mf][nf][0], acc[mf][nf][1]);
                *(float2*)&C[(size_t)(m + 8) * N + n] =
                    make_float2(acc[mf][nf][2], acc[mf][nf][3]);
            }
        }
    }
}

// ---------------- conv1d + SiLU, smem-tiled (kills 4x L1 re-read) ----------
// block: 32 l-rows x 32 float4-cols (128 channels); halo 3 rows.
__global__ __launch_bounds__(256)
void conv_silu_k(const float* __restrict__ cw, const float* __restrict__ cb) {
    __shared__ float4 sx[35][32];                  // 17.9 KB
    const int C4 = CONVDIM / 4;                    // 1056
    int bc = blockIdx.x % (C4 / 32);               // 0..32
    int bl0 = (blockIdx.x / (C4 / 32)) * 32;       // 0..MROWS-32, 32 | SEQ
    int b = bl0 / SEQ, l0 = bl0 % SEQ;
    int c40 = bc * 32;
    int t = threadIdx.x;
    // load rows l0-3 .. l0+31 (35) x 32 float4
    for (int i = t; i < 35 * 32; i += 256) {
        int r = i >> 5, cc = i & 31;
        int ls = l0 - 3 + r;
        float4 v = make_float4(0.f, 0.f, 0.f, 0.f);
        if (ls >= 0)
            v = *(const float4*)&g_zx[(size_t)(b * SEQ + ls) * EPROJ + DINNER + (c40 + cc) * 4];
        sx[r][cc] = v;
    }
    __syncthreads();
    int cc = t & 31, lr0 = (t >> 5) * 4;
    int c = (c40 + cc) * 4;
    float4 bias = *(const float4*)&cb[c];
    float w[4][4];
    #pragma unroll
    for (int j = 0; j < 4; j++)
        *(float4*)w[j] = *(const float4*)&cw[(c + j) * 4];
    #pragma unroll
    for (int j = 0; j < 4; j++) {
        int lr = lr0 + j;
        float4 acc = bias;
        #pragma unroll
        for (int k = 0; k < 4; k++) {
            float4 v = sx[lr + k][cc];
            acc.x += v.x * w[0][k];
            acc.y += v.y * w[1][k];
            acc.z += v.z * w[2][k];
            acc.w += v.w * w[3][k];
        }
        acc.x = acc.x / (1.f + __expf(-acc.x));
        acc.y = acc.y / (1.f + __expf(-acc.y));
        acc.z = acc.z / (1.f + __expf(-acc.z));
        acc.w = acc.w / (1.f + __expf(-acc.w));
        *(float4*)&g_xc[(size_t)(bl0 + lr) * CONVDIM + c] = acc;
    }
}

// ---------------- dt softplus + per-chunk cumsum(dA) ----------------
__global__ void dtcum_k(const float* __restrict__ dtb, const float* __restrict__ Alog) {
    int blk = blockIdx.x;                // ((b*16+c)*32+h)
    int h = blk & 31, c = (blk >> 5) & 15, b = blk >> 9;
    int s = threadIdx.x;
    int l = c * CHUNK + s;
    float raw = g_zx[((size_t)(b * SEQ + l)) * EPROJ + (EPROJ - NHEADS) + h] + dtb[h];
    float dtv = (raw > 20.f) ? raw : log1pf(__expf(raw));
    g_dtv[(size_t)(b * SEQ + l) * NHEADS + h] = dtv;
    float dA = dtv * (-__expf(Alog[h]));
    __shared__ float sc[256];
    sc[s] = dA;
    __syncthreads();
    for (int off = 1; off < 256; off <<= 1) {
        float v = (s >= off) ? sc[s - off] : 0.f;
        __syncthreads();
        sc[s] += v;
        __syncthreads();
    }
    g_cum[blk * CHUNK + s] = sc[s];
}

// ---------------- per-chunk states (512 threads, 4x4 tile, 2 CTAs/SM) ------
__global__ __launch_bounds__(512, 2)
void states_k() {
    extern __shared__ float sm[];
    float* xw  = sm;                 // 64*128
    float* Bsh = xw + 64 * 128;      // 64*64
    float* ws  = Bsh + 64 * 64;      // 256
    int blk = blockIdx.x;
    int h = blk & 31, c = (blk >> 5) & 15, b = blk >> 9;
    int t = threadIdx.x;
    if (t < 256) {
        float clast = g_cum[blk * CHUNK + 255];
        float cz = g_cum[blk * CHUNK + t];
        float dtv = g_dtv[(size_t)(b * SEQ + c * CHUNK + t) * NHEADS + h];
        ws[t] = __expf(clast - cz) * dtv;
    }
    __syncthreads();
    int tx = t & 31, ty = t >> 5;        // p-group / n-group
    int p0 = tx * 4, n0 = ty * 4;
    float acc[4][4];
    #pragma unroll
    for (int i = 0; i < 4; i++)
        #pragma unroll
        for (int j = 0; j < 4; j++) acc[i][j] = 0.f;
    size_t base = (size_t)(b * SEQ + c * CHUNK) * CONVDIM;
    for (int zt = 0; zt < 4; zt++) {
        #pragma unroll
        for (int i = 0; i < 16; i++) {
            int lin = t + i * 512; int zz = lin >> 7; int p = lin & 127; int z = zt * 64 + zz;
            xw[zz * 128 + p] = g_xc[base + (size_t)z * CONVDIM + h * DHEAD + p] * ws[z];
        }
        #pragma unroll
        for (int i = 0; i < 8; i++) {
            int lin = t + i * 512; int zz = lin >> 6; int n = lin & 63; int z = zt * 64 + zz;
            Bsh[zz * 64 + n] = g_xc[base + (size_t)z * CONVDIM + DINNER + n];
        }
        __syncthreads();
        #pragma unroll
        for (int zz = 0; zz < 64; zz++) {
            float4 xv4 = *(const float4*)&xw[zz * 128 + p0];
            float4 bv = *(const float4*)&Bsh[zz * 64 + n0];
            float xv[4] = {xv4.x, xv4.y, xv4.z, xv4.w};
            float bb[4] = {bv.x, bv.y, bv.z, bv.w};
            #pragma unroll
            for (int i = 0; i < 4; i++)
                #pragma unroll
                for (int j = 0; j < 4; j++)
                    acc[i][j] += xv[i] * bb[j];
        }
        __syncthreads();
    }
    size_t ob = (size_t)blk * DHEAD * DSTATE;
    #pragma unroll
    for (int i = 0; i < 4; i++)
        #pragma unroll
        for (int j = 0; j < 4; j++)
            g_st[ob + (size_t)(p0 + i) * DSTATE + n0 + j] = acc[i][j];
}

// ---------------- inter-chunk scan (256 blocks: (b,h,quarter)) -------------
__global__ void scan_k() {
    int blk = blockIdx.x;                // b*128 + h*4 + q
    int q = blk & 3, h = (blk >> 2) & 31, b = blk >> 7;
    int t = threadIdx.x;
    int e0 = q * 2048 + t;
    float carry[8];
    #pragma unroll
    for (int k = 0; k < 8; k++) carry[k] = 0.f;
    for (int c = 0; c < NCHUNK; c++) {
        int idx = (b * NCHUNK + c) * NHEADS + h;
        float decay = __expf(g_cum[idx * CHUNK + 255]);
        size_t base = (size_t)idx * DHEAD * DSTATE + e0;
        #pragma unroll
        for (int k = 0; k < 8; k++) {
            size_t e = base + k * 256;
            g_pv[e] = carry[k];
            carry[k] = carry[k] * decay + g_st[e];
        }
    }
}

// ---------------- Y kernel: Y = masked(C B^T L) @ xdt + exp(cum)*C@prev^T + D*x
#define BTS 260
#define CTS 68
#define PTS 132
__global__ __launch_bounds__(256, 1)
void y_k(const float* __restrict__ Dvec) {
    extern __shared__ float sm[];
    float* Bt   = sm;                  // [64][BTS]  B^T (n-major)
    float* Gtt  = Bt + 64 * BTS;       // [256][64]  G^T (z-major, masked*L)
    float* Ct   = Gtt + 256 * 64;      // [64][CTS]  C^T tile (n-major)
    float* sX   = Ct + 64 * CTS;       // [64][128]  xdt z-tile
    float* pT   = sX + 64 * 128;       // [64][PTS]  prev^T (n-major)
    float* cums = pT + 64 * PTS;       // [256]
    float* sdt  = cums + 256;          // [256]
    int blk = blockIdx.x;
    int h = blk & 31, c = (blk >> 5) & 15, b = blk >> 9;
    int t = threadIdx.x;
    size_t base = (size_t)(b * SEQ + c * CHUNK) * CONVDIM;

    cums[t] = g_cum[blk * CHUNK + t];
    sdt[t]  = g_dtv[(size_t)(b * SEQ + c * CHUNK + t) * NHEADS + h];
    #pragma unroll
    for (int i = 0; i < 64; i++) {
        int lin = t + i * 256; int n = lin & 63; int z = lin >> 6;
        Bt[n * BTS + z] = g_xc[base + (size_t)z * CONVDIM + DINNER + n];
    }
    size_t pvb = (size_t)blk * DHEAD * DSTATE;
    #pragma unroll
    for (int i = 0; i < 32; i++) {
        int lin = t + i * 256; int n = lin & 63; int p = lin >> 6;
        pT[n * PTS + p] = g_pv[pvb + (size_t)p * DSTATE + n];
    }
    __syncthreads();
    float Dh = Dvec[h];
    const int sg = t & 15, zg = t >> 4;    // phase-1 mapping
    const int pg = t & 15, sg2 = t >> 4;   // phase-2/3 mapping

    for (int st = 0; st < 4; st++) {
        int s0 = st * 64;
        #pragma unroll
        for (int i = 0; i < 16; i++) {
            int lin = t + i * 256; int n = lin & 63; int si = lin >> 6;
            Ct[n * CTS + si] = g_xc[base + (size_t)(s0 + si) * CONVDIM + DINNER + DSTATE + n];
        }
        __syncthreads();
        // -------- phase 1: G^T tile = (C_tile · B^T), masked * L --------
        {
            int sl0 = sg * 4, z0 = zg * 16;
            float acc1[4][16];
            #pragma unroll
            for (int i = 0; i < 4; i++)
                #pragma unroll
                for (int j = 0; j < 16; j++) acc1[i][j] = 0.f;
            if (z0 <= s0 + 63) {
                for (int n = 0; n < 64; n++) {
                    float cv[4];
                    *(float4*)cv = *(const float4*)&Ct[n * CTS + sl0];
                    float bz[16];
                    #pragma unroll
                    for (int j = 0; j < 16; j += 4)
                        *(float4*)&bz[j] = *(const float4*)&Bt[n * BTS + z0 + j];
                    #pragma unroll
                    for (int i = 0; i < 4; i++)
                        #pragma unroll
                        for (int j = 0; j < 16; j++)
                            acc1[i][j] += cv[i] * bz[j];
                }
            }
            #pragma unroll
            for (int i = 0; i < 4; i++) {
                int sgl = s0 + sl0 + i;
                float cs = cums[sgl];
                #pragma unroll
                for (int j = 0; j < 16; j++) {
                    int z = z0 + j;
                    float v = (z <= sgl) ? acc1[i][j] * __expf(cs - cums[z]) : 0.f;
                    Gtt[z * 64 + sl0 + i] = v;
                }
            }
        }
        __syncthreads();
        // -------- phase 2: Y_tile += G^T-masked @ xdt --------
        int p0 = pg * 8, sl0 = sg2 * 4;
        float acc2[4][8];
        #pragma unroll
        for (int i = 0; i < 4; i++)
            #pragma unroll
            for (int j = 0; j < 8; j++) acc2[i][j] = 0.f;
        for (int zt = 0; zt <= st; zt++) {
            #pragma unroll
            for (int i = 0; i < 32; i++) {
                int lin = t + i * 256; int zz = lin >> 7; int p = lin & 127; int z = zt * 64 + zz;
                sX[zz * 128 + p] = g_xc[base + (size_t)z * CONVDIM + h * DHEAD + p] * sdt[z];
            }
            __syncthreads();
            #pragma unroll
            for (int zz = 0; zz < 64; zz++) {
                float gv[4];
                *(float4*)gv = *(const float4*)&Gtt[(zt * 64 + zz) * 64 + sl0];
                float xv[8];
                *(float4*)&xv[0] = *(const float4*)&sX[zz * 128 + p0];
                *(float4*)&xv[4] = *(const float4*)&sX[zz * 128 + p0 + 4];
                #pragma unroll
                for (int i = 0; i < 4; i++)
                    #pragma unroll
                    for (int j = 0; j < 8; j++)
                        acc2[i][j] += gv[i] * xv[j];
            }
            __syncthreads();
        }
        // -------- phase 3: Y_off = exp(cum[s]) * C · prev^T --------
        {
            float es[4];
            #pragma unroll
            for (int i = 0; i < 4; i++) es[i] = __expf(cums[s0 + sl0 + i]);
            for (int n = 0; n < 64; n++) {
                float cv[4];
                *(float4*)cv = *(const float4*)&Ct[n * CTS + sl0];
                float pv[8];
                *(float4*)&pv[0] = *(const float4*)&pT[n * PTS + p0];
                *(float4*)&pv[4] = *(const float4*)&pT[n * PTS + p0 + 4];
                #pragma unroll
                for (int i = 0; i < 4; i++) {
                    float cvs = cv[i] * es[i];
                    #pragma unroll
                    for (int j = 0; j < 8; j++)
                        acc2[i][j] += cvs * pv[j];
                }
            }
        }
        // -------- store: + D*x --------
        #pragma unroll
        for (int i = 0; i < 4; i++) {
            int s = s0 + sl0 + i;
            size_t row = (size_t)(b * SEQ + c * CHUNK + s);
            #pragma unroll
            for (int j = 0; j < 8; j++) {
                int p = p0 + j;
                g_y[row * DINNER + h * DHEAD + p] =
                    acc2[i][j] + Dh * g_xc[row * CONVDIM + h * DHEAD + p];
            }
        }
        __syncthreads();
    }
}

// ---------------- gated RMSNorm fused with fp16 round for GEMM2 ------
__global__ void gatenorm_k(const float* __restrict__ nw) {
    int row = blockIdx.x;
    __shared__ float yg[DINNER];
    __shared__ float red[256];
    int t = threadIdx.x;
    float ss = 0.f;
    size_t zb = (size_t)row * EPROJ;
    size_t yb = (size_t)row * DINNER;
    #pragma unroll
    for (int i = 0; i < 16; i++) {
        int e = t + i * 256;
        float z = g_zx[zb + e];
        float sz = z / (1.f + __expf(-z));
        float v = g_y[yb + e] * sz;
        yg[e] = v;
        ss += v * v;
    }
    red[t] = ss;
    __syncthreads();
    for (int off = 128; off > 0; off >>= 1) {
        if (t < off) red[t] += red[t + off];
        __syncthreads();
    }
    float scale = rsqrtf(red[0] / (float)DINNER + 1e-5f);
    #pragma unroll
    for (int i = 0; i < 16; i++) {
        int e = t + i * 256;
        float v = yg[e] * scale * nw[e];
        g_Ah[yb + e] = __float2half_rn(v);
    }
}

// ---------------- launch ----------------
extern "C" void kernel_launch(void* const* d_in, const int* in_sizes, int n_in,
                              void* d_out, int out_size) {
    const float* u     = (const float*)d_in[0];
    const float* W_in  = (const float*)d_in[1];
    const float* convw = (const float*)d_in[2];
    const float* convb = (const float*)d_in[3];
    const float* dtb   = (const float*)d_in[4];
    const float* Alog  = (const float*)d_in[5];
    const float* Dvec  = (const float*)d_in[6];
    const float* nw    = (const float*)d_in[7];
    const float* W_out = (const float*)d_in[8];
    float* out = (float*)d_out;

    float* zx_p;
    __half *ah_p, *bh_p;
    cudaGetSymbolAddress((void**)&zx_p, g_zx);
    cudaGetSymbolAddress((void**)&ah_p, g_Ah);
    cudaGetSymbolAddress((void**)&bh_p, g_Bh);

    const int STATES_SMEM = (64 * 128 + 64 * 64 + 256) * 4;
    const int Y_SMEM = (64 * BTS + 256 * 64 + 64 * CTS + 64 * 128 + 64 * PTS + 512) * 4;
    cudaFuncSetAttribute(states_k, cudaFuncAttributeMaxDynamicSharedMemorySize, STATES_SMEM);
    cudaFuncSetAttribute(y_k,      cudaFuncAttributeMaxDynamicSharedMemorySize, Y_SMEM);
    cudaFuncSetAttribute(gemm_hf,  cudaFuncAttributeMaxDynamicSharedMemorySize, GSMEM);

    // ---- GEMM1: zx[8192,8352] = u[8192,2048] @ W_in[8352,2048]^T ----
    {
        int n4a = MROWS * DMODEL / 4;       // u
        int n4b = EPROJ * DMODEL / 4;       // W_in
        cvt_k<<<(n4a + 255) / 256, 256>>>((const float4*)u, (uint2*)ah_p, n4a);
        cvt_k<<<(n4b + 255) / 256, 256>>>((const float4*)W_in, (uint2*)bh_p, n4b);
        gemm_hf<<<dim3(66, 64), 256, GSMEM>>>(ah_p, bh_p, zx_p, MROWS, EPROJ, DMODEL);
    }
    // ---- SSD middle section ----
    conv_silu_k<<<(CONVDIM / 128) * (MROWS / 32), 256>>>(convw, convb);
    dtcum_k<<<1024, 256>>>(dtb, Alog);
    states_k<<<1024, 512, STATES_SMEM>>>();
    scan_k<<<256, 256>>>();
    y_k<<<1024, 256, Y_SMEM>>>(Dvec);
    gatenorm_k<<<MROWS, 256>>>(nw);     // writes fp16 yn into g_Ah
    // ---- GEMM2: out[8192,2048] = yn[8192,4096] @ W_out[2048,4096]^T ----
    {
        int n4b = DMODEL * DINNER / 4;      // W_out
        cvt_k<<<(n4b + 255) / 256, 256>>>((const float4*)W_out, (uint2*)bh_p, n4b);
        gemm_hf<<<dim3(16, 64), 256, GSMEM>>>(ah_p, bh_p, out, MROWS, DMODEL, DINNER);
    }
}

// round 15
// speedup vs baseline: 3.9513x; 1.3697x over previous
#include <cuda_runtime.h>
#include <cuda_fp16.h>
#include <cstdint>
#include <cstddef>

#define BATCH   2
#define SEQ     4096
#define DMODEL  2048
#define DINNER  4096
#define NHEADS  32
#define DHEAD   128
#define DSTATE  64
#define CONVDIM 4224          // DINNER + 2*DSTATE
#define EPROJ   8352          // 2*DINNER + 2*DSTATE + NHEADS
#define NCHUNK  16
#define CHUNK   256
#define MROWS   8192          // BATCH*SEQ

// ---------------- device scratch (static: allocation-free) ----------------
__device__ float g_zx[(size_t)MROWS * EPROJ];     // in_proj output
__device__ float g_xc[(size_t)MROWS * CONVDIM];   // conv+silu output
__device__ float g_dtv[(size_t)MROWS * NHEADS];   // softplus dt
__device__ float g_cum[BATCH * NCHUNK * NHEADS * CHUNK]; // per-chunk cumsum(dA)
__device__ float g_st[(size_t)BATCH * NCHUNK * NHEADS * DHEAD * DSTATE]; // chunk states
__device__ float g_pv[(size_t)BATCH * NCHUNK * NHEADS * DHEAD * DSTATE]; // prev states
__device__ float g_y [(size_t)MROWS * DINNER];    // y (pre-norm)
// fp16 operands (single-rounded A and B)
__device__ __half g_Ah[(size_t)MROWS * DINNER];
__device__ __half g_Bh[(size_t)EPROJ * DMODEL];

// ============================================================================
// helpers
// ============================================================================
__device__ __forceinline__ uint32_t smem_u32(const void* p) {
    uint32_t a;
    asm("{ .reg .u64 t; cvta.to.shared.u64 t, %1; cvt.u32.u64 %0, t; }" : "=r"(a) : "l"(p));
    return a;
}
__device__ __forceinline__ void ldm4(uint32_t* r, uint32_t a) {
    asm volatile("ldmatrix.sync.aligned.m8n8.x4.shared.b16 {%0,%1,%2,%3}, [%4];"
                 : "=r"(r[0]), "=r"(r[1]), "=r"(r[2]), "=r"(r[3]) : "r"(a));
}
__device__ __forceinline__ void ldm4t(uint32_t* r, uint32_t a) {
    asm volatile("ldmatrix.sync.aligned.m8n8.x4.trans.shared.b16 {%0,%1,%2,%3}, [%4];"
                 : "=r"(r[0]), "=r"(r[1]), "=r"(r[2]), "=r"(r[3]) : "r"(a));
}
__device__ __forceinline__ void mma16816(float* d, const uint32_t* a, uint32_t b0, uint32_t b1) {
    asm volatile("mma.sync.aligned.m16n8k16.row.col.f32.f16.f16.f32 "
                 "{%0,%1,%2,%3}, {%4,%5,%6,%7}, {%8,%9}, {%0,%1,%2,%3};"
                 : "+f"(d[0]), "+f"(d[1]), "+f"(d[2]), "+f"(d[3])
                 : "r"(a[0]), "r"(a[1]), "r"(a[2]), "r"(a[3]), "r"(b0), "r"(b1));
}
__device__ __forceinline__ uint32_t pk2h(__half a, __half b) {
    return (uint32_t)__half_as_ushort(a) | ((uint32_t)__half_as_ushort(b) << 16);
}
__device__ __forceinline__ void cpasync16(uint32_t dst, const void* src, int srcsz) {
    asm volatile("cp.async.cg.shared.global [%0], [%1], 16, %2;"
                 :: "r"(dst), "l"(src), "r"(srcsz) : "memory");
}
#define CP_COMMIT() asm volatile("cp.async.commit_group;" ::: "memory")
#define CP_WAIT2()  asm volatile("cp.async.wait_group 2;" ::: "memory")

// ---------------- fp32 -> fp16 round (memory-bound pass) ----------
__global__ void cvt_k(const float4* __restrict__ in, uint2* __restrict__ out, int n4) {
    int i = blockIdx.x * 256 + threadIdx.x;
    if (i < n4) {
        float4 v = in[i];
        out[i] = make_uint2(pk2h(__float2half_rn(v.x), __float2half_rn(v.y)),
                            pk2h(__float2half_rn(v.z), __float2half_rn(v.w)));
    }
}

// ============================================================================
// HMMA fp16 NT GEMM (unchanged from R13/R14 winner)
// ============================================================================
#define BK      32
#define TROW    80
#define TILE_B  (128 * TROW)
#define STAGE_B (2 * TILE_B)
#define NSTAGE  4
#define GSMEM   (NSTAGE * STAGE_B)

__device__ __forceinline__ void ld_stage(uint32_t sb, int stage,
        const __half* __restrict__ Ah, const __half* __restrict__ Bh,
        int m0, int n0, int K, int N, int k0, int t) {
    uint32_t stb = sb + (uint32_t)stage * STAGE_B;
    #pragma unroll
    for (int j = 0; j < 4; j++) {
        int lin = t + j * 256;
        int tile = lin >> 9, li = lin & 511;
        int row = li >> 2, c = li & 3;
        uint32_t dst = stb + (uint32_t)tile * TILE_B + (uint32_t)row * TROW + c * 16;
        const __half* src;
        int sz = 16;
        if (tile == 0) {
            src = Ah + (size_t)(m0 + row) * K + k0 + c * 8;
        } else {
            int r = n0 + row;
            if (r >= N) { r = 0; sz = 0; }
            src = Bh + (size_t)r * K + k0 + c * 8;
        }
        cpasync16(dst, src, sz);
    }
}

__global__ __launch_bounds__(256, 2)
void gemm_hf(const __half* __restrict__ Ah, const __half* __restrict__ Bh,
             float* __restrict__ C, int M, int N, int K) {
    extern __shared__ char smem[];
    const uint32_t sb = smem_u32(smem);
    const int t = threadIdx.x, wid = t >> 5, lane = t & 31;
    const int m0 = blockIdx.y * 128, n0b = blockIdx.x * 128;
    const int wm = (wid & 1) * 64, wn = (wid >> 1) * 32;

    float acc[4][4][4];
    #pragma unroll
    for (int i = 0; i < 4; i++)
        #pragma unroll
        for (int j = 0; j < 4; j++)
            #pragma unroll
            for (int k = 0; k < 4; k++) acc[i][j][k] = 0.f;

    const int NC = K / BK;
    #pragma unroll
    for (int s = 0; s < NSTAGE - 1; s++) {
        if (s < NC)
            ld_stage(sb, s, Ah, Bh, m0, n0b, K, N, s * BK, t);
        CP_COMMIT();
    }

    const int lr = lane & 15, lh = lane >> 4;

    for (int c = 0; c < NC; c++) {
        CP_WAIT2();
        __syncthreads();
        int nx = c + NSTAGE - 1;
        if (nx < NC)
            ld_stage(sb, nx & (NSTAGE - 1), Ah, Bh, m0, n0b, K, N, nx * BK, t);
        CP_COMMIT();

        uint32_t stb = sb + (uint32_t)(c & (NSTAGE - 1)) * STAGE_B;
        #pragma unroll
        for (int kk = 0; kk < 2; kk++) {
            uint32_t kb = kk * 32 + lh * 16;
            uint32_t ah[4][4], bh[2][4];
            #pragma unroll
            for (int mf = 0; mf < 4; mf++) {
                uint32_t ro = (uint32_t)(wm + mf * 16 + lr) * TROW + kb;
                ldm4(ah[mf], stb + ro);
            }
            #pragma unroll
            for (int np = 0; np < 2; np++) {
                uint32_t ro = (uint32_t)(wn + np * 16 + lr) * TROW + kb;
                ldm4(bh[np], stb + TILE_B + ro);
            }
            #pragma unroll
            for (int mf = 0; mf < 4; mf++)
                #pragma unroll
                for (int np = 0; np < 2; np++) {
                    mma16816(acc[mf][2 * np],     ah[mf], bh[np][0], bh[np][2]);
                    mma16816(acc[mf][2 * np + 1], ah[mf], bh[np][1], bh[np][3]);
                }
        }
    }

    const int gr = lane >> 2, gc = (lane & 3) * 2;
    #pragma unroll
    for (int mf = 0; mf < 4; mf++) {
        int m = m0 + wm + mf * 16 + gr;
        #pragma unroll
        for (int nf = 0; nf < 4; nf++) {
            int n = n0b + wn + nf * 8 + gc;
            if (n < N) {
                *(float2*)&C[(size_t)m * N + n] =
                    make_float2(acc[mf][nf][0], acc[mf][nf][1]);
                *(float2*)&C[(size_t)(m + 8) * N + n] =
                    make_float2(acc[mf][nf][2], acc[mf][nf][3]);
            }
        }
    }
}

// ---------------- conv1d + SiLU, smem-tiled (R14 winner) ----------
__global__ __launch_bounds__(256)
void conv_silu_k(const float* __restrict__ cw, const float* __restrict__ cb) {
    __shared__ float4 sx[35][32];
    const int C4 = CONVDIM / 4;
    int bc = blockIdx.x % (C4 / 32);
    int bl0 = (blockIdx.x / (C4 / 32)) * 32;
    int b = bl0 / SEQ, l0 = bl0 % SEQ;
    int c40 = bc * 32;
    int t = threadIdx.x;
    for (int i = t; i < 35 * 32; i += 256) {
        int r = i >> 5, cc = i & 31;
        int ls = l0 - 3 + r;
        float4 v = make_float4(0.f, 0.f, 0.f, 0.f);
        if (ls >= 0)
            v = *(const float4*)&g_zx[(size_t)(b * SEQ + ls) * EPROJ + DINNER + (c40 + cc) * 4];
        sx[r][cc] = v;
    }
    __syncthreads();
    int cc = t & 31, lr0 = (t >> 5) * 4;
    int c = (c40 + cc) * 4;
    float4 bias = *(const float4*)&cb[c];
    float w[4][4];
    #pragma unroll
    for (int j = 0; j < 4; j++)
        *(float4*)w[j] = *(const float4*)&cw[(c + j) * 4];
    #pragma unroll
    for (int j = 0; j < 4; j++) {
        int lr = lr0 + j;
        float4 acc = bias;
        #pragma unroll
        for (int k = 0; k < 4; k++) {
            float4 v = sx[lr + k][cc];
            acc.x += v.x * w[0][k];
            acc.y += v.y * w[1][k];
            acc.z += v.z * w[2][k];
            acc.w += v.w * w[3][k];
        }
        acc.x = acc.x / (1.f + __expf(-acc.x));
        acc.y = acc.y / (1.f + __expf(-acc.y));
        acc.z = acc.z / (1.f + __expf(-acc.z));
        acc.w = acc.w / (1.f + __expf(-acc.w));
        *(float4*)&g_xc[(size_t)(bl0 + lr) * CONVDIM + c] = acc;
    }
}

// ---------------- dt softplus + per-chunk cumsum(dA) ----------------
__global__ void dtcum_k(const float* __restrict__ dtb, const float* __restrict__ Alog) {
    int blk = blockIdx.x;
    int h = blk & 31, c = (blk >> 5) & 15, b = blk >> 9;
    int s = threadIdx.x;
    int l = c * CHUNK + s;
    float raw = g_zx[((size_t)(b * SEQ + l)) * EPROJ + (EPROJ - NHEADS) + h] + dtb[h];
    float dtv = (raw > 20.f) ? raw : log1pf(__expf(raw));
    g_dtv[(size_t)(b * SEQ + l) * NHEADS + h] = dtv;
    float dA = dtv * (-__expf(Alog[h]));
    __shared__ float sc[256];
    sc[s] = dA;
    __syncthreads();
    for (int off = 1; off < 256; off <<= 1) {
        float v = (s >= off) ? sc[s - off] : 0.f;
        __syncthreads();
        sc[s] += v;
        __syncthreads();
    }
    g_cum[blk * CHUNK + s] = sc[s];
}

// ---------------- per-chunk states (R14 winner) ------
__global__ __launch_bounds__(512, 2)
void states_k() {
    extern __shared__ float sm[];
    float* xw  = sm;
    float* Bsh = xw + 64 * 128;
    float* ws  = Bsh + 64 * 64;
    int blk = blockIdx.x;
    int h = blk & 31, c = (blk >> 5) & 15, b = blk >> 9;
    int t = threadIdx.x;
    if (t < 256) {
        float clast = g_cum[blk * CHUNK + 255];
        float cz = g_cum[blk * CHUNK + t];
        float dtv = g_dtv[(size_t)(b * SEQ + c * CHUNK + t) * NHEADS + h];
        ws[t] = __expf(clast - cz) * dtv;
    }
    __syncthreads();
    int tx = t & 31, ty = t >> 5;
    int p0 = tx * 4, n0 = ty * 4;
    float acc[4][4];
    #pragma unroll
    for (int i = 0; i < 4; i++)
        #pragma unroll
        for (int j = 0; j < 4; j++) acc[i][j] = 0.f;
    size_t base = (size_t)(b * SEQ + c * CHUNK) * CONVDIM;
    for (int zt = 0; zt < 4; zt++) {
        #pragma unroll
        for (int i = 0; i < 16; i++) {
            int lin = t + i * 512; int zz = lin >> 7; int p = lin & 127; int z = zt * 64 + zz;
            xw[zz * 128 + p] = g_xc[base + (size_t)z * CONVDIM + h * DHEAD + p] * ws[z];
        }
        #pragma unroll
        for (int i = 0; i < 8; i++) {
            int lin = t + i * 512; int zz = lin >> 6; int n = lin & 63; int z = zt * 64 + zz;
            Bsh[zz * 64 + n] = g_xc[base + (size_t)z * CONVDIM + DINNER + n];
        }
        __syncthreads();
        #pragma unroll
        for (int zz = 0; zz < 64; zz++) {
            float4 xv4 = *(const float4*)&xw[zz * 128 + p0];
            float4 bv = *(const float4*)&Bsh[zz * 64 + n0];
            float xv[4] = {xv4.x, xv4.y, xv4.z, xv4.w};
            float bb[4] = {bv.x, bv.y, bv.z, bv.w};
            #pragma unroll
            for (int i = 0; i < 4; i++)
                #pragma unroll
                for (int j = 0; j < 4; j++)
                    acc[i][j] += xv[i] * bb[j];
        }
        __syncthreads();
    }
    size_t ob = (size_t)blk * DHEAD * DSTATE;
    #pragma unroll
    for (int i = 0; i < 4; i++)
        #pragma unroll
        for (int j = 0; j < 4; j++)
            g_st[ob + (size_t)(p0 + i) * DSTATE + n0 + j] = acc[i][j];
}

// ---------------- inter-chunk scan (R14 winner) -------------
__global__ void scan_k() {
    int blk = blockIdx.x;
    int q = blk & 3, h = (blk >> 2) & 31, b = blk >> 7;
    int t = threadIdx.x;
    int e0 = q * 2048 + t;
    float carry[8];
    #pragma unroll
    for (int k = 0; k < 8; k++) carry[k] = 0.f;
    for (int c = 0; c < NCHUNK; c++) {
        int idx = (b * NCHUNK + c) * NHEADS + h;
        float decay = __expf(g_cum[idx * CHUNK + 255]);
        size_t base = (size_t)idx * DHEAD * DSTATE + e0;
        #pragma unroll
        for (int k = 0; k < 8; k++) {
            size_t e = base + k * 256;
            g_pv[e] = carry[k];
            carry[k] = carry[k] * decay + g_st[e];
        }
    }
}

// ============================================================================
// y_k (HMMA rewrite): Y = masked(C·B^T)*L @ xdt + es*C @ prev^T + D*x
// A_ext[s][0:64)   = es[s]*C[s][n]   (prev product)
// A_ext[s][64:320) = G_masked[s][z]  (diag product)
// B side: prev[p][n] (non-trans ldm), xdt[z][p] (trans ldm).
// smem strides (halfs): 72 (64-wide), 136 (128-wide), 328 (A_ext) — all odd*8.
// ============================================================================
#define YSM_BT   0                         // Bt  [256][72] h  (36864 B)
#define YSM_SX   36864                     // sX  [256][136] h (69632 B)
#define YSM_PV   106496                    // pv  [128][72] h  (18432 B)
#define YSM_CT   124928                    // Ct  [64][72] h   (9216 B)
#define YSM_AG   134144                    // AhG [64][328] h  (41984 B)
#define YSM_CUM  176128                    // cums [256] f
#define YSM_SDT  177152                    // sdt  [256] f
#define YSM_ES   178176                    // esv  [256] f
#define Y_SMEM   179200

__global__ __launch_bounds__(256, 1)
void y_k(const float* __restrict__ Dvec) {
    extern __shared__ char ysm[];
    __half* Bt  = (__half*)(ysm + YSM_BT);
    __half* sX  = (__half*)(ysm + YSM_SX);
    __half* pv  = (__half*)(ysm + YSM_PV);
    __half* Ct  = (__half*)(ysm + YSM_CT);
    __half* AhG = (__half*)(ysm + YSM_AG);
    float* cums = (float*)(ysm + YSM_CUM);
    float* sdt  = (float*)(ysm + YSM_SDT);
    float* esv  = (float*)(ysm + YSM_ES);
    const uint32_t sb = smem_u32(ysm);

    int blk = blockIdx.x;
    int h = blk & 31, c = (blk >> 5) & 15, b = blk >> 9;
    int t = threadIdx.x, wid = t >> 5, lane = t & 31;
    const int lr = lane & 15, lh = lane >> 4;
    const int gr = lane >> 2, gc = (lane & 3) * 2;
    const int ti = lane & 7, tg = lane >> 3;
    size_t base = (size_t)(b * SEQ + c * CHUNK) * CONVDIM;
    float Dh = Dvec[h];

    {
        float cv = g_cum[blk * CHUNK + t];
        cums[t] = cv;
        esv[t] = __expf(cv);
        sdt[t] = g_dtv[(size_t)(b * SEQ + c * CHUNK + t) * NHEADS + h];
    }
    __syncthreads();
    // Bt: [z][n] fp16  (256 x 64)
    #pragma unroll
    for (int j = 0; j < 16; j++) {
        int idx = t + j * 256;                  // float4 index
        int z = idx >> 4, c4 = idx & 15;
        float4 v = *(const float4*)&g_xc[base + (size_t)z * CONVDIM + DINNER + c4 * 4];
        *(__half2*)&Bt[z * 72 + c4 * 4]     = __floats2half2_rn(v.x, v.y);
        *(__half2*)&Bt[z * 72 + c4 * 4 + 2] = __floats2half2_rn(v.z, v.w);
    }
    // sX: [z][p] fp16 = x*dt (256 x 128)
    #pragma unroll
    for (int j = 0; j < 32; j++) {
        int idx = t + j * 256;
        int z = idx >> 5, c4 = idx & 31;
        float d = sdt[z];
        float4 v = *(const float4*)&g_xc[base + (size_t)z * CONVDIM + h * DHEAD + c4 * 4];
        *(__half2*)&sX[z * 136 + c4 * 4]     = __floats2half2_rn(v.x * d, v.y * d);
        *(__half2*)&sX[z * 136 + c4 * 4 + 2] = __floats2half2_rn(v.z * d, v.w * d);
    }
    // pv: [p][n] fp16 (128 x 64)
    size_t pvb = (size_t)blk * DHEAD * DSTATE;
    #pragma unroll
    for (int j = 0; j < 8; j++) {
        int idx = t + j * 256;
        int p = idx >> 4, c4 = idx & 15;
        float4 v = *(const float4*)&g_pv[pvb + (size_t)p * DSTATE + c4 * 4];
        *(__half2*)&pv[p * 72 + c4 * 4]     = __floats2half2_rn(v.x, v.y);
        *(__half2*)&pv[p * 72 + c4 * 4 + 2] = __floats2half2_rn(v.z, v.w);
    }

    const int wmG = (wid & 3) * 16, wzG = (wid >> 2) * 32;   // G-phase warp tile 16s x 32z
    const int wm2 = (wid & 3) * 16, wp2 = (wid >> 2) * 64;   // Y-phase warp tile 16s x 64p

    for (int st = 0; st < 4; st++) {
        int s0 = st * 64;
        __syncthreads();   // previous phase-2 reads of AhG/Ct done
        // build Ct[s][n] and AhG[s][0:64) = es[s]*C[s][n]
        #pragma unroll
        for (int j = 0; j < 4; j++) {
            int idx = t + j * 256;
            int s = idx >> 4, c4 = idx & 15;
            float4 v = *(const float4*)&g_xc[base + (size_t)(s0 + s) * CONVDIM + DINNER + DSTATE + c4 * 4];
            *(__half2*)&Ct[s * 72 + c4 * 4]     = __floats2half2_rn(v.x, v.y);
            *(__half2*)&Ct[s * 72 + c4 * 4 + 2] = __floats2half2_rn(v.z, v.w);
            float e = esv[s0 + s];
            *(__half2*)&AhG[s * 328 + c4 * 4]     = __floats2half2_rn(v.x * e, v.y * e);
            *(__half2*)&AhG[s * 328 + c4 * 4 + 2] = __floats2half2_rn(v.z * e, v.w * e);
        }
        __syncthreads();
        // G tiles: for zt = 0..st compute G = Ct·Bt^T, mask*L, store fp16 to AhG
        for (int zt = 0; zt <= st; zt++) {
            float ga[2][2][4];
            #pragma unroll
            for (int i = 0; i < 2; i++)
                #pragma unroll
                for (int j = 0; j < 2; j++)
                    #pragma unroll
                    for (int k = 0; k < 4; k++) ga[i][j][k] = 0.f;
            #pragma unroll
            for (int ks = 0; ks < 4; ks++) {
                uint32_t kb = ks * 32 + lh * 16;
                uint32_t af[4];
                ldm4(af, sb + YSM_CT + (uint32_t)(wmG + lr) * 144 + kb);
                #pragma unroll
                for (int np = 0; np < 2; np++) {
                    uint32_t bf[4];
                    ldm4(bf, sb + YSM_BT + (uint32_t)(zt * 64 + wzG + np * 16 + lr) * 144 + kb);
                    mma16816(ga[np][0], af, bf[0], bf[2]);
                    mma16816(ga[np][1], af, bf[1], bf[3]);
                }
            }
            // mask * L and store to AhG[s][64 + zt*64 + zloc]
            #pragma unroll
            for (int np = 0; np < 2; np++)
                #pragma unroll
                for (int nf = 0; nf < 2; nf++) {
                    int zl = zt * 64 + wzG + np * 16 + nf * 8 + gc;   // chunk-local z
                    float cz0 = cums[zl], cz1 = cums[zl + 1];
                    #pragma unroll
                    for (int half = 0; half < 2; half++) {
                        int sl = s0 + wmG + gr + half * 8;            // chunk-local s
                        float cs = cums[sl];
                        float v0 = (zl     <= sl) ? ga[np][nf][half * 2]     * __expf(cs - cz0) : 0.f;
                        float v1 = (zl + 1 <= sl) ? ga[np][nf][half * 2 + 1] * __expf(cs - cz1) : 0.f;
                        *(__half2*)&AhG[(wmG + gr + half * 8) * 328 + 64 + zl] =
                            __floats2half2_rn(v0, v1);
                    }
                }
        }
        __syncthreads();
        // phase 2: Y[64s x 128p] = AhG(k=64+ (st+1)*64) x [pv | sX]
        float acc[8][4];
        #pragma unroll
        for (int i = 0; i < 8; i++)
            #pragma unroll
            for (int k = 0; k < 4; k++) acc[i][k] = 0.f;
        int nks = 4 + (st + 1) * 4;
        for (int ks = 0; ks < nks; ks++) {
            uint32_t af[4];
            ldm4(af, sb + YSM_AG + (uint32_t)(wm2 + lr) * 656 + (uint32_t)ks * 32 + lh * 16);
            if (ks < 4) {
                uint32_t kb = ks * 32 + lh * 16;
                #pragma unroll
                for (int np = 0; np < 4; np++) {
                    uint32_t bf[4];
                    ldm4(bf, sb + YSM_PV + (uint32_t)(wp2 + np * 16 + lr) * 144 + kb);
                    mma16816(acc[2 * np],     af, bf[0], bf[2]);
                    mma16816(acc[2 * np + 1], af, bf[1], bf[3]);
                }
            } else {
                int z0 = (ks - 4) * 16;
                uint32_t rowz = (uint32_t)(z0 + ti + (tg >> 1) * 8) * 272;
                #pragma unroll
                for (int np = 0; np < 4; np++) {
                    uint32_t bf[4];
                    uint32_t colp = (uint32_t)(wp2 + np * 16 + (tg & 1) * 8) * 2;
                    ldm4t(bf, sb + YSM_SX + rowz + colp);
                    mma16816(acc[2 * np],     af, bf[0], bf[2]);
                    mma16816(acc[2 * np + 1], af, bf[1], bf[3]);
                }
            }
        }
        // epilogue: + D*x, store g_y
        #pragma unroll
        for (int nf = 0; nf < 8; nf++) {
            int p = wp2 + nf * 8 + gc;
            #pragma unroll
            for (int half = 0; half < 2; half++) {
                int srow = s0 + wm2 + gr + half * 8;
                size_t row = (size_t)(b * SEQ + c * CHUNK + srow);
                float2 xv = *(const float2*)&g_xc[row * CONVDIM + h * DHEAD + p];
                *(float2*)&g_y[row * DINNER + h * DHEAD + p] =
                    make_float2(acc[nf][half * 2]     + Dh * xv.x,
                                acc[nf][half * 2 + 1] + Dh * xv.y);
            }
        }
    }
}

// ---------------- gated RMSNorm fused with fp16 round for GEMM2 ------
__global__ void gatenorm_k(const float* __restrict__ nw) {
    int row = blockIdx.x;
    __shared__ float yg[DINNER];
    __shared__ float red[256];
    int t = threadIdx.x;
    float ss = 0.f;
    size_t zb = (size_t)row * EPROJ;
    size_t yb = (size_t)row * DINNER;
    #pragma unroll
    for (int i = 0; i < 16; i++) {
        int e = t + i * 256;
        float z = g_zx[zb + e];
        float sz = z / (1.f + __expf(-z));
        float v = g_y[yb + e] * sz;
        yg[e] = v;
        ss += v * v;
    }
    red[t] = ss;
    __syncthreads();
    for (int off = 128; off > 0; off >>= 1) {
        if (t < off) red[t] += red[t + off];
        __syncthreads();
    }
    float scale = rsqrtf(red[0] / (float)DINNER + 1e-5f);
    #pragma unroll
    for (int i = 0; i < 16; i++) {
        int e = t + i * 256;
        float v = yg[e] * scale * nw[e];
        g_Ah[yb + e] = __float2half_rn(v);
    }
}

// ---------------- launch ----------------
extern "C" void kernel_launch(void* const* d_in, const int* in_sizes, int n_in,
                              void* d_out, int out_size) {
    const float* u     = (const float*)d_in[0];
    const float* W_in  = (const float*)d_in[1];
    const float* convw = (const float*)d_in[2];
    const float* convb = (const float*)d_in[3];
    const float* dtb   = (const float*)d_in[4];
    const float* Alog  = (const float*)d_in[5];
    const float* Dvec  = (const float*)d_in[6];
    const float* nw    = (const float*)d_in[7];
    const float* W_out = (const float*)d_in[8];
    float* out = (float*)d_out;

    float* zx_p;
    __half *ah_p, *bh_p;
    cudaGetSymbolAddress((void**)&zx_p, g_zx);
    cudaGetSymbolAddress((void**)&ah_p, g_Ah);
    cudaGetSymbolAddress((void**)&bh_p, g_Bh);

    const int STATES_SMEM = (64 * 128 + 64 * 64 + 256) * 4;
    cudaFuncSetAttribute(states_k, cudaFuncAttributeMaxDynamicSharedMemorySize, STATES_SMEM);
    cudaFuncSetAttribute(y_k,      cudaFuncAttributeMaxDynamicSharedMemorySize, Y_SMEM);
    cudaFuncSetAttribute(gemm_hf,  cudaFuncAttributeMaxDynamicSharedMemorySize, GSMEM);

    // ---- GEMM1: zx[8192,8352] = u[8192,2048] @ W_in[8352,2048]^T ----
    {
        int n4a = MROWS * DMODEL / 4;
        int n4b = EPROJ * DMODEL / 4;
        cvt_k<<<(n4a + 255) / 256, 256>>>((const float4*)u, (uint2*)ah_p, n4a);
        cvt_k<<<(n4b + 255) / 256, 256>>>((const float4*)W_in, (uint2*)bh_p, n4b);
        gemm_hf<<<dim3(66, 64), 256, GSMEM>>>(ah_p, bh_p, zx_p, MROWS, EPROJ, DMODEL);
    }
    // ---- SSD middle section ----
    conv_silu_k<<<(CONVDIM / 128) * (MROWS / 32), 256>>>(convw, convb);
    dtcum_k<<<1024, 256>>>(dtb, Alog);
    states_k<<<1024, 512, STATES_SMEM>>>();
    scan_k<<<256, 256>>>();
    y_k<<<1024, 256, Y_SMEM>>>(Dvec);
    gatenorm_k<<<MROWS, 256>>>(nw);
    // ---- GEMM2: out[8192,2048] = yn[8192,4096] @ W_out[2048,4096]^T ----
    {
        int n4b = DMODEL * DINNER / 4;
        cvt_k<<<(n4b + 255) / 256, 256>>>((const float4*)W_out, (uint2*)bh_p, n4b);
        gemm_hf<<<dim3(16, 64), 256, GSMEM>>>(ah_p, bh_p, out, MROWS, DMODEL, DINNER);
    }
}

// round 16
// speedup vs baseline: 4.0362x; 1.0215x over previous
#include <cuda_runtime.h>
#include <cuda_fp16.h>
#include <cstdint>
#include <cstddef>

#define BATCH   2
#define SEQ     4096
#define DMODEL  2048
#define DINNER  4096
#define NHEADS  32
#define DHEAD   128
#define DSTATE  64
#define CONVDIM 4224          // DINNER + 2*DSTATE
#define EPROJ   8352          // 2*DINNER + 2*DSTATE + NHEADS
#define NCHUNK  16
#define CHUNK   256
#define MROWS   8192          // BATCH*SEQ

// ---------------- device scratch (static: allocation-free) ----------------
__device__ float g_zx[(size_t)MROWS * EPROJ];     // in_proj output
__device__ __half g_xc[(size_t)MROWS * CONVDIM];  // conv+silu output (fp16)
__device__ float g_dtv[(size_t)MROWS * NHEADS];   // softplus dt
__device__ float g_cum[BATCH * NCHUNK * NHEADS * CHUNK]; // per-chunk cumsum(dA)
__device__ float g_st[(size_t)BATCH * NCHUNK * NHEADS * DHEAD * DSTATE]; // chunk states
__device__ float g_pv[(size_t)BATCH * NCHUNK * NHEADS * DHEAD * DSTATE]; // prev states
__device__ float g_y [(size_t)MROWS * DINNER];    // y (pre-norm)
// fp16 operands (single-rounded A and B)
__device__ __half g_Ah[(size_t)MROWS * DINNER];
__device__ __half g_Bh[(size_t)EPROJ * DMODEL];

// ============================================================================
// helpers
// ============================================================================
__device__ __forceinline__ uint32_t smem_u32(const void* p) {
    uint32_t a;
    asm("{ .reg .u64 t; cvta.to.shared.u64 t, %1; cvt.u32.u64 %0, t; }" : "=r"(a) : "l"(p));
    return a;
}
__device__ __forceinline__ void ldm4(uint32_t* r, uint32_t a) {
    asm volatile("ldmatrix.sync.aligned.m8n8.x4.shared.b16 {%0,%1,%2,%3}, [%4];"
                 : "=r"(r[0]), "=r"(r[1]), "=r"(r[2]), "=r"(r[3]) : "r"(a));
}
__device__ __forceinline__ void ldm4t(uint32_t* r, uint32_t a) {
    asm volatile("ldmatrix.sync.aligned.m8n8.x4.trans.shared.b16 {%0,%1,%2,%3}, [%4];"
                 : "=r"(r[0]), "=r"(r[1]), "=r"(r[2]), "=r"(r[3]) : "r"(a));
}
__device__ __forceinline__ void mma16816(float* d, const uint32_t* a, uint32_t b0, uint32_t b1) {
    asm volatile("mma.sync.aligned.m16n8k16.row.col.f32.f16.f16.f32 "
                 "{%0,%1,%2,%3}, {%4,%5,%6,%7}, {%8,%9}, {%0,%1,%2,%3};"
                 : "+f"(d[0]), "+f"(d[1]), "+f"(d[2]), "+f"(d[3])
                 : "r"(a[0]), "r"(a[1]), "r"(a[2]), "r"(a[3]), "r"(b0), "r"(b1));
}
__device__ __forceinline__ uint32_t pk2h(__half a, __half b) {
    return (uint32_t)__half_as_ushort(a) | ((uint32_t)__half_as_ushort(b) << 16);
}
__device__ __forceinline__ void cpasync16(uint32_t dst, const void* src, int srcsz) {
    asm volatile("cp.async.cg.shared.global [%0], [%1], 16, %2;"
                 :: "r"(dst), "l"(src), "r"(srcsz) : "memory");
}
#define CP_COMMIT() asm volatile("cp.async.commit_group;" ::: "memory")
#define CP_WAIT2()  asm volatile("cp.async.wait_group 2;" ::: "memory")

// ---------------- fp32 -> fp16 round (memory-bound pass) ----------
__global__ void cvt_k(const float4* __restrict__ in, uint2* __restrict__ out, int n4) {
    int i = blockIdx.x * 256 + threadIdx.x;
    if (i < n4) {
        float4 v = in[i];
        out[i] = make_uint2(pk2h(__float2half_rn(v.x), __float2half_rn(v.y)),
                            pk2h(__float2half_rn(v.z), __float2half_rn(v.w)));
    }
}

// ============================================================================
// HMMA fp16 NT GEMM (R13/R14 winner, unchanged)
// ============================================================================
#define BK      32
#define TROW    80
#define TILE_B  (128 * TROW)
#define STAGE_B (2 * TILE_B)
#define NSTAGE  4
#define GSMEM   (NSTAGE * STAGE_B)

__device__ __forceinline__ void ld_stage(uint32_t sb, int stage,
        const __half* __restrict__ Ah, const __half* __restrict__ Bh,
        int m0, int n0, int K, int N, int k0, int t) {
    uint32_t stb = sb + (uint32_t)stage * STAGE_B;
    #pragma unroll
    for (int j = 0; j < 4; j++) {
        int lin = t + j * 256;
        int tile = lin >> 9, li = lin & 511;
        int row = li >> 2, c = li & 3;
        uint32_t dst = stb + (uint32_t)tile * TILE_B + (uint32_t)row * TROW + c * 16;
        const __half* src;
        int sz = 16;
        if (tile == 0) {
            src = Ah + (size_t)(m0 + row) * K + k0 + c * 8;
        } else {
            int r = n0 + row;
            if (r >= N) { r = 0; sz = 0; }
            src = Bh + (size_t)r * K + k0 + c * 8;
        }
        cpasync16(dst, src, sz);
    }
}

__global__ __launch_bounds__(256, 2)
void gemm_hf(const __half* __restrict__ Ah, const __half* __restrict__ Bh,
             float* __restrict__ C, int M, int N, int K) {
    extern __shared__ char smem[];
    const uint32_t sb = smem_u32(smem);
    const int t = threadIdx.x, wid = t >> 5, lane = t & 31;
    const int m0 = blockIdx.y * 128, n0b = blockIdx.x * 128;
    const int wm = (wid & 1) * 64, wn = (wid >> 1) * 32;

    float acc[4][4][4];
    #pragma unroll
    for (int i = 0; i < 4; i++)
        #pragma unroll
        for (int j = 0; j < 4; j++)
            #pragma unroll
            for (int k = 0; k < 4; k++) acc[i][j][k] = 0.f;

    const int NC = K / BK;
    #pragma unroll
    for (int s = 0; s < NSTAGE - 1; s++) {
        if (s < NC)
            ld_stage(sb, s, Ah, Bh, m0, n0b, K, N, s * BK, t);
        CP_COMMIT();
    }

    const int lr = lane & 15, lh = lane >> 4;

    for (int c = 0; c < NC; c++) {
        CP_WAIT2();
        __syncthreads();
        int nx = c + NSTAGE - 1;
        if (nx < NC)
            ld_stage(sb, nx & (NSTAGE - 1), Ah, Bh, m0, n0b, K, N, nx * BK, t);
        CP_COMMIT();

        uint32_t stb = sb + (uint32_t)(c & (NSTAGE - 1)) * STAGE_B;
        #pragma unroll
        for (int kk = 0; kk < 2; kk++) {
            uint32_t kb = kk * 32 + lh * 16;
            uint32_t ah[4][4], bh[2][4];
            #pragma unroll
            for (int mf = 0; mf < 4; mf++) {
                uint32_t ro = (uint32_t)(wm + mf * 16 + lr) * TROW + kb;
                ldm4(ah[mf], stb + ro);
            }
            #pragma unroll
            for (int np = 0; np < 2; np++) {
                uint32_t ro = (uint32_t)(wn + np * 16 + lr) * TROW + kb;
                ldm4(bh[np], stb + TILE_B + ro);
            }
            #pragma unroll
            for (int mf = 0; mf < 4; mf++)
                #pragma unroll
                for (int np = 0; np < 2; np++) {
                    mma16816(acc[mf][2 * np],     ah[mf], bh[np][0], bh[np][2]);
                    mma16816(acc[mf][2 * np + 1], ah[mf], bh[np][1], bh[np][3]);
                }
        }
    }

    const int gr = lane >> 2, gc = (lane & 3) * 2;
    #pragma unroll
    for (int mf = 0; mf < 4; mf++) {
        int m = m0 + wm + mf * 16 + gr;
        #pragma unroll
        for (int nf = 0; nf < 4; nf++) {
            int n = n0b + wn + nf * 8 + gc;
            if (n < N) {
                *(float2*)&C[(size_t)m * N + n] =
                    make_float2(acc[mf][nf][0], acc[mf][nf][1]);
                *(float2*)&C[(size_t)(m + 8) * N + n] =
                    make_float2(acc[mf][nf][2], acc[mf][nf][3]);
            }
        }
    }
}

// ---------------- conv1d + SiLU, smem-tiled; fp16 output ----------
__global__ __launch_bounds__(256)
void conv_silu_k(const float* __restrict__ cw, const float* __restrict__ cb) {
    __shared__ float4 sx[35][32];
    const int C4 = CONVDIM / 4;
    int bc = blockIdx.x % (C4 / 32);
    int bl0 = (blockIdx.x / (C4 / 32)) * 32;
    int b = bl0 / SEQ, l0 = bl0 % SEQ;
    int c40 = bc * 32;
    int t = threadIdx.x;
    for (int i = t; i < 35 * 32; i += 256) {
        int r = i >> 5, cc = i & 31;
        int ls = l0 - 3 + r;
        float4 v = make_float4(0.f, 0.f, 0.f, 0.f);
        if (ls >= 0)
            v = *(const float4*)&g_zx[(size_t)(b * SEQ + ls) * EPROJ + DINNER + (c40 + cc) * 4];
        sx[r][cc] = v;
    }
    __syncthreads();
    int cc = t & 31, lr0 = (t >> 5) * 4;
    int c = (c40 + cc) * 4;
    float4 bias = *(const float4*)&cb[c];
    float w[4][4];
    #pragma unroll
    for (int j = 0; j < 4; j++)
        *(float4*)w[j] = *(const float4*)&cw[(c + j) * 4];
    #pragma unroll
    for (int j = 0; j < 4; j++) {
        int lr = lr0 + j;
        float4 acc = bias;
        #pragma unroll
        for (int k = 0; k < 4; k++) {
            float4 v = sx[lr + k][cc];
            acc.x += v.x * w[0][k];
            acc.y += v.y * w[1][k];
            acc.z += v.z * w[2][k];
            acc.w += v.w * w[3][k];
        }
        acc.x = acc.x / (1.f + __expf(-acc.x));
        acc.y = acc.y / (1.f + __expf(-acc.y));
        acc.z = acc.z / (1.f + __expf(-acc.z));
        acc.w = acc.w / (1.f + __expf(-acc.w));
        uint2 o;
        *(__half2*)&o.x = __floats2half2_rn(acc.x, acc.y);
        *(__half2*)&o.y = __floats2half2_rn(acc.z, acc.w);
        *(uint2*)&g_xc[(size_t)(bl0 + lr) * CONVDIM + c] = o;
    }
}

// ---------------- dt softplus + per-chunk cumsum(dA) ----------------
__global__ void dtcum_k(const float* __restrict__ dtb, const float* __restrict__ Alog) {
    int blk = blockIdx.x;
    int h = blk & 31, c = (blk >> 5) & 15, b = blk >> 9;
    int s = threadIdx.x;
    int l = c * CHUNK + s;
    float raw = g_zx[((size_t)(b * SEQ + l)) * EPROJ + (EPROJ - NHEADS) + h] + dtb[h];
    float dtv = (raw > 20.f) ? raw : log1pf(__expf(raw));
    g_dtv[(size_t)(b * SEQ + l) * NHEADS + h] = dtv;
    float dA = dtv * (-__expf(Alog[h]));
    __shared__ float sc[256];
    sc[s] = dA;
    __syncthreads();
    for (int off = 1; off < 256; off <<= 1) {
        float v = (s >= off) ? sc[s - off] : 0.f;
        __syncthreads();
        sc[s] += v;
        __syncthreads();
    }
    g_cum[blk * CHUNK + s] = sc[s];
}

// ---------------- per-chunk states (fp16 inputs) ------
__global__ __launch_bounds__(512, 2)
void states_k() {
    extern __shared__ float sm[];
    float* xw  = sm;
    float* Bsh = xw + 64 * 128;
    float* ws  = Bsh + 64 * 64;
    int blk = blockIdx.x;
    int h = blk & 31, c = (blk >> 5) & 15, b = blk >> 9;
    int t = threadIdx.x;
    if (t < 256) {
        float clast = g_cum[blk * CHUNK + 255];
        float cz = g_cum[blk * CHUNK + t];
        float dtv = g_dtv[(size_t)(b * SEQ + c * CHUNK + t) * NHEADS + h];
        ws[t] = __expf(clast - cz) * dtv;
    }
    __syncthreads();
    int tx = t & 31, ty = t >> 5;
    int p0 = tx * 4, n0 = ty * 4;
    float acc[4][4];
    #pragma unroll
    for (int i = 0; i < 4; i++)
        #pragma unroll
        for (int j = 0; j < 4; j++) acc[i][j] = 0.f;
    size_t base = (size_t)(b * SEQ + c * CHUNK) * CONVDIM;
    for (int zt = 0; zt < 4; zt++) {
        #pragma unroll
        for (int i = 0; i < 8; i++) {
            int lin = t + i * 512;                 // 0..4095: half2 over 64z x 64pp
            int zz = lin >> 6; int pp = lin & 63; int z = zt * 64 + zz;
            __half2 hv = *(const __half2*)&g_xc[base + (size_t)z * CONVDIM + h * DHEAD + pp * 2];
            float2 f = __half22float2(hv);
            float w = ws[z];
            xw[zz * 128 + pp * 2]     = f.x * w;
            xw[zz * 128 + pp * 2 + 1] = f.y * w;
        }
        #pragma unroll
        for (int i = 0; i < 4; i++) {
            int lin = t + i * 512;                 // 0..2047: half2 over 64z x 32nn
            int zz = lin >> 5; int nn = lin & 31; int z = zt * 64 + zz;
            __half2 hv = *(const __half2*)&g_xc[base + (size_t)z * CONVDIM + DINNER + nn * 2];
            float2 f = __half22float2(hv);
            Bsh[zz * 64 + nn * 2]     = f.x;
            Bsh[zz * 64 + nn * 2 + 1] = f.y;
        }
        __syncthreads();
        #pragma unroll
        for (int zz = 0; zz < 64; zz++) {
            float4 xv4 = *(const float4*)&xw[zz * 128 + p0];
            float4 bv = *(const float4*)&Bsh[zz * 64 + n0];
            float xv[4] = {xv4.x, xv4.y, xv4.z, xv4.w};
            float bb[4] = {bv.x, bv.y, bv.z, bv.w};
            #pragma unroll
            for (int i = 0; i < 4; i++)
                #pragma unroll
                for (int j = 0; j < 4; j++)
                    acc[i][j] += xv[i] * bb[j];
        }
        __syncthreads();
    }
    size_t ob = (size_t)blk * DHEAD * DSTATE;
    #pragma unroll
    for (int i = 0; i < 4; i++)
        #pragma unroll
        for (int j = 0; j < 4; j++)
            g_st[ob + (size_t)(p0 + i) * DSTATE + n0 + j] = acc[i][j];
}

// ---------------- inter-chunk scan (R14 winner) -------------
__global__ void scan_k() {
    int blk = blockIdx.x;
    int q = blk & 3, h = (blk >> 2) & 31, b = blk >> 7;
    int t = threadIdx.x;
    int e0 = q * 2048 + t;
    float carry[8];
    #pragma unroll
    for (int k = 0; k < 8; k++) carry[k] = 0.f;
    for (int c = 0; c < NCHUNK; c++) {
        int idx = (b * NCHUNK + c) * NHEADS + h;
        float decay = __expf(g_cum[idx * CHUNK + 255]);
        size_t base = (size_t)idx * DHEAD * DSTATE + e0;
        #pragma unroll
        for (int k = 0; k < 8; k++) {
            size_t e = base + k * 256;
            g_pv[e] = carry[k];
            carry[k] = carry[k] * decay + g_st[e];
        }
    }
}

// ============================================================================
// y_k (HMMA, fp16 g_xc inputs — raw byte copies for B/C tiles)
// ============================================================================
#define YSM_BT   0                         // Bt  [256][72] h  (36864 B)
#define YSM_SX   36864                     // sX  [256][136] h (69632 B)
#define YSM_PV   106496                    // pv  [128][72] h  (18432 B)
#define YSM_CT   124928                    // Ct  [64][72] h   (9216 B)
#define YSM_AG   134144                    // AhG [64][328] h  (41984 B)
#define YSM_CUM  176128                    // cums [256] f
#define YSM_SDT  177152                    // sdt  [256] f
#define YSM_ES   178176                    // esv  [256] f
#define Y_SMEM   179200

__global__ __launch_bounds__(256, 1)
void y_k(const float* __restrict__ Dvec) {
    extern __shared__ char ysm[];
    __half* Bt  = (__half*)(ysm + YSM_BT);
    __half* sX  = (__half*)(ysm + YSM_SX);
    __half* pv  = (__half*)(ysm + YSM_PV);
    __half* Ct  = (__half*)(ysm + YSM_CT);
    __half* AhG = (__half*)(ysm + YSM_AG);
    float* cums = (float*)(ysm + YSM_CUM);
    float* sdt  = (float*)(ysm + YSM_SDT);
    float* esv  = (float*)(ysm + YSM_ES);
    const uint32_t sb = smem_u32(ysm);

    int blk = blockIdx.x;
    int h = blk & 31, c = (blk >> 5) & 15, b = blk >> 9;
    int t = threadIdx.x, wid = t >> 5, lane = t & 31;
    const int lr = lane & 15, lh = lane >> 4;
    const int gr = lane >> 2, gc = (lane & 3) * 2;
    const int ti = lane & 7, tg = lane >> 3;
    size_t base = (size_t)(b * SEQ + c * CHUNK) * CONVDIM;
    float Dh = Dvec[h];

    {
        float cv = g_cum[blk * CHUNK + t];
        cums[t] = cv;
        esv[t] = __expf(cv);
        sdt[t] = g_dtv[(size_t)(b * SEQ + c * CHUNK + t) * NHEADS + h];
    }
    __syncthreads();
    // Bt: [z][n] fp16 — raw copy (256 x 64 halves = 2048 uint4)
    #pragma unroll
    for (int j = 0; j < 8; j++) {
        int idx = t + j * 256;
        int z = idx >> 3, c8 = idx & 7;
        *(uint4*)&Bt[z * 72 + c8 * 8] =
            *(const uint4*)&g_xc[base + (size_t)z * CONVDIM + DINNER + c8 * 8];
    }
    // sX: [z][p] fp16 = x*dt (256 x 128 halves = 4096 uint4)
    #pragma unroll
    for (int j = 0; j < 16; j++) {
        int idx = t + j * 256;
        int z = idx >> 4, c8 = idx & 15;
        uint4 raw = *(const uint4*)&g_xc[base + (size_t)z * CONVDIM + h * DHEAD + c8 * 8];
        __half2 dh = __float2half2_rn(sdt[z]);
        __half2* rp = (__half2*)&raw;
        uint4 outv;
        __half2* op = (__half2*)&outv;
        op[0] = __hmul2(rp[0], dh);
        op[1] = __hmul2(rp[1], dh);
        op[2] = __hmul2(rp[2], dh);
        op[3] = __hmul2(rp[3], dh);
        *(uint4*)&sX[z * 136 + c8 * 8] = outv;
    }
    // pv: [p][n] fp16 from fp32 g_pv (128 x 64)
    size_t pvb = (size_t)blk * DHEAD * DSTATE;
    #pragma unroll
    for (int j = 0; j < 8; j++) {
        int idx = t + j * 256;
        int p = idx >> 4, c4 = idx & 15;
        float4 v = *(const float4*)&g_pv[pvb + (size_t)p * DSTATE + c4 * 4];
        *(__half2*)&pv[p * 72 + c4 * 4]     = __floats2half2_rn(v.x, v.y);
        *(__half2*)&pv[p * 72 + c4 * 4 + 2] = __floats2half2_rn(v.z, v.w);
    }

    const int wmG = (wid & 3) * 16, wzG = (wid >> 2) * 32;   // G-phase warp tile
    const int wm2 = (wid & 3) * 16, wp2 = (wid >> 2) * 64;   // Y-phase warp tile

    for (int st = 0; st < 4; st++) {
        int s0 = st * 64;
        __syncthreads();
        // Ct[s][n] raw copy + AhG[s][0:64) = es[s]*C[s][n]
        #pragma unroll
        for (int j = 0; j < 2; j++) {
            int idx = t + j * 256;
            int s = idx >> 3, c8 = idx & 7;
            uint4 raw = *(const uint4*)&g_xc[base + (size_t)(s0 + s) * CONVDIM + DINNER + DSTATE + c8 * 8];
            *(uint4*)&Ct[s * 72 + c8 * 8] = raw;
            __half2 eh = __float2half2_rn(esv[s0 + s]);
            __half2* rp = (__half2*)&raw;
            uint4 outv;
            __half2* op = (__half2*)&outv;
            op[0] = __hmul2(rp[0], eh);
            op[1] = __hmul2(rp[1], eh);
            op[2] = __hmul2(rp[2], eh);
            op[3] = __hmul2(rp[3], eh);
            *(uint4*)&AhG[s * 328 + c8 * 8] = outv;
        }
        __syncthreads();
        // G tiles: G = Ct·Bt^T, mask*L, store fp16 to AhG
        for (int zt = 0; zt <= st; zt++) {
            float ga[2][2][4];
            #pragma unroll
            for (int i = 0; i < 2; i++)
                #pragma unroll
                for (int j = 0; j < 2; j++)
                    #pragma unroll
                    for (int k = 0; k < 4; k++) ga[i][j][k] = 0.f;
            #pragma unroll
            for (int ks = 0; ks < 4; ks++) {
                uint32_t kb = ks * 32 + lh * 16;
                uint32_t af[4];
                ldm4(af, sb + YSM_CT + (uint32_t)(wmG + lr) * 144 + kb);
                #pragma unroll
                for (int np = 0; np < 2; np++) {
                    uint32_t bf[4];
                    ldm4(bf, sb + YSM_BT + (uint32_t)(zt * 64 + wzG + np * 16 + lr) * 144 + kb);
                    mma16816(ga[np][0], af, bf[0], bf[2]);
                    mma16816(ga[np][1], af, bf[1], bf[3]);
                }
            }
            #pragma unroll
            for (int np = 0; np < 2; np++)
                #pragma unroll
                for (int nf = 0; nf < 2; nf++) {
                    int zl = zt * 64 + wzG + np * 16 + nf * 8 + gc;
                    float cz0 = cums[zl], cz1 = cums[zl + 1];
                    #pragma unroll
                    for (int half = 0; half < 2; half++) {
                        int sl = s0 + wmG + gr + half * 8;
                        float cs = cums[sl];
                        float v0 = (zl     <= sl) ? ga[np][nf][half * 2]     * __expf(cs - cz0) : 0.f;
                        float v1 = (zl + 1 <= sl) ? ga[np][nf][half * 2 + 1] * __expf(cs - cz1) : 0.f;
                        *(__half2*)&AhG[(wmG + gr + half * 8) * 328 + 64 + zl] =
                            __floats2half2_rn(v0, v1);
                    }
                }
        }
        __syncthreads();
        // phase 2: Y[64s x 128p] = AhG x [pv | sX]
        float acc[8][4];
        #pragma unroll
        for (int i = 0; i < 8; i++)
            #pragma unroll
            for (int k = 0; k < 4; k++) acc[i][k] = 0.f;
        int nks = 4 + (st + 1) * 4;
        for (int ks = 0; ks < nks; ks++) {
            uint32_t af[4];
            ldm4(af, sb + YSM_AG + (uint32_t)(wm2 + lr) * 656 + (uint32_t)ks * 32 + lh * 16);
            if (ks < 4) {
                uint32_t kb = ks * 32 + lh * 16;
                #pragma unroll
                for (int np = 0; np < 4; np++) {
                    uint32_t bf[4];
                    ldm4(bf, sb + YSM_PV + (uint32_t)(wp2 + np * 16 + lr) * 144 + kb);
                    mma16816(acc[2 * np],     af, bf[0], bf[2]);
                    mma16816(acc[2 * np + 1], af, bf[1], bf[3]);
                }
            } else {
                int z0 = (ks - 4) * 16;
                uint32_t rowz = (uint32_t)(z0 + ti + (tg >> 1) * 8) * 272;
                #pragma unroll
                for (int np = 0; np < 4; np++) {
                    uint32_t bf[4];
                    uint32_t colp = (uint32_t)(wp2 + np * 16 + (tg & 1) * 8) * 2;
                    ldm4t(bf, sb + YSM_SX + rowz + colp);
                    mma16816(acc[2 * np],     af, bf[0], bf[2]);
                    mma16816(acc[2 * np + 1], af, bf[1], bf[3]);
                }
            }
        }
        // epilogue: + D*x, store g_y
        #pragma unroll
        for (int nf = 0; nf < 8; nf++) {
            int p = wp2 + nf * 8 + gc;
            #pragma unroll
            for (int half = 0; half < 2; half++) {
                int srow = s0 + wm2 + gr + half * 8;
                size_t row = (size_t)(b * SEQ + c * CHUNK + srow);
                __half2 xh = *(const __half2*)&g_xc[row * CONVDIM + h * DHEAD + p];
                float2 xv = __half22float2(xh);
                *(float2*)&g_y[row * DINNER + h * DHEAD + p] =
                    make_float2(acc[nf][half * 2]     + Dh * xv.x,
                                acc[nf][half * 2 + 1] + Dh * xv.y);
            }
        }
    }
}

// ---------------- gated RMSNorm fused with fp16 round for GEMM2 ------
__global__ void gatenorm_k(const float* __restrict__ nw) {
    int row = blockIdx.x;
    __shared__ float yg[DINNER];
    __shared__ float red[256];
    int t = threadIdx.x;
    float ss = 0.f;
    size_t zb = (size_t)row * EPROJ;
    size_t yb = (size_t)row * DINNER;
    #pragma unroll
    for (int i = 0; i < 16; i++) {
        int e = t + i * 256;
        float z = g_zx[zb + e];
        float sz = z / (1.f + __expf(-z));
        float v = g_y[yb + e] * sz;
        yg[e] = v;
        ss += v * v;
    }
    red[t] = ss;
    __syncthreads();
    for (int off = 128; off > 0; off >>= 1) {
        if (t < off) red[t] += red[t + off];
        __syncthreads();
    }
    float scale = rsqrtf(red[0] / (float)DINNER + 1e-5f);
    #pragma unroll
    for (int i = 0; i < 16; i++) {
        int e = t + i * 256;
        float v = yg[e] * scale * nw[e];
        g_Ah[yb + e] = __float2half_rn(v);
    }
}

// ---------------- launch ----------------
extern "C" void kernel_launch(void* const* d_in, const int* in_sizes, int n_in,
                              void* d_out, int out_size) {
    const float* u     = (const float*)d_in[0];
    const float* W_in  = (const float*)d_in[1];
    const float* convw = (const float*)d_in[2];
    const float* convb = (const float*)d_in[3];
    const float* dtb   = (const float*)d_in[4];
    const float* Alog  = (const float*)d_in[5];
    const float* Dvec  = (const float*)d_in[6];
    const float* nw    = (const float*)d_in[7];
    const float* W_out = (const float*)d_in[8];
    float* out = (float*)d_out;

    float* zx_p;
    __half *ah_p, *bh_p;
    cudaGetSymbolAddress((void**)&zx_p, g_zx);
    cudaGetSymbolAddress((void**)&ah_p, g_Ah);
    cudaGetSymbolAddress((void**)&bh_p, g_Bh);

    const int STATES_SMEM = (64 * 128 + 64 * 64 + 256) * 4;
    cudaFuncSetAttribute(states_k, cudaFuncAttributeMaxDynamicSharedMemorySize, STATES_SMEM);
    cudaFuncSetAttribute(y_k,      cudaFuncAttributeMaxDynamicSharedMemorySize, Y_SMEM);
    cudaFuncSetAttribute(gemm_hf,  cudaFuncAttributeMaxDynamicSharedMemorySize, GSMEM);

    // ---- GEMM1: zx[8192,8352] = u[8192,2048] @ W_in[8352,2048]^T ----
    {
        int n4a = MROWS * DMODEL / 4;
        int n4b = EPROJ * DMODEL / 4;
        cvt_k<<<(n4a + 255) / 256, 256>>>((const float4*)u, (uint2*)ah_p, n4a);
        cvt_k<<<(n4b + 255) / 256, 256>>>((const float4*)W_in, (uint2*)bh_p, n4b);
        gemm_hf<<<dim3(66, 64), 256, GSMEM>>>(ah_p, bh_p, zx_p, MROWS, EPROJ, DMODEL);
    }
    // ---- SSD middle section ----
    conv_silu_k<<<(CONVDIM / 128) * (MROWS / 32), 256>>>(convw, convb);
    dtcum_k<<<1024, 256>>>(dtb, Alog);
    states_k<<<1024, 512, STATES_SMEM>>>();
    scan_k<<<256, 256>>>();
    y_k<<<1024, 256, Y_SMEM>>>(Dvec);
    gatenorm_k<<<MROWS, 256>>>(nw);
    // ---- GEMM2: out[8192,2048] = yn[8192,4096] @ W_out[2048,4096]^T ----
    {
        int n4b = DMODEL * DINNER / 4;
        cvt_k<<<(n4b + 255) / 256, 256>>>((const float4*)W_out, (uint2*)bh_p, n4b);
        gemm_hf<<<dim3(16, 64), 256, GSMEM>>>(ah_p, bh_p, out, MROWS, DMODEL, DINNER);
    }
}